// round 9
// baseline (speedup 1.0000x reference)
#include <cuda_runtime.h>
#include <cuda_bf16.h>
#include <math.h>
#include <cstdint>

#define BB 8
#define SS 512
#define HH 1024
#define NHD 16
#define DD 64
#define MM (BB*SS)      // 4096
#define BH (BB*NHD)     // 128
#define CD 192          // concatenated head dim (q|qp|qf)

// ---- scratch (device globals; no allocations allowed) ----
static __device__ __align__(16) float g_v[(size_t)BH*SS*DD];       // [bh][s][64] fp32
static __device__ __align__(16) float g_scores[(size_t)BH*SS*SS];  // [bh][q][k] fp32

static __device__ __align__(16) __nv_bfloat16 g_qcat_hi[(size_t)BH*SS*CD];
static __device__ __align__(16) __nv_bfloat16 g_qcat_lo[(size_t)BH*SS*CD];
static __device__ __align__(16) __nv_bfloat16 g_kcat_hi[(size_t)BH*SS*CD];
static __device__ __align__(16) __nv_bfloat16 g_kcat_lo[(size_t)BH*SS*CD];
static __device__ __align__(16) __nv_bfloat16 g_act_hi[(size_t)5*MM*HH];
static __device__ __align__(16) __nv_bfloat16 g_act_lo[(size_t)5*MM*HH];
static __device__ __align__(16) __nv_bfloat16 g_w_hi[(size_t)8*HH*HH];
static __device__ __align__(16) __nv_bfloat16 g_w_lo[(size_t)8*HH*HH];
static __device__ __align__(16) __nv_bfloat16 g_ctx_hi[(size_t)MM*HH];
static __device__ __align__(16) __nv_bfloat16 g_ctx_lo[(size_t)MM*HH];
static __device__ __align__(16) __nv_bfloat16 g_p_hi[(size_t)BH*SS*SS];   // probs hi
static __device__ __align__(16) __nv_bfloat16 g_p_lo[(size_t)BH*SS*SS];   // probs lo
static __device__ __align__(16) __nv_bfloat16 g_vT_hi[(size_t)BH*DD*SS];  // [bh][d][s]
static __device__ __align__(16) __nv_bfloat16 g_vT_lo[(size_t)BH*DD*SS];

// ---- 512-thread gemm geometry: tile 128x256, K-chunk 32, 3 stages ----
// stage layout: Ah[128x40] Al[128x40] Bh[256x40] Bl[256x40] (bf16, 80B rows)
#define A_SZ 10240                    // 128*40*2
#define B_SZ 20480                    // 256*40*2
#define BUF5 (2*A_SZ + 2*B_SZ)        // 61440
#define SMEM5 (3*BUF5)                // 184320

// ---- ctx tile geometry (128x64): Ph[128x40] Pl[128x40] Vh[64x40] Vl[64x40] ----
#define CTILE_A 10240                 // 128*40*2
#define CTILE_B 5120                  // 64*40*2
#define CBUF_B  (2*CTILE_A + 2*CTILE_B)  // 30720
#define CSMEM_B (3*CBUF_B)               // 92160

__device__ __forceinline__ uint32_t smem_to_u32(const void* p) {
    uint32_t a;
    asm("{ .reg .u64 t; cvta.to.shared.u64 t, %1; cvt.u32.u64 %0, t; }" : "=r"(a) : "l"(p));
    return a;
}
__device__ __forceinline__ void cp16(uint32_t s, const void* g) {
    asm volatile("cp.async.cg.shared.global [%0], [%1], 16;" :: "r"(s), "l"(g));
}
#define CP_COMMIT() asm volatile("cp.async.commit_group;" ::: "memory")
template<int N> __device__ __forceinline__ void cp_wait() {
    asm volatile("cp.async.wait_group %0;" :: "n"(N) : "memory");
}

__device__ __forceinline__ void mma_bf(float* c, const uint32_t* a, const uint32_t* b) {
    asm volatile(
        "mma.sync.aligned.m16n8k16.row.col.f32.bf16.bf16.f32 "
        "{%0,%1,%2,%3}, {%4,%5,%6,%7}, {%8,%9}, {%0,%1,%2,%3};"
        : "+f"(c[0]), "+f"(c[1]), "+f"(c[2]), "+f"(c[3])
        : "r"(a[0]), "r"(a[1]), "r"(a[2]), "r"(a[3]), "r"(b[0]), "r"(b[1]));
}

__device__ __forceinline__ void ldsm_x4(uint32_t* r, uint32_t addr) {
    asm volatile("ldmatrix.sync.aligned.m8n8.x4.shared.b16 {%0,%1,%2,%3}, [%4];"
        : "=r"(r[0]), "=r"(r[1]), "=r"(r[2]), "=r"(r[3]) : "r"(addr));
}

// Load one K-chunk: A(hi,lo) 128 rows + B(hi,lo) 256 rows. 512 threads.
__device__ __forceinline__ void load_chunk512(uint32_t sbuf, int tid,
    const __nv_bfloat16* __restrict__ Ah, const __nv_bfloat16* __restrict__ Al, int lda,
    const __nv_bfloat16* __restrict__ Bh, const __nv_bfloat16* __restrict__ Bl, int ldb,
    int m0, int n0, int k0) {
    // A: 1024 cp16 slots (128 rows x 4 col-groups x 2 hi/lo)
    #pragma unroll
    for (int j = 0; j < 2; j++) {
        const int u = tid + 512*j;
        const int row = u >> 3, rem = u & 7;
        const int hl = rem >> 2, cg = (rem & 3) * 8;
        const uint32_t so = (uint32_t)(row*80 + cg*2);
        const __nv_bfloat16* src = (hl ? Al : Ah) + (size_t)(m0+row)*lda + k0 + cg;
        cp16(sbuf + (uint32_t)hl*A_SZ + so, src);
    }
    // B: 2048 cp16 slots (256 rows x 4 col-groups x 2 hi/lo)
    #pragma unroll
    for (int j = 0; j < 4; j++) {
        const int u = tid + 512*j;
        const int row = u >> 3, rem = u & 7;
        const int hl = rem >> 2, cg = (rem & 3) * 8;
        const uint32_t so = (uint32_t)(row*80 + cg*2);
        const __nv_bfloat16* src = (hl ? Bl : Bh) + (size_t)(n0+row)*ldb + k0 + cg;
        cp16(sbuf + 2*A_SZ + (uint32_t)hl*B_SZ + so, src);
    }
    CP_COMMIT();
}

// One K-chunk of bf16x3 mma (warp tile 64x32; wm in 0..1, wn in 0..7).
__device__ __forceinline__ void mma_chunk512(uint32_t buf, int lane, int wm, int wn,
                                             float acc[4][4][4]) {
    const uint32_t l7 = lane & 7, l8 = (lane >> 3) & 1, l16 = (lane >> 4) & 1;
    #pragma unroll
    for (int kk = 0; kk < 2; kk++) {
        const uint32_t colA = kk*32 + l16*16;
        const uint32_t colB = kk*32 + l8*16;
        uint32_t ah[4][4], al[4][4], bh[4][2], bl[4][2];
        #pragma unroll
        for (int mt = 0; mt < 4; mt++) {
            const uint32_t row = wm*64 + mt*16 + l7 + l8*8;
            ldsm_x4(ah[mt], buf + row*80 + colA);
            ldsm_x4(al[mt], buf + A_SZ + row*80 + colA);
        }
        #pragma unroll
        for (int np = 0; np < 2; np++) {
            const uint32_t row = wn*32 + np*16 + l7 + l16*8;
            uint32_t t0[4], t1[4];
            ldsm_x4(t0, buf + 2*A_SZ + row*80 + colB);
            ldsm_x4(t1, buf + 2*A_SZ + B_SZ + row*80 + colB);
            bh[2*np][0] = t0[0]; bh[2*np][1] = t0[1];
            bh[2*np+1][0] = t0[2]; bh[2*np+1][1] = t0[3];
            bl[2*np][0] = t1[0]; bl[2*np][1] = t1[1];
            bl[2*np+1][0] = t1[2]; bl[2*np+1][1] = t1[3];
        }
        #pragma unroll
        for (int mt = 0; mt < 4; mt++)
            #pragma unroll
            for (int nt = 0; nt < 4; nt++)
                mma_bf(acc[mt][nt], ah[mt], bh[nt]);
        #pragma unroll
        for (int mt = 0; mt < 4; mt++)
            #pragma unroll
            for (int nt = 0; nt < 4; nt++)
                mma_bf(acc[mt][nt], ah[mt], bl[nt]);
        #pragma unroll
        for (int mt = 0; mt < 4; mt++)
            #pragma unroll
            for (int nt = 0; nt < 4; nt++)
                mma_bf(acc[mt][nt], al[mt], bh[nt]);
    }
}

// ============================================================
// Kernel 0: convert fp32 -> bf16 hi/lo.
// ============================================================
struct ConvArgs { const float* src[13]; };

__global__ void convert_kernel(ConvArgs ca) {
    const int z = blockIdx.z;
    const size_t nvec = (z < 5) ? (size_t)MM*HH/4 : (size_t)HH*HH/4;
    const size_t i = (size_t)blockIdx.x * 256 + threadIdx.x;
    if (i >= nvec) return;
    const float4 v = ((const float4*)ca.src[z])[i];

    __nv_bfloat16 h0 = __float2bfloat16_rn(v.x);
    __nv_bfloat16 h1 = __float2bfloat16_rn(v.y);
    __nv_bfloat16 h2 = __float2bfloat16_rn(v.z);
    __nv_bfloat16 h3 = __float2bfloat16_rn(v.w);
    __nv_bfloat16 l0 = __float2bfloat16_rn(v.x - __bfloat162float(h0));
    __nv_bfloat16 l1 = __float2bfloat16_rn(v.y - __bfloat162float(h1));
    __nv_bfloat16 l2 = __float2bfloat16_rn(v.z - __bfloat162float(h2));
    __nv_bfloat16 l3 = __float2bfloat16_rn(v.w - __bfloat162float(h3));

    __nv_bfloat16 *dh, *dl;
    if (z < 5) { dh = g_act_hi + (size_t)z*MM*HH + i*4; dl = g_act_lo + (size_t)z*MM*HH + i*4; }
    else       { dh = g_w_hi + (size_t)(z-5)*HH*HH + i*4; dl = g_w_lo + (size_t)(z-5)*HH*HH + i*4; }
    *(ushort4*)dh = make_ushort4(__bfloat16_as_ushort(h0), __bfloat16_as_ushort(h1),
                                 __bfloat16_as_ushort(h2), __bfloat16_as_ushort(h3));
    *(ushort4*)dl = make_ushort4(__bfloat16_as_ushort(l0), __bfloat16_as_ushort(l1),
                                 __bfloat16_as_ushort(l2), __bfloat16_as_ushort(l3));
}

// ============================================================
// Kernel 1: 7 fused projections, 128x256 tiles, 512 threads.
// ============================================================
struct TCArgs { const float* bias[7]; };

__global__ void __launch_bounds__(512) proj_mma_kernel(TCArgs ta) {
    extern __shared__ char smem[];
    const int tid = threadIdx.x, lane = tid & 31, w = tid >> 5;
    const int wm = w & 1, wn = w >> 1;
    const int z = blockIdx.z;
    const int ai = (z <= 2) ? z : (z <= 4 ? 3 : 4);
    const int m0 = blockIdx.y * 128, n0 = blockIdx.x * 256;

    const __nv_bfloat16* Ah = g_act_hi + (size_t)ai*MM*HH;
    const __nv_bfloat16* Al = g_act_lo + (size_t)ai*MM*HH;
    const __nv_bfloat16* Bh = g_w_hi + (size_t)z*HH*HH;
    const __nv_bfloat16* Bl = g_w_lo + (size_t)z*HH*HH;
    const uint32_t sb = smem_to_u32(smem);

    float acc[4][4][4];
    #pragma unroll
    for (int a = 0; a < 4; a++)
        #pragma unroll
        for (int b = 0; b < 4; b++)
            #pragma unroll
            for (int c = 0; c < 4; c++) acc[a][b][c] = 0.f;

    load_chunk512(sb,        tid, Ah, Al, HH, Bh, Bl, HH, m0, n0, 0);
    load_chunk512(sb + BUF5, tid, Ah, Al, HH, Bh, Bl, HH, m0, n0, 32);
    const int KT = HH / 32;  // 32
    for (int t = 0; t < KT; t++) {
        cp_wait<1>();
        __syncthreads();
        if (t + 2 < KT)
            load_chunk512(sb + (uint32_t)((t+2)%3)*BUF5, tid,
                          Ah, Al, HH, Bh, Bl, HH, m0, n0, (t+2)*32);
        else
            CP_COMMIT();
        mma_chunk512(sb + (uint32_t)(t%3)*BUF5, lane, wm, wn, acc);
    }

    int od0 = 0;
    __nv_bfloat16 *dh = nullptr, *dl = nullptr;
    switch (z) {
        case 0: dh = g_qcat_hi; dl = g_qcat_lo; od0 = 0;   break;
        case 1: dh = g_kcat_hi; dl = g_kcat_lo; od0 = 0;   break;
        case 2: break;  // v -> fp32
        case 3: dh = g_qcat_hi; dl = g_qcat_lo; od0 = 64;  break;
        case 4: dh = g_kcat_hi; dl = g_kcat_lo; od0 = 64;  break;
        case 5: dh = g_qcat_hi; dl = g_qcat_lo; od0 = 128; break;
        default: dh = g_kcat_hi; dl = g_kcat_lo; od0 = 128; break;
    }
    const float* bias = ta.bias[z];
    const int r0 = lane >> 2, tig = lane & 3;
    #pragma unroll
    for (int mt = 0; mt < 4; mt++)
        #pragma unroll
        for (int nt = 0; nt < 4; nt++) {
            const int n = n0 + wn*32 + nt*8 + tig*2;
            const float bv0 = bias[n], bv1 = bias[n+1];
            const int h = n >> 6, d = n & 63;
            #pragma unroll
            for (int rr = 0; rr < 2; rr++) {
                const int m = m0 + wm*64 + mt*16 + r0 + rr*8;
                const int b_ = m >> 9, s = m & 511;
                const float v0 = acc[mt][nt][rr*2]   + bv0;
                const float v1 = acc[mt][nt][rr*2+1] + bv1;
                if (z == 2) {
                    float2 t2 = make_float2(v0, v1);
                    *(float2*)&g_v[((size_t)((b_*NHD + h)*SS + s))*DD + d] = t2;
                } else {
                    const size_t idx = ((size_t)((b_*NHD + h)*SS + s))*CD + od0 + d;
                    __nv_bfloat16 h0 = __float2bfloat16_rn(v0);
                    __nv_bfloat16 h1 = __float2bfloat16_rn(v1);
                    __nv_bfloat16 q0 = __float2bfloat16_rn(v0 - __bfloat162float(h0));
                    __nv_bfloat16 q1 = __float2bfloat16_rn(v1 - __bfloat162float(h1));
                    *(uint32_t*)&dh[idx] =
                        ((uint32_t)__bfloat16_as_ushort(h1) << 16) | __bfloat16_as_ushort(h0);
                    *(uint32_t*)&dl[idx] =
                        ((uint32_t)__bfloat16_as_ushort(q1) << 16) | __bfloat16_as_ushort(q0);
                }
            }
        }
}

// ============================================================
// Kernel 1b: V transpose + hi/lo convert.
// ============================================================
__global__ void vt_kernel() {
    __shared__ float t[32][33];
    const int bh = blockIdx.z;
    const int s0 = blockIdx.x * 32, d0 = blockIdx.y * 32;
    const int tx = threadIdx.x, ty = threadIdx.y;
    const float* src = g_v + (size_t)bh*SS*DD;
    #pragma unroll
    for (int i = 0; i < 4; i++)
        t[ty + i*8][tx] = src[(size_t)(s0 + ty + i*8)*DD + d0 + tx];
    __syncthreads();
    #pragma unroll
    for (int i = 0; i < 4; i++) {
        const int d = d0 + ty + i*8, s = s0 + tx;
        const float v = t[tx][ty + i*8];
        const __nv_bfloat16 h = __float2bfloat16_rn(v);
        const __nv_bfloat16 l = __float2bfloat16_rn(v - __bfloat162float(h));
        g_vT_hi[(size_t)(bh*DD + d)*SS + s] = h;
        g_vT_lo[(size_t)(bh*DD + d)*SS + s] = l;
    }
}

// ============================================================
// Kernel 2: scores per (b,h), 128x256 tiles, 512 threads.
// ============================================================
__global__ void __launch_bounds__(512) scores_mma_kernel(
    const float* __restrict__ mask, float* __restrict__ attnmap) {
    extern __shared__ char smem[];
    const int tid = threadIdx.x, lane = tid & 31, w = tid >> 5;
    const int wm = w & 1, wn = w >> 1;
    const int bh = blockIdx.z, b_ = bh >> 4;
    const int m0 = blockIdx.y * 128, n0 = blockIdx.x * 256;

    const __nv_bfloat16* Ah = g_qcat_hi + (size_t)bh*SS*CD;
    const __nv_bfloat16* Al = g_qcat_lo + (size_t)bh*SS*CD;
    const __nv_bfloat16* Bh = g_kcat_hi + (size_t)bh*SS*CD;
    const __nv_bfloat16* Bl = g_kcat_lo + (size_t)bh*SS*CD;
    const uint32_t sb = smem_to_u32(smem);
    const int r0 = lane >> 2, tig = lane & 3;

    float acc[4][4][4];
    #pragma unroll
    for (int a = 0; a < 4; a++)
        #pragma unroll
        for (int b = 0; b < 4; b++)
            #pragma unroll
            for (int c = 0; c < 4; c++) acc[a][b][c] = 0.f;

    load_chunk512(sb,        tid, Ah, Al, CD, Bh, Bl, CD, m0, n0, 0);
    load_chunk512(sb + BUF5, tid, Ah, Al, CD, Bh, Bl, CD, m0, n0, 32);
    const int KT = CD / 32;  // 6
    for (int t = 0; t < KT; t++) {
        cp_wait<1>();
        __syncthreads();
        if (t + 2 < KT)
            load_chunk512(sb + (uint32_t)((t+2)%3)*BUF5, tid,
                          Ah, Al, CD, Bh, Bl, CD, m0, n0, (t+2)*32);
        else
            CP_COMMIT();
        mma_chunk512(sb + (uint32_t)(t%3)*BUF5, lane, wm, wn, acc);
        if (t == 1) {  // content part (K=0..63) complete -> attention_map
            float* amb = attnmap + (size_t)bh*SS*SS;
            #pragma unroll
            for (int mt = 0; mt < 4; mt++)
                #pragma unroll
                for (int nt = 0; nt < 4; nt++) {
                    const int n = n0 + wn*32 + nt*8 + tig*2;
                    #pragma unroll
                    for (int rr = 0; rr < 2; rr++) {
                        const int m = m0 + wm*64 + mt*16 + r0 + rr*8;
                        float2 t2 = make_float2(acc[mt][nt][rr*2], acc[mt][nt][rr*2+1]);
                        *(float2*)&amb[(size_t)m*SS + n] = t2;
                    }
                }
        }
    }

    float* scb = g_scores + (size_t)bh*SS*SS;
    #pragma unroll
    for (int mt = 0; mt < 4; mt++)
        #pragma unroll
        for (int nt = 0; nt < 4; nt++) {
            const int n = n0 + wn*32 + nt*8 + tig*2;
            #pragma unroll
            for (int rr = 0; rr < 2; rr++) {
                const int m = m0 + wm*64 + mt*16 + r0 + rr*8;
                const float2 mk = *(const float2*)&mask[((size_t)b_*SS + m)*SS + n];
                float2 t2 = make_float2(acc[mt][nt][rr*2]*0.125f + mk.x,
                                        acc[mt][nt][rr*2+1]*0.125f + mk.y);
                *(float2*)&scb[(size_t)m*SS + n] = t2;
            }
        }
}

// ============================================================
// Kernel 3: row softmax on g_scores -> g_p_{hi,lo} bf16.
// ============================================================
__global__ void softmax_kernel() {
    const size_t r = blockIdx.x;
    const float* row = g_scores + r * SS;
    float4 v = ((const float4*)row)[threadIdx.x];

    float mx = fmaxf(fmaxf(v.x, v.y), fmaxf(v.z, v.w));
    #pragma unroll
    for (int o = 16; o; o >>= 1) mx = fmaxf(mx, __shfl_xor_sync(0xffffffffu, mx, o));
    __shared__ float sm[4];
    const int w = threadIdx.x >> 5;
    if ((threadIdx.x & 31) == 0) sm[w] = mx;
    __syncthreads();
    mx = fmaxf(fmaxf(sm[0], sm[1]), fmaxf(sm[2], sm[3]));

    v.x = expf(v.x - mx); v.y = expf(v.y - mx);
    v.z = expf(v.z - mx); v.w = expf(v.w - mx);
    float s = v.x + v.y + v.z + v.w;
    #pragma unroll
    for (int o = 16; o; o >>= 1) s += __shfl_xor_sync(0xffffffffu, s, o);
    __shared__ float ss[4];
    if ((threadIdx.x & 31) == 0) ss[w] = s;
    __syncthreads();
    s = ss[0] + ss[1] + ss[2] + ss[3];

    const float inv = 1.f / s;
    v.x *= inv; v.y *= inv; v.z *= inv; v.w *= inv;

    const __nv_bfloat16 h0 = __float2bfloat16_rn(v.x);
    const __nv_bfloat16 h1 = __float2bfloat16_rn(v.y);
    const __nv_bfloat16 h2 = __float2bfloat16_rn(v.z);
    const __nv_bfloat16 h3 = __float2bfloat16_rn(v.w);
    const __nv_bfloat16 l0 = __float2bfloat16_rn(v.x - __bfloat162float(h0));
    const __nv_bfloat16 l1 = __float2bfloat16_rn(v.y - __bfloat162float(h1));
    const __nv_bfloat16 l2 = __float2bfloat16_rn(v.z - __bfloat162float(h2));
    const __nv_bfloat16 l3 = __float2bfloat16_rn(v.w - __bfloat162float(h3));
    ((ushort4*)(g_p_hi + r*SS))[threadIdx.x] =
        make_ushort4(__bfloat16_as_ushort(h0), __bfloat16_as_ushort(h1),
                     __bfloat16_as_ushort(h2), __bfloat16_as_ushort(h3));
    ((ushort4*)(g_p_lo + r*SS))[threadIdx.x] =
        make_ushort4(__bfloat16_as_ushort(l0), __bfloat16_as_ushort(l1),
                     __bfloat16_as_ushort(l2), __bfloat16_as_ushort(l3));
}

// ============================================================
// Kernel 4: ctx = P @ V via mma bf16x3, 3-stage, 1 sync/chunk.
// ============================================================
__device__ __forceinline__ void ctx_load_chunk(uint32_t sbuf, int tid,
    const __nv_bfloat16* __restrict__ Ph, const __nv_bfloat16* __restrict__ Pl,
    const __nv_bfloat16* __restrict__ Vh, const __nv_bfloat16* __restrict__ Vl,
    int m0, int k0) {
    #pragma unroll
    for (int j = 0; j < 2; j++) {
        const int u = tid + 256*j;               // 0..511
        const int row = u >> 2, cg = (u & 3) * 8;
        const uint32_t so = (uint32_t)(row*40 + cg)*2;
        const size_t ga = (size_t)(m0+row)*SS + k0 + cg;
        cp16(sbuf + so,           Ph + ga);
        cp16(sbuf + CTILE_A + so, Pl + ga);
    }
    {
        const int u = tid;                        // 0..255
        const int row = u >> 2, cg = (u & 3) * 8;
        const uint32_t so = (uint32_t)(row*40 + cg)*2;
        const size_t gb = (size_t)row*SS + k0 + cg;
        cp16(sbuf + 2*CTILE_A + so,           Vh + gb);
        cp16(sbuf + 2*CTILE_A + CTILE_B + so, Vl + gb);
    }
    CP_COMMIT();
}

__device__ __forceinline__ void ctx_mma_chunk(uint32_t buf, int lane, int wm, int wn,
                                              float acc[4][2][4]) {
    const uint32_t l7 = lane & 7, l8 = (lane >> 3) & 1, l16 = (lane >> 4) & 1;
    #pragma unroll
    for (int kk = 0; kk < 2; kk++) {
        const uint32_t colA = kk*32 + l16*16;
        const uint32_t colB = kk*32 + l8*16;
        uint32_t ah[4][4], al[4][4], bh[2][2], bl[2][2];
        #pragma unroll
        for (int mt = 0; mt < 4; mt++) {
            const uint32_t row = wm*64 + mt*16 + l7 + l8*8;
            ldsm_x4(ah[mt], buf + row*80 + colA);
            ldsm_x4(al[mt], buf + CTILE_A + row*80 + colA);
        }
        {
            const uint32_t row = wn*16 + l7 + l16*8;
            uint32_t t0[4], t1[4];
            ldsm_x4(t0, buf + 2*CTILE_A + row*80 + colB);
            ldsm_x4(t1, buf + 2*CTILE_A + CTILE_B + row*80 + colB);
            bh[0][0] = t0[0]; bh[0][1] = t0[1]; bh[1][0] = t0[2]; bh[1][1] = t0[3];
            bl[0][0] = t1[0]; bl[0][1] = t1[1]; bl[1][0] = t1[2]; bl[1][1] = t1[3];
        }
        #pragma unroll
        for (int mt = 0; mt < 4; mt++)
            #pragma unroll
            for (int nt = 0; nt < 2; nt++)
                mma_bf(acc[mt][nt], ah[mt], bh[nt]);
        #pragma unroll
        for (int mt = 0; mt < 4; mt++)
            #pragma unroll
            for (int nt = 0; nt < 2; nt++)
                mma_bf(acc[mt][nt], ah[mt], bl[nt]);
        #pragma unroll
        for (int mt = 0; mt < 4; mt++)
            #pragma unroll
            for (int nt = 0; nt < 2; nt++)
                mma_bf(acc[mt][nt], al[mt], bh[nt]);
    }
}

__global__ void __launch_bounds__(256) ctx_mma_kernel() {
    extern __shared__ char smem[];
    const int tid = threadIdx.x, lane = tid & 31, w = tid >> 5;
    const int wm = w & 1, wn = w >> 1;
    const int bh = blockIdx.y, b_ = bh >> 4, h = bh & 15;
    const int m0 = blockIdx.x * 128;

    const __nv_bfloat16* Ph = g_p_hi + (size_t)bh*SS*SS;
    const __nv_bfloat16* Pl = g_p_lo + (size_t)bh*SS*SS;
    const __nv_bfloat16* Vh = g_vT_hi + (size_t)bh*DD*SS;
    const __nv_bfloat16* Vl = g_vT_lo + (size_t)bh*DD*SS;
    const uint32_t sb = smem_to_u32(smem);

    float acc[4][2][4];
    #pragma unroll
    for (int a = 0; a < 4; a++)
        #pragma unroll
        for (int b = 0; b < 2; b++)
            #pragma unroll
            for (int c = 0; c < 4; c++) acc[a][b][c] = 0.f;

    ctx_load_chunk(sb,          tid, Ph, Pl, Vh, Vl, m0, 0);
    ctx_load_chunk(sb + CBUF_B, tid, Ph, Pl, Vh, Vl, m0, 32);
    const int KT = SS / 32;  // 16
    for (int t = 0; t < KT; t++) {
        cp_wait<1>();
        __syncthreads();
        if (t + 2 < KT)
            ctx_load_chunk(sb + (uint32_t)((t+2)%3)*CBUF_B, tid, Ph, Pl, Vh, Vl, m0, (t+2)*32);
        else
            CP_COMMIT();
        ctx_mma_chunk(sb + (uint32_t)(t%3)*CBUF_B, lane, wm, wn, acc);
    }

    const int r0 = lane >> 2, tig = lane & 3;
    #pragma unroll
    for (int mt = 0; mt < 4; mt++)
        #pragma unroll
        for (int nt = 0; nt < 2; nt++) {
            const int d = wn*16 + nt*8 + tig*2;
            #pragma unroll
            for (int rr = 0; rr < 2; rr++) {
                const int m = m0 + wm*64 + mt*16 + r0 + rr*8;
                const float v0 = acc[mt][nt][rr*2];
                const float v1 = acc[mt][nt][rr*2+1];
                const size_t idx = ((size_t)(b_*SS + m))*HH + h*DD + d;
                const __nv_bfloat16 h0 = __float2bfloat16_rn(v0);
                const __nv_bfloat16 h1 = __float2bfloat16_rn(v1);
                const __nv_bfloat16 q0 = __float2bfloat16_rn(v0 - __bfloat162float(h0));
                const __nv_bfloat16 q1 = __float2bfloat16_rn(v1 - __bfloat162float(h1));
                *(uint32_t*)&g_ctx_hi[idx] =
                    ((uint32_t)__bfloat16_as_ushort(h1) << 16) | __bfloat16_as_ushort(h0);
                *(uint32_t*)&g_ctx_lo[idx] =
                    ((uint32_t)__bfloat16_as_ushort(q1) << 16) | __bfloat16_as_ushort(q0);
            }
        }
}

// ============================================================
// Kernel 5: hidden = ctx @ Wd^T + bd, 128x256 tiles, 512 threads.
// ============================================================
__global__ void __launch_bounds__(512) final_mma_kernel(
    const float* __restrict__ bias, float* __restrict__ out) {
    extern __shared__ char smem[];
    const int tid = threadIdx.x, lane = tid & 31, w = tid >> 5;
    const int wm = w & 1, wn = w >> 1;
    const int m0 = blockIdx.y * 128, n0 = blockIdx.x * 256;

    const __nv_bfloat16* Ah = g_ctx_hi;
    const __nv_bfloat16* Al = g_ctx_lo;
    const __nv_bfloat16* Bh = g_w_hi + (size_t)7*HH*HH;
    const __nv_bfloat16* Bl = g_w_lo + (size_t)7*HH*HH;
    const uint32_t sb = smem_to_u32(smem);

    float acc[4][4][4];
    #pragma unroll
    for (int a = 0; a < 4; a++)
        #pragma unroll
        for (int b = 0; b < 4; b++)
            #pragma unroll
            for (int c = 0; c < 4; c++) acc[a][b][c] = 0.f;

    load_chunk512(sb,        tid, Ah, Al, HH, Bh, Bl, HH, m0, n0, 0);
    load_chunk512(sb + BUF5, tid, Ah, Al, HH, Bh, Bl, HH, m0, n0, 32);
    const int KT = HH / 32;
    for (int t = 0; t < KT; t++) {
        cp_wait<1>();
        __syncthreads();
        if (t + 2 < KT)
            load_chunk512(sb + (uint32_t)((t+2)%3)*BUF5, tid,
                          Ah, Al, HH, Bh, Bl, HH, m0, n0, (t+2)*32);
        else
            CP_COMMIT();
        mma_chunk512(sb + (uint32_t)(t%3)*BUF5, lane, wm, wn, acc);
    }

    const int r0 = lane >> 2, tig = lane & 3;
    #pragma unroll
    for (int mt = 0; mt < 4; mt++)
        #pragma unroll
        for (int nt = 0; nt < 4; nt++) {
            const int n = n0 + wn*32 + nt*8 + tig*2;
            const float bv0 = bias[n], bv1 = bias[n+1];
            #pragma unroll
            for (int rr = 0; rr < 2; rr++) {
                const int m = m0 + wm*64 + mt*16 + r0 + rr*8;
                float2 t2 = make_float2(acc[mt][nt][rr*2] + bv0,
                                        acc[mt][nt][rr*2+1] + bv1);
                *(float2*)&out[(size_t)m*HH + n] = t2;
            }
        }
}

// ============================================================
// Launch
// ============================================================
extern "C" void kernel_launch(void* const* d_in, const int* in_sizes, int n_in,
                              void* d_out, int out_size) {
    (void)in_sizes; (void)n_in; (void)out_size;

    const float* query = (const float*)d_in[0];
    const float* key   = (const float*)d_in[1];
    const float* value = (const float*)d_in[2];
    const float* mask  = (const float*)d_in[3];
    const float* pos   = (const float*)d_in[4];
    const float* feat  = (const float*)d_in[5];

    ConvArgs ca;
    ca.src[0] = query; ca.src[1] = key; ca.src[2] = value;
    ca.src[3] = pos;   ca.src[4] = feat;
    for (int i = 0; i < 7; i++) ca.src[5 + i] = (const float*)d_in[6 + 2*i];
    ca.src[12] = (const float*)d_in[20];  // Wd

    TCArgs ta;
    for (int i = 0; i < 7; i++) ta.bias[i] = (const float*)d_in[7 + 2*i];
    const float* bd = (const float*)d_in[21];

    float* out     = (float*)d_out;
    float* hidden  = out;                        // [B,S,H]
    float* attnmap = out + (size_t)MM * HH;      // [B,NH,S,S]

    cudaFuncSetAttribute(proj_mma_kernel,   cudaFuncAttributeMaxDynamicSharedMemorySize, SMEM5);
    cudaFuncSetAttribute(scores_mma_kernel, cudaFuncAttributeMaxDynamicSharedMemorySize, SMEM5);
    cudaFuncSetAttribute(final_mma_kernel,  cudaFuncAttributeMaxDynamicSharedMemorySize, SMEM5);
    cudaFuncSetAttribute(ctx_mma_kernel,    cudaFuncAttributeMaxDynamicSharedMemorySize, CSMEM_B);

    convert_kernel<<<dim3(4096, 1, 13), 256>>>(ca);
    proj_mma_kernel<<<dim3(4, 32, 7), 512, SMEM5>>>(ta);
    vt_kernel<<<dim3(16, 2, BH), dim3(32, 8)>>>();
    scores_mma_kernel<<<dim3(2, 4, BH), 512, SMEM5>>>(mask, attnmap);
    softmax_kernel<<<BH * SS, 128>>>();
    ctx_mma_kernel<<<dim3(4, BH), 256, CSMEM_B>>>();
    final_mma_kernel<<<dim3(4, 32), 512, SMEM5>>>(bd, hidden);
}

// round 11
// speedup vs baseline: 1.3808x; 1.3808x over previous
#include <cuda_runtime.h>
#include <cuda_bf16.h>
#include <math.h>
#include <cstdint>

#define BB 8
#define SS 512
#define HH 1024
#define NHD 16
#define DD 64
#define MM (BB*SS)      // 4096
#define BH (BB*NHD)     // 128
#define CD 192          // concatenated head dim (q|qp|qf)

// ---- scratch (device globals; no allocations allowed) ----
static __device__ __align__(16) float g_v[(size_t)BH*SS*DD];       // [bh][s][64] fp32
static __device__ __align__(16) float g_scores[(size_t)BH*SS*SS];  // [bh][q][k] fp32

static __device__ __align__(16) __nv_bfloat16 g_qcat_hi[(size_t)BH*SS*CD];
static __device__ __align__(16) __nv_bfloat16 g_qcat_lo[(size_t)BH*SS*CD];
static __device__ __align__(16) __nv_bfloat16 g_kcat_hi[(size_t)BH*SS*CD];
static __device__ __align__(16) __nv_bfloat16 g_kcat_lo[(size_t)BH*SS*CD];
static __device__ __align__(16) __nv_bfloat16 g_act_hi[(size_t)5*MM*HH];
static __device__ __align__(16) __nv_bfloat16 g_act_lo[(size_t)5*MM*HH];
static __device__ __align__(16) __nv_bfloat16 g_w_hi[(size_t)8*HH*HH];
static __device__ __align__(16) __nv_bfloat16 g_w_lo[(size_t)8*HH*HH];
static __device__ __align__(16) __nv_bfloat16 g_ctx_hi[(size_t)MM*HH];
static __device__ __align__(16) __nv_bfloat16 g_ctx_lo[(size_t)MM*HH];
static __device__ __align__(16) __nv_bfloat16 g_p_hi[(size_t)BH*SS*SS];   // probs hi
static __device__ __align__(16) __nv_bfloat16 g_p_lo[(size_t)BH*SS*SS];   // probs lo
static __device__ __align__(16) __nv_bfloat16 g_vT_hi[(size_t)BH*DD*SS];  // [bh][d][s]
static __device__ __align__(16) __nv_bfloat16 g_vT_lo[(size_t)BH*DD*SS];

// ---- gemm geometry: 256 thr, tile 128x128, K-chunk 16, 4 stages ----
// Row stride 24 halves (48 B): 16B-unit phase i*3 mod 8 -> conflict-free ldmatrix.
#define A_SZ6 6144                    // 128*24*2
#define STG_B (4*A_SZ6)               // 24576 (Ah, Al, Bh, Bl)
#define SMEM4 (4*STG_B)               // 98304

// ---- ctx geometry: tile 128x64, K-chunk 16, 4 stages ----
#define CT_A 6144                     // 128*24*2
#define CT_B 3072                     // 64*24*2
#define CSTG_B (2*CT_A + 2*CT_B)      // 18432
#define CSMEM4 (4*CSTG_B)             // 73728

__device__ __forceinline__ uint32_t smem_to_u32(const void* p) {
    uint32_t a;
    asm("{ .reg .u64 t; cvta.to.shared.u64 t, %1; cvt.u32.u64 %0, t; }" : "=r"(a) : "l"(p));
    return a;
}
__device__ __forceinline__ void cp16(uint32_t s, const void* g) {
    asm volatile("cp.async.cg.shared.global [%0], [%1], 16;" :: "r"(s), "l"(g));
}
#define CP_COMMIT() asm volatile("cp.async.commit_group;" ::: "memory")
template<int N> __device__ __forceinline__ void cp_wait() {
    asm volatile("cp.async.wait_group %0;" :: "n"(N) : "memory");
}

__device__ __forceinline__ void mma_bf(float* c, const uint32_t* a, const uint32_t* b) {
    asm volatile(
        "mma.sync.aligned.m16n8k16.row.col.f32.bf16.bf16.f32 "
        "{%0,%1,%2,%3}, {%4,%5,%6,%7}, {%8,%9}, {%0,%1,%2,%3};"
        : "+f"(c[0]), "+f"(c[1]), "+f"(c[2]), "+f"(c[3])
        : "r"(a[0]), "r"(a[1]), "r"(a[2]), "r"(a[3]), "r"(b[0]), "r"(b[1]));
}

__device__ __forceinline__ void ldsm_x4(uint32_t* r, uint32_t addr) {
    asm volatile("ldmatrix.sync.aligned.m8n8.x4.shared.b16 {%0,%1,%2,%3}, [%4];"
        : "=r"(r[0]), "=r"(r[1]), "=r"(r[2]), "=r"(r[3]) : "r"(addr));
}

// Load one K16 chunk: A(hi,lo) 128 rows + B(hi,lo) 128 rows. 256 threads, 4 cp16 each.
__device__ __forceinline__ void load_chunk16(uint32_t sbuf, int tid,
    const __nv_bfloat16* __restrict__ Ah, const __nv_bfloat16* __restrict__ Al, int lda,
    const __nv_bfloat16* __restrict__ Bh, const __nv_bfloat16* __restrict__ Bl, int ldb,
    int m0, int n0, int k0) {
    #pragma unroll
    for (int j = 0; j < 2; j++) {          // A: 512 slots
        const int u = tid + 256*j;
        const int row = u >> 2, rem = u & 3;
        const int hl = rem >> 1, cg = rem & 1;
        const uint32_t so = (uint32_t)(row*48 + cg*16);
        const __nv_bfloat16* src = (hl ? Al : Ah) + (size_t)(m0+row)*lda + k0 + cg*8;
        cp16(sbuf + (uint32_t)hl*A_SZ6 + so, src);
    }
    #pragma unroll
    for (int j = 0; j < 2; j++) {          // B: 512 slots
        const int u = tid + 256*j;
        const int row = u >> 2, rem = u & 3;
        const int hl = rem >> 1, cg = rem & 1;
        const uint32_t so = (uint32_t)(row*48 + cg*16);
        const __nv_bfloat16* src = (hl ? Bl : Bh) + (size_t)(n0+row)*ldb + k0 + cg*8;
        cp16(sbuf + 2*A_SZ6 + (uint32_t)hl*A_SZ6 + so, src);
    }
    CP_COMMIT();
}

// One K16 chunk of bf16x3 mma (warp tile 64x32; wm 0..1, wn 0..3).
__device__ __forceinline__ void mma_chunk16(uint32_t buf, int lane, int wm, int wn,
                                            float acc[4][4][4]) {
    const uint32_t l7 = lane & 7, l8 = (lane >> 3) & 1, l16 = (lane >> 4) & 1;
    const uint32_t colA = l16*16;
    const uint32_t colB = l8*16;
    uint32_t ah[4][4], al[4][4], bh[4][2], bl[4][2];
    #pragma unroll
    for (int mt = 0; mt < 4; mt++) {
        const uint32_t row = wm*64 + mt*16 + l7 + l8*8;
        ldsm_x4(ah[mt], buf + row*48 + colA);
        ldsm_x4(al[mt], buf + A_SZ6 + row*48 + colA);
    }
    #pragma unroll
    for (int np = 0; np < 2; np++) {
        const uint32_t row = wn*32 + np*16 + l7 + l16*8;
        uint32_t t0[4], t1[4];
        ldsm_x4(t0, buf + 2*A_SZ6 + row*48 + colB);
        ldsm_x4(t1, buf + 3*A_SZ6 + row*48 + colB);
        bh[2*np][0] = t0[0]; bh[2*np][1] = t0[1];
        bh[2*np+1][0] = t0[2]; bh[2*np+1][1] = t0[3];
        bl[2*np][0] = t1[0]; bl[2*np][1] = t1[1];
        bl[2*np+1][0] = t1[2]; bl[2*np+1][1] = t1[3];
    }
    #pragma unroll
    for (int mt = 0; mt < 4; mt++)
        #pragma unroll
        for (int nt = 0; nt < 4; nt++)
            mma_bf(acc[mt][nt], ah[mt], bh[nt]);
    #pragma unroll
    for (int mt = 0; mt < 4; mt++)
        #pragma unroll
        for (int nt = 0; nt < 4; nt++)
            mma_bf(acc[mt][nt], ah[mt], bl[nt]);
    #pragma unroll
    for (int mt = 0; mt < 4; mt++)
        #pragma unroll
        for (int nt = 0; nt < 4; nt++)
            mma_bf(acc[mt][nt], al[mt], bh[nt]);
}

// ============================================================
// Kernel 0: convert fp32 -> bf16 hi/lo.
// ============================================================
struct ConvArgs { const float* src[13]; };

__global__ void convert_kernel(ConvArgs ca) {
    const int z = blockIdx.z;
    const size_t nvec = (z < 5) ? (size_t)MM*HH/4 : (size_t)HH*HH/4;
    const size_t i = (size_t)blockIdx.x * 256 + threadIdx.x;
    if (i >= nvec) return;
    const float4 v = ((const float4*)ca.src[z])[i];

    __nv_bfloat16 h0 = __float2bfloat16_rn(v.x);
    __nv_bfloat16 h1 = __float2bfloat16_rn(v.y);
    __nv_bfloat16 h2 = __float2bfloat16_rn(v.z);
    __nv_bfloat16 h3 = __float2bfloat16_rn(v.w);
    __nv_bfloat16 l0 = __float2bfloat16_rn(v.x - __bfloat162float(h0));
    __nv_bfloat16 l1 = __float2bfloat16_rn(v.y - __bfloat162float(h1));
    __nv_bfloat16 l2 = __float2bfloat16_rn(v.z - __bfloat162float(h2));
    __nv_bfloat16 l3 = __float2bfloat16_rn(v.w - __bfloat162float(h3));

    __nv_bfloat16 *dh, *dl;
    if (z < 5) { dh = g_act_hi + (size_t)z*MM*HH + i*4; dl = g_act_lo + (size_t)z*MM*HH + i*4; }
    else       { dh = g_w_hi + (size_t)(z-5)*HH*HH + i*4; dl = g_w_lo + (size_t)(z-5)*HH*HH + i*4; }
    *(ushort4*)dh = make_ushort4(__bfloat16_as_ushort(h0), __bfloat16_as_ushort(h1),
                                 __bfloat16_as_ushort(h2), __bfloat16_as_ushort(h3));
    *(ushort4*)dl = make_ushort4(__bfloat16_as_ushort(l0), __bfloat16_as_ushort(l1),
                                 __bfloat16_as_ushort(l2), __bfloat16_as_ushort(l3));
}

// ============================================================
// Kernel 1: 7 fused projections, 128x128 tiles, 256 threads,
// K16 chunks, 4-stage ring, one sync per chunk.
// ============================================================
struct TCArgs { const float* bias[7]; };

__global__ void __launch_bounds__(256) proj_mma_kernel(TCArgs ta) {
    extern __shared__ char smem[];
    const int tid = threadIdx.x, lane = tid & 31, w = tid >> 5;
    const int wm = w & 1, wn = w >> 1;
    const int z = blockIdx.z;
    const int ai = (z <= 2) ? z : (z <= 4 ? 3 : 4);
    const int m0 = blockIdx.y * 128, n0 = blockIdx.x * 128;

    const __nv_bfloat16* Ah = g_act_hi + (size_t)ai*MM*HH;
    const __nv_bfloat16* Al = g_act_lo + (size_t)ai*MM*HH;
    const __nv_bfloat16* Bh = g_w_hi + (size_t)z*HH*HH;
    const __nv_bfloat16* Bl = g_w_lo + (size_t)z*HH*HH;
    const uint32_t sb = smem_to_u32(smem);

    float acc[4][4][4];
    #pragma unroll
    for (int a = 0; a < 4; a++)
        #pragma unroll
        for (int b = 0; b < 4; b++)
            #pragma unroll
            for (int c = 0; c < 4; c++) acc[a][b][c] = 0.f;

    load_chunk16(sb,           tid, Ah, Al, HH, Bh, Bl, HH, m0, n0, 0);
    load_chunk16(sb + STG_B,   tid, Ah, Al, HH, Bh, Bl, HH, m0, n0, 16);
    load_chunk16(sb + 2*STG_B, tid, Ah, Al, HH, Bh, Bl, HH, m0, n0, 32);
    const int KT = HH / 16;  // 64
    for (int t = 0; t < KT; t++) {
        cp_wait<2>();
        __syncthreads();
        if (t + 3 < KT)
            load_chunk16(sb + (uint32_t)((t+3)&3)*STG_B, tid,
                         Ah, Al, HH, Bh, Bl, HH, m0, n0, (t+3)*16);
        else
            CP_COMMIT();
        mma_chunk16(sb + (uint32_t)(t&3)*STG_B, lane, wm, wn, acc);
    }

    int od0 = 0;
    __nv_bfloat16 *dh = nullptr, *dl = nullptr;
    switch (z) {
        case 0: dh = g_qcat_hi; dl = g_qcat_lo; od0 = 0;   break;
        case 1: dh = g_kcat_hi; dl = g_kcat_lo; od0 = 0;   break;
        case 2: break;  // v -> fp32
        case 3: dh = g_qcat_hi; dl = g_qcat_lo; od0 = 64;  break;
        case 4: dh = g_kcat_hi; dl = g_kcat_lo; od0 = 64;  break;
        case 5: dh = g_qcat_hi; dl = g_qcat_lo; od0 = 128; break;
        default: dh = g_kcat_hi; dl = g_kcat_lo; od0 = 128; break;
    }
    const float* bias = ta.bias[z];
    const int r0 = lane >> 2, tig = lane & 3;
    #pragma unroll
    for (int mt = 0; mt < 4; mt++)
        #pragma unroll
        for (int nt = 0; nt < 4; nt++) {
            const int n = n0 + wn*32 + nt*8 + tig*2;
            const float bv0 = bias[n], bv1 = bias[n+1];
            const int h = n >> 6, d = n & 63;
            #pragma unroll
            for (int rr = 0; rr < 2; rr++) {
                const int m = m0 + wm*64 + mt*16 + r0 + rr*8;
                const int b_ = m >> 9, s = m & 511;
                const float v0 = acc[mt][nt][rr*2]   + bv0;
                const float v1 = acc[mt][nt][rr*2+1] + bv1;
                if (z == 2) {
                    float2 t2 = make_float2(v0, v1);
                    *(float2*)&g_v[((size_t)((b_*NHD + h)*SS + s))*DD + d] = t2;
                } else {
                    const size_t idx = ((size_t)((b_*NHD + h)*SS + s))*CD + od0 + d;
                    __nv_bfloat16 h0 = __float2bfloat16_rn(v0);
                    __nv_bfloat16 h1 = __float2bfloat16_rn(v1);
                    __nv_bfloat16 q0 = __float2bfloat16_rn(v0 - __bfloat162float(h0));
                    __nv_bfloat16 q1 = __float2bfloat16_rn(v1 - __bfloat162float(h1));
                    *(uint32_t*)&dh[idx] =
                        ((uint32_t)__bfloat16_as_ushort(h1) << 16) | __bfloat16_as_ushort(h0);
                    *(uint32_t*)&dl[idx] =
                        ((uint32_t)__bfloat16_as_ushort(q1) << 16) | __bfloat16_as_ushort(q0);
                }
            }
        }
}

// ============================================================
// Kernel 1b: V transpose + hi/lo convert.
// ============================================================
__global__ void vt_kernel() {
    __shared__ float t[32][33];
    const int bh = blockIdx.z;
    const int s0 = blockIdx.x * 32, d0 = blockIdx.y * 32;
    const int tx = threadIdx.x, ty = threadIdx.y;
    const float* src = g_v + (size_t)bh*SS*DD;
    #pragma unroll
    for (int i = 0; i < 4; i++)
        t[ty + i*8][tx] = src[(size_t)(s0 + ty + i*8)*DD + d0 + tx];
    __syncthreads();
    #pragma unroll
    for (int i = 0; i < 4; i++) {
        const int d = d0 + ty + i*8, s = s0 + tx;
        const float v = t[tx][ty + i*8];
        const __nv_bfloat16 h = __float2bfloat16_rn(v);
        const __nv_bfloat16 l = __float2bfloat16_rn(v - __bfloat162float(h));
        g_vT_hi[(size_t)(bh*DD + d)*SS + s] = h;
        g_vT_lo[(size_t)(bh*DD + d)*SS + s] = l;
    }
}

// ============================================================
// Kernel 2: scores per (b,h), 128x128, K16, 4-stage.
// Snapshot after chunk 3 (content K=0..63) -> attention_map.
// ============================================================
__global__ void __launch_bounds__(256) scores_mma_kernel(
    const float* __restrict__ mask, float* __restrict__ attnmap) {
    extern __shared__ char smem[];
    const int tid = threadIdx.x, lane = tid & 31, w = tid >> 5;
    const int wm = w & 1, wn = w >> 1;
    const int bh = blockIdx.z, b_ = bh >> 4;
    const int m0 = blockIdx.y * 128, n0 = blockIdx.x * 128;

    const __nv_bfloat16* Ah = g_qcat_hi + (size_t)bh*SS*CD;
    const __nv_bfloat16* Al = g_qcat_lo + (size_t)bh*SS*CD;
    const __nv_bfloat16* Bh = g_kcat_hi + (size_t)bh*SS*CD;
    const __nv_bfloat16* Bl = g_kcat_lo + (size_t)bh*SS*CD;
    const uint32_t sb = smem_to_u32(smem);
    const int r0 = lane >> 2, tig = lane & 3;

    float acc[4][4][4];
    #pragma unroll
    for (int a = 0; a < 4; a++)
        #pragma unroll
        for (int b = 0; b < 4; b++)
            #pragma unroll
            for (int c = 0; c < 4; c++) acc[a][b][c] = 0.f;

    load_chunk16(sb,           tid, Ah, Al, CD, Bh, Bl, CD, m0, n0, 0);
    load_chunk16(sb + STG_B,   tid, Ah, Al, CD, Bh, Bl, CD, m0, n0, 16);
    load_chunk16(sb + 2*STG_B, tid, Ah, Al, CD, Bh, Bl, CD, m0, n0, 32);
    const int KT = CD / 16;  // 12
    for (int t = 0; t < KT; t++) {
        cp_wait<2>();
        __syncthreads();
        if (t + 3 < KT)
            load_chunk16(sb + (uint32_t)((t+3)&3)*STG_B, tid,
                         Ah, Al, CD, Bh, Bl, CD, m0, n0, (t+3)*16);
        else
            CP_COMMIT();
        mma_chunk16(sb + (uint32_t)(t&3)*STG_B, lane, wm, wn, acc);
        if (t == 3) {  // content part (K=0..63) complete -> attention_map
            float* amb = attnmap + (size_t)bh*SS*SS;
            #pragma unroll
            for (int mt = 0; mt < 4; mt++)
                #pragma unroll
                for (int nt = 0; nt < 4; nt++) {
                    const int n = n0 + wn*32 + nt*8 + tig*2;
                    #pragma unroll
                    for (int rr = 0; rr < 2; rr++) {
                        const int m = m0 + wm*64 + mt*16 + r0 + rr*8;
                        float2 t2 = make_float2(acc[mt][nt][rr*2], acc[mt][nt][rr*2+1]);
                        *(float2*)&amb[(size_t)m*SS + n] = t2;
                    }
                }
        }
    }

    float* scb = g_scores + (size_t)bh*SS*SS;
    #pragma unroll
    for (int mt = 0; mt < 4; mt++)
        #pragma unroll
        for (int nt = 0; nt < 4; nt++) {
            const int n = n0 + wn*32 + nt*8 + tig*2;
            #pragma unroll
            for (int rr = 0; rr < 2; rr++) {
                const int m = m0 + wm*64 + mt*16 + r0 + rr*8;
                const float2 mk = *(const float2*)&mask[((size_t)b_*SS + m)*SS + n];
                float2 t2 = make_float2(acc[mt][nt][rr*2]*0.125f + mk.x,
                                        acc[mt][nt][rr*2+1]*0.125f + mk.y);
                *(float2*)&scb[(size_t)m*SS + n] = t2;
            }
        }
}

// ============================================================
// Kernel 3: row softmax on g_scores -> g_p_{hi,lo} bf16.
// ============================================================
__global__ void softmax_kernel() {
    const size_t r = blockIdx.x;
    const float* row = g_scores + r * SS;
    float4 v = ((const float4*)row)[threadIdx.x];

    float mx = fmaxf(fmaxf(v.x, v.y), fmaxf(v.z, v.w));
    #pragma unroll
    for (int o = 16; o; o >>= 1) mx = fmaxf(mx, __shfl_xor_sync(0xffffffffu, mx, o));
    __shared__ float sm[4];
    const int w = threadIdx.x >> 5;
    if ((threadIdx.x & 31) == 0) sm[w] = mx;
    __syncthreads();
    mx = fmaxf(fmaxf(sm[0], sm[1]), fmaxf(sm[2], sm[3]));

    v.x = expf(v.x - mx); v.y = expf(v.y - mx);
    v.z = expf(v.z - mx); v.w = expf(v.w - mx);
    float s = v.x + v.y + v.z + v.w;
    #pragma unroll
    for (int o = 16; o; o >>= 1) s += __shfl_xor_sync(0xffffffffu, s, o);
    __shared__ float ss[4];
    if ((threadIdx.x & 31) == 0) ss[w] = s;
    __syncthreads();
    s = ss[0] + ss[1] + ss[2] + ss[3];

    const float inv = 1.f / s;
    v.x *= inv; v.y *= inv; v.z *= inv; v.w *= inv;

    const __nv_bfloat16 h0 = __float2bfloat16_rn(v.x);
    const __nv_bfloat16 h1 = __float2bfloat16_rn(v.y);
    const __nv_bfloat16 h2 = __float2bfloat16_rn(v.z);
    const __nv_bfloat16 h3 = __float2bfloat16_rn(v.w);
    const __nv_bfloat16 l0 = __float2bfloat16_rn(v.x - __bfloat162float(h0));
    const __nv_bfloat16 l1 = __float2bfloat16_rn(v.y - __bfloat162float(h1));
    const __nv_bfloat16 l2 = __float2bfloat16_rn(v.z - __bfloat162float(h2));
    const __nv_bfloat16 l3 = __float2bfloat16_rn(v.w - __bfloat162float(h3));
    ((ushort4*)(g_p_hi + r*SS))[threadIdx.x] =
        make_ushort4(__bfloat16_as_ushort(h0), __bfloat16_as_ushort(h1),
                     __bfloat16_as_ushort(h2), __bfloat16_as_ushort(h3));
    ((ushort4*)(g_p_lo + r*SS))[threadIdx.x] =
        make_ushort4(__bfloat16_as_ushort(l0), __bfloat16_as_ushort(l1),
                     __bfloat16_as_ushort(l2), __bfloat16_as_ushort(l3));
}

// ============================================================
// Kernel 4: ctx = P @ V, 128x64 tiles, K16, 4-stage.
// ============================================================
__device__ __forceinline__ void ctx_load_chunk16(uint32_t sbuf, int tid,
    const __nv_bfloat16* __restrict__ Ph, const __nv_bfloat16* __restrict__ Pl,
    const __nv_bfloat16* __restrict__ Vh, const __nv_bfloat16* __restrict__ Vl,
    int m0, int k0) {
    #pragma unroll
    for (int j = 0; j < 2; j++) {          // P: 512 slots
        const int u = tid + 256*j;
        const int row = u >> 2, rem = u & 3;
        const int hl = rem >> 1, cg = rem & 1;
        const uint32_t so = (uint32_t)(row*48 + cg*16);
        const __nv_bfloat16* src = (hl ? Pl : Ph) + (size_t)(m0+row)*SS + k0 + cg*8;
        cp16(sbuf + (uint32_t)hl*CT_A + so, src);
    }
    {                                      // V: 256 slots (64 rows)
        const int u = tid;
        const int row = u >> 2, rem = u & 3;
        const int hl = rem >> 1, cg = rem & 1;
        const uint32_t so = (uint32_t)(row*48 + cg*16);
        const __nv_bfloat16* src = (hl ? Vl : Vh) + (size_t)row*SS + k0 + cg*8;
        cp16(sbuf + 2*CT_A + (uint32_t)hl*CT_B + so, src);
    }
    CP_COMMIT();
}

__device__ __forceinline__ void ctx_mma_chunk16(uint32_t buf, int lane, int wm, int wn,
                                                float acc[4][2][4]) {
    const uint32_t l7 = lane & 7, l8 = (lane >> 3) & 1, l16 = (lane >> 4) & 1;
    const uint32_t colA = l16*16;
    const uint32_t colB = l8*16;
    uint32_t ah[4][4], al[4][4], bh[2][2], bl[2][2];
    #pragma unroll
    for (int mt = 0; mt < 4; mt++) {
        const uint32_t row = wm*64 + mt*16 + l7 + l8*8;
        ldsm_x4(ah[mt], buf + row*48 + colA);
        ldsm_x4(al[mt], buf + CT_A + row*48 + colA);
    }
    {
        const uint32_t row = wn*16 + l7 + l16*8;
        uint32_t t0[4], t1[4];
        ldsm_x4(t0, buf + 2*CT_A + row*48 + colB);
        ldsm_x4(t1, buf + 2*CT_A + CT_B + row*48 + colB);
        bh[0][0] = t0[0]; bh[0][1] = t0[1]; bh[1][0] = t0[2]; bh[1][1] = t0[3];
        bl[0][0] = t1[0]; bl[0][1] = t1[1]; bl[1][0] = t1[2]; bl[1][1] = t1[3];
    }
    #pragma unroll
    for (int mt = 0; mt < 4; mt++)
        #pragma unroll
        for (int nt = 0; nt < 2; nt++)
            mma_bf(acc[mt][nt], ah[mt], bh[nt]);
    #pragma unroll
    for (int mt = 0; mt < 4; mt++)
        #pragma unroll
        for (int nt = 0; nt < 2; nt++)
            mma_bf(acc[mt][nt], ah[mt], bl[nt]);
    #pragma unroll
    for (int mt = 0; mt < 4; mt++)
        #pragma unroll
        for (int nt = 0; nt < 2; nt++)
            mma_bf(acc[mt][nt], al[mt], bh[nt]);
}

__global__ void __launch_bounds__(256) ctx_mma_kernel() {
    extern __shared__ char smem[];
    const int tid = threadIdx.x, lane = tid & 31, w = tid >> 5;
    const int wm = w & 1, wn = w >> 1;
    const int bh = blockIdx.y, b_ = bh >> 4, h = bh & 15;
    const int m0 = blockIdx.x * 128;

    const __nv_bfloat16* Ph = g_p_hi + (size_t)bh*SS*SS;
    const __nv_bfloat16* Pl = g_p_lo + (size_t)bh*SS*SS;
    const __nv_bfloat16* Vh = g_vT_hi + (size_t)bh*DD*SS;
    const __nv_bfloat16* Vl = g_vT_lo + (size_t)bh*DD*SS;
    const uint32_t sb = smem_to_u32(smem);

    float acc[4][2][4];
    #pragma unroll
    for (int a = 0; a < 4; a++)
        #pragma unroll
        for (int b = 0; b < 2; b++)
            #pragma unroll
            for (int c = 0; c < 4; c++) acc[a][b][c] = 0.f;

    ctx_load_chunk16(sb,            tid, Ph, Pl, Vh, Vl, m0, 0);
    ctx_load_chunk16(sb + CSTG_B,   tid, Ph, Pl, Vh, Vl, m0, 16);
    ctx_load_chunk16(sb + 2*CSTG_B, tid, Ph, Pl, Vh, Vl, m0, 32);
    const int KT = SS / 16;  // 32
    for (int t = 0; t < KT; t++) {
        cp_wait<2>();
        __syncthreads();
        if (t + 3 < KT)
            ctx_load_chunk16(sb + (uint32_t)((t+3)&3)*CSTG_B, tid, Ph, Pl, Vh, Vl, m0, (t+3)*16);
        else
            CP_COMMIT();
        ctx_mma_chunk16(sb + (uint32_t)(t&3)*CSTG_B, lane, wm, wn, acc);
    }

    const int r0 = lane >> 2, tig = lane & 3;
    #pragma unroll
    for (int mt = 0; mt < 4; mt++)
        #pragma unroll
        for (int nt = 0; nt < 2; nt++) {
            const int d = wn*16 + nt*8 + tig*2;
            #pragma unroll
            for (int rr = 0; rr < 2; rr++) {
                const int m = m0 + wm*64 + mt*16 + r0 + rr*8;
                const float v0 = acc[mt][nt][rr*2];
                const float v1 = acc[mt][nt][rr*2+1];
                const size_t idx = ((size_t)(b_*SS + m))*HH + h*DD + d;
                const __nv_bfloat16 h0 = __float2bfloat16_rn(v0);
                const __nv_bfloat16 h1 = __float2bfloat16_rn(v1);
                const __nv_bfloat16 q0 = __float2bfloat16_rn(v0 - __bfloat162float(h0));
                const __nv_bfloat16 q1 = __float2bfloat16_rn(v1 - __bfloat162float(h1));
                *(uint32_t*)&g_ctx_hi[idx] =
                    ((uint32_t)__bfloat16_as_ushort(h1) << 16) | __bfloat16_as_ushort(h0);
                *(uint32_t*)&g_ctx_lo[idx] =
                    ((uint32_t)__bfloat16_as_ushort(q1) << 16) | __bfloat16_as_ushort(q0);
            }
        }
}

// ============================================================
// Kernel 5: hidden = ctx @ Wd^T + bd, 128x128, K16, 4-stage.
// ============================================================
__global__ void __launch_bounds__(256) final_mma_kernel(
    const float* __restrict__ bias, float* __restrict__ out) {
    extern __shared__ char smem[];
    const int tid = threadIdx.x, lane = tid & 31, w = tid >> 5;
    const int wm = w & 1, wn = w >> 1;
    const int m0 = blockIdx.y * 128, n0 = blockIdx.x * 128;

    const __nv_bfloat16* Ah = g_ctx_hi;
    const __nv_bfloat16* Al = g_ctx_lo;
    const __nv_bfloat16* Bh = g_w_hi + (size_t)7*HH*HH;
    const __nv_bfloat16* Bl = g_w_lo + (size_t)7*HH*HH;
    const uint32_t sb = smem_to_u32(smem);

    float acc[4][4][4];
    #pragma unroll
    for (int a = 0; a < 4; a++)
        #pragma unroll
        for (int b = 0; b < 4; b++)
            #pragma unroll
            for (int c = 0; c < 4; c++) acc[a][b][c] = 0.f;

    load_chunk16(sb,           tid, Ah, Al, HH, Bh, Bl, HH, m0, n0, 0);
    load_chunk16(sb + STG_B,   tid, Ah, Al, HH, Bh, Bl, HH, m0, n0, 16);
    load_chunk16(sb + 2*STG_B, tid, Ah, Al, HH, Bh, Bl, HH, m0, n0, 32);
    const int KT = HH / 16;  // 64
    for (int t = 0; t < KT; t++) {
        cp_wait<2>();
        __syncthreads();
        if (t + 3 < KT)
            load_chunk16(sb + (uint32_t)((t+3)&3)*STG_B, tid,
                         Ah, Al, HH, Bh, Bl, HH, m0, n0, (t+3)*16);
        else
            CP_COMMIT();
        mma_chunk16(sb + (uint32_t)(t&3)*STG_B, lane, wm, wn, acc);
    }

    const int r0 = lane >> 2, tig = lane & 3;
    #pragma unroll
    for (int mt = 0; mt < 4; mt++)
        #pragma unroll
        for (int nt = 0; nt < 4; nt++) {
            const int n = n0 + wn*32 + nt*8 + tig*2;
            const float bv0 = bias[n], bv1 = bias[n+1];
            #pragma unroll
            for (int rr = 0; rr < 2; rr++) {
                const int m = m0 + wm*64 + mt*16 + r0 + rr*8;
                float2 t2 = make_float2(acc[mt][nt][rr*2] + bv0,
                                        acc[mt][nt][rr*2+1] + bv1);
                *(float2*)&out[(size_t)m*HH + n] = t2;
            }
        }
}

// ============================================================
// Launch
// ============================================================
extern "C" void kernel_launch(void* const* d_in, const int* in_sizes, int n_in,
                              void* d_out, int out_size) {
    (void)in_sizes; (void)n_in; (void)out_size;

    const float* query = (const float*)d_in[0];
    const float* key   = (const float*)d_in[1];
    const float* value = (const float*)d_in[2];
    const float* mask  = (const float*)d_in[3];
    const float* pos   = (const float*)d_in[4];
    const float* feat  = (const float*)d_in[5];

    ConvArgs ca;
    ca.src[0] = query; ca.src[1] = key; ca.src[2] = value;
    ca.src[3] = pos;   ca.src[4] = feat;
    for (int i = 0; i < 7; i++) ca.src[5 + i] = (const float*)d_in[6 + 2*i];
    ca.src[12] = (const float*)d_in[20];  // Wd

    TCArgs ta;
    for (int i = 0; i < 7; i++) ta.bias[i] = (const float*)d_in[7 + 2*i];
    const float* bd = (const float*)d_in[21];

    float* out     = (float*)d_out;
    float* hidden  = out;                        // [B,S,H]
    float* attnmap = out + (size_t)MM * HH;      // [B,NH,S,S]

    cudaFuncSetAttribute(proj_mma_kernel,   cudaFuncAttributeMaxDynamicSharedMemorySize, SMEM4);
    cudaFuncSetAttribute(scores_mma_kernel, cudaFuncAttributeMaxDynamicSharedMemorySize, SMEM4);
    cudaFuncSetAttribute(final_mma_kernel,  cudaFuncAttributeMaxDynamicSharedMemorySize, SMEM4);
    cudaFuncSetAttribute(ctx_mma_kernel,    cudaFuncAttributeMaxDynamicSharedMemorySize, CSMEM4);

    convert_kernel<<<dim3(4096, 1, 13), 256>>>(ca);
    proj_mma_kernel<<<dim3(8, 32, 7), 256, SMEM4>>>(ta);
    vt_kernel<<<dim3(16, 2, BH), dim3(32, 8)>>>();
    scores_mma_kernel<<<dim3(4, 4, BH), 256, SMEM4>>>(mask, attnmap);
    softmax_kernel<<<BH * SS, 128>>>();
    ctx_mma_kernel<<<dim3(4, BH), 256, CSMEM4>>>();
    final_mma_kernel<<<dim3(8, 32), 256, SMEM4>>>(bd, hidden);
}

// round 12
// speedup vs baseline: 1.5782x; 1.1430x over previous
#include <cuda_runtime.h>
#include <cuda_bf16.h>
#include <math.h>
#include <cstdint>

#define BB 8
#define SS 512
#define HH 1024
#define NHD 16
#define DD 64
#define MM (BB*SS)      // 4096
#define BH (BB*NHD)     // 128
#define CD 192          // concatenated head dim (q|qp|qf)

// ---- scratch (device globals; no allocations allowed) ----
static __device__ __align__(16) float g_v[(size_t)BH*SS*DD];       // [bh][s][64] fp32
static __device__ __align__(16) float g_scores[(size_t)BH*SS*SS];  // [bh][q][k] fp32

static __device__ __align__(16) __nv_bfloat16 g_qcat_hi[(size_t)BH*SS*CD];
static __device__ __align__(16) __nv_bfloat16 g_qcat_lo[(size_t)BH*SS*CD];
static __device__ __align__(16) __nv_bfloat16 g_kcat_hi[(size_t)BH*SS*CD];
static __device__ __align__(16) __nv_bfloat16 g_kcat_lo[(size_t)BH*SS*CD];
static __device__ __align__(16) __nv_bfloat16 g_act_hi[(size_t)5*MM*HH];
static __device__ __align__(16) __nv_bfloat16 g_act_lo[(size_t)5*MM*HH];
static __device__ __align__(16) __nv_bfloat16 g_w_hi[(size_t)8*HH*HH];
static __device__ __align__(16) __nv_bfloat16 g_w_lo[(size_t)8*HH*HH];
static __device__ __align__(16) __nv_bfloat16 g_ctx_hi[(size_t)MM*HH];
static __device__ __align__(16) __nv_bfloat16 g_ctx_lo[(size_t)MM*HH];
static __device__ __align__(16) __nv_bfloat16 g_p_hi[(size_t)BH*SS*SS];   // probs hi
static __device__ __align__(16) __nv_bfloat16 g_p_lo[(size_t)BH*SS*SS];   // probs lo
static __device__ __align__(16) __nv_bfloat16 g_vT_hi[(size_t)BH*DD*SS];  // [bh][d][s]
static __device__ __align__(16) __nv_bfloat16 g_vT_lo[(size_t)BH*DD*SS];

// ---- gemm geometry: 256 thr, tile 128x128, K-chunk 32, 3 stages ----
// A tiles: 80B row stride (conflict-free, proven). B tiles: 64B row stride
// with unit swizzle ((cu + r/2)&3) -> conflict-free ldmatrix at 3-stage size.
#define A_SZ 10240                    // 128 rows * 80 B
#define B_SZ 8192                     // 128 rows * 64 B (swizzled)
#define CHUNK_B (2*A_SZ + 2*B_SZ)     // 36864
#define SMEM3 (3*CHUNK_B)             // 110592  (x2 CTAs = 221184 <= 227K)

// ---- ctx geometry: tile 128x64, K-chunk 32, 3 stages ----
#define CT_A 10240                    // P: 128 rows * 80 B
#define CT_B 4096                     // vT: 64 rows * 64 B (swizzled)
#define CCHUNK (2*CT_A + 2*CT_B)      // 28672
#define CSMEM3 (3*CCHUNK)             // 86016

__device__ __forceinline__ uint32_t smem_to_u32(const void* p) {
    uint32_t a;
    asm("{ .reg .u64 t; cvta.to.shared.u64 t, %1; cvt.u32.u64 %0, t; }" : "=r"(a) : "l"(p));
    return a;
}
__device__ __forceinline__ void cp16(uint32_t s, const void* g) {
    asm volatile("cp.async.cg.shared.global [%0], [%1], 16;" :: "r"(s), "l"(g));
}
#define CP_COMMIT() asm volatile("cp.async.commit_group;" ::: "memory")
template<int N> __device__ __forceinline__ void cp_wait() {
    asm volatile("cp.async.wait_group %0;" :: "n"(N) : "memory");
}

__device__ __forceinline__ void mma_bf(float* c, const uint32_t* a, const uint32_t* b) {
    asm volatile(
        "mma.sync.aligned.m16n8k16.row.col.f32.bf16.bf16.f32 "
        "{%0,%1,%2,%3}, {%4,%5,%6,%7}, {%8,%9}, {%0,%1,%2,%3};"
        : "+f"(c[0]), "+f"(c[1]), "+f"(c[2]), "+f"(c[3])
        : "r"(a[0]), "r"(a[1]), "r"(a[2]), "r"(a[3]), "r"(b[0]), "r"(b[1]));
}

__device__ __forceinline__ void ldsm_x4(uint32_t* r, uint32_t addr) {
    asm volatile("ldmatrix.sync.aligned.m8n8.x4.shared.b16 {%0,%1,%2,%3}, [%4];"
        : "=r"(r[0]), "=r"(r[1]), "=r"(r[2]), "=r"(r[3]) : "r"(addr));
}

// 64B-stride B swizzle: 16B-unit for (row, cu) -> row*64 + ((cu + row/2)&3)*16
__device__ __forceinline__ uint32_t bsw(uint32_t row, uint32_t cu) {
    return row*64u + (((cu + (row >> 1)) & 3u) << 4);
}

// Load one K32 chunk: A(hi,lo) 128 rows @80B + B(hi,lo) 128 rows @64B swizzled.
// 256 threads, 8 cp16 each.
__device__ __forceinline__ void load_chunk(uint32_t sbuf, int tid,
    const __nv_bfloat16* __restrict__ Ah, const __nv_bfloat16* __restrict__ Al, int lda,
    const __nv_bfloat16* __restrict__ Bh, const __nv_bfloat16* __restrict__ Bl, int ldb,
    int m0, int n0, int k0) {
    #pragma unroll
    for (int j = 0; j < 2; j++) {
        const int u = tid + 256*j;               // 0..511: 128 rows x 4 units
        const int row = u >> 2, cu = u & 3;
        const uint32_t soA = (uint32_t)row*80 + (uint32_t)cu*16;
        const uint32_t soB = bsw(row, cu);
        const size_t ga = (size_t)(m0+row)*lda + k0 + cu*8;
        const size_t gb = (size_t)(n0+row)*ldb + k0 + cu*8;
        cp16(sbuf + soA,                 Ah + ga);
        cp16(sbuf + A_SZ + soA,          Al + ga);
        cp16(sbuf + 2*A_SZ + soB,        Bh + gb);
        cp16(sbuf + 2*A_SZ + B_SZ + soB, Bl + gb);
    }
    CP_COMMIT();
}

// One K32 chunk of bf16x3 mma (warp tile 64x32; wm 0..1, wn 0..3).
__device__ __forceinline__ void mma_chunk(uint32_t buf, int lane, int wm, int wn,
                                          float acc[4][4][4]) {
    const uint32_t l7 = lane & 7, l8 = (lane >> 3) & 1, l16 = (lane >> 4) & 1;
    #pragma unroll
    for (int kk = 0; kk < 2; kk++) {
        const uint32_t colA = kk*32 + l16*16;    // bytes
        const uint32_t cuB  = kk*2 + l8;         // 16B unit index
        uint32_t ah[4][4], al[4][4], bh[4][2], bl[4][2];
        #pragma unroll
        for (int mt = 0; mt < 4; mt++) {
            const uint32_t row = wm*64 + mt*16 + l7 + l8*8;
            ldsm_x4(ah[mt], buf + row*80 + colA);
            ldsm_x4(al[mt], buf + A_SZ + row*80 + colA);
        }
        #pragma unroll
        for (int np = 0; np < 2; np++) {
            const uint32_t row = wn*32 + np*16 + l7 + l16*8;
            const uint32_t so = bsw(row, cuB);
            uint32_t t0[4], t1[4];
            ldsm_x4(t0, buf + 2*A_SZ + so);
            ldsm_x4(t1, buf + 2*A_SZ + B_SZ + so);
            bh[2*np][0] = t0[0]; bh[2*np][1] = t0[1];
            bh[2*np+1][0] = t0[2]; bh[2*np+1][1] = t0[3];
            bl[2*np][0] = t1[0]; bl[2*np][1] = t1[1];
            bl[2*np+1][0] = t1[2]; bl[2*np+1][1] = t1[3];
        }
        #pragma unroll
        for (int mt = 0; mt < 4; mt++)
            #pragma unroll
            for (int nt = 0; nt < 4; nt++)
                mma_bf(acc[mt][nt], ah[mt], bh[nt]);
        #pragma unroll
        for (int mt = 0; mt < 4; mt++)
            #pragma unroll
            for (int nt = 0; nt < 4; nt++)
                mma_bf(acc[mt][nt], ah[mt], bl[nt]);
        #pragma unroll
        for (int mt = 0; mt < 4; mt++)
            #pragma unroll
            for (int nt = 0; nt < 4; nt++)
                mma_bf(acc[mt][nt], al[mt], bh[nt]);
    }
}

// ============================================================
// Kernel 0: convert fp32 -> bf16 hi/lo.
// ============================================================
struct ConvArgs { const float* src[13]; };

__global__ void convert_kernel(ConvArgs ca) {
    const int z = blockIdx.z;
    const size_t nvec = (z < 5) ? (size_t)MM*HH/4 : (size_t)HH*HH/4;
    const size_t i = (size_t)blockIdx.x * 256 + threadIdx.x;
    if (i >= nvec) return;
    const float4 v = ((const float4*)ca.src[z])[i];

    __nv_bfloat16 h0 = __float2bfloat16_rn(v.x);
    __nv_bfloat16 h1 = __float2bfloat16_rn(v.y);
    __nv_bfloat16 h2 = __float2bfloat16_rn(v.z);
    __nv_bfloat16 h3 = __float2bfloat16_rn(v.w);
    __nv_bfloat16 l0 = __float2bfloat16_rn(v.x - __bfloat162float(h0));
    __nv_bfloat16 l1 = __float2bfloat16_rn(v.y - __bfloat162float(h1));
    __nv_bfloat16 l2 = __float2bfloat16_rn(v.z - __bfloat162float(h2));
    __nv_bfloat16 l3 = __float2bfloat16_rn(v.w - __bfloat162float(h3));

    __nv_bfloat16 *dh, *dl;
    if (z < 5) { dh = g_act_hi + (size_t)z*MM*HH + i*4; dl = g_act_lo + (size_t)z*MM*HH + i*4; }
    else       { dh = g_w_hi + (size_t)(z-5)*HH*HH + i*4; dl = g_w_lo + (size_t)(z-5)*HH*HH + i*4; }
    *(ushort4*)dh = make_ushort4(__bfloat16_as_ushort(h0), __bfloat16_as_ushort(h1),
                                 __bfloat16_as_ushort(h2), __bfloat16_as_ushort(h3));
    *(ushort4*)dl = make_ushort4(__bfloat16_as_ushort(l0), __bfloat16_as_ushort(l1),
                                 __bfloat16_as_ushort(l2), __bfloat16_as_ushort(l3));
}

// ============================================================
// Kernel 1: 7 fused projections, 128x128 tiles, 256 threads,
// K32 chunks, 3-stage ring, ONE sync per chunk.
// ============================================================
struct TCArgs { const float* bias[7]; };

__global__ void __launch_bounds__(256) proj_mma_kernel(TCArgs ta) {
    extern __shared__ char smem[];
    const int tid = threadIdx.x, lane = tid & 31, w = tid >> 5;
    const int wm = w & 1, wn = w >> 1;
    const int z = blockIdx.z;
    const int ai = (z <= 2) ? z : (z <= 4 ? 3 : 4);
    const int m0 = blockIdx.y * 128, n0 = blockIdx.x * 128;

    const __nv_bfloat16* Ah = g_act_hi + (size_t)ai*MM*HH;
    const __nv_bfloat16* Al = g_act_lo + (size_t)ai*MM*HH;
    const __nv_bfloat16* Bh = g_w_hi + (size_t)z*HH*HH;
    const __nv_bfloat16* Bl = g_w_lo + (size_t)z*HH*HH;
    const uint32_t sb = smem_to_u32(smem);

    float acc[4][4][4];
    #pragma unroll
    for (int a = 0; a < 4; a++)
        #pragma unroll
        for (int b = 0; b < 4; b++)
            #pragma unroll
            for (int c = 0; c < 4; c++) acc[a][b][c] = 0.f;

    load_chunk(sb,           tid, Ah, Al, HH, Bh, Bl, HH, m0, n0, 0);
    load_chunk(sb + CHUNK_B, tid, Ah, Al, HH, Bh, Bl, HH, m0, n0, 32);
    const int KT = HH / 32;  // 32
    for (int t = 0; t < KT; t++) {
        cp_wait<1>();
        __syncthreads();
        if (t + 2 < KT)
            load_chunk(sb + (uint32_t)((t+2)%3)*CHUNK_B, tid,
                       Ah, Al, HH, Bh, Bl, HH, m0, n0, (t+2)*32);
        else
            CP_COMMIT();
        mma_chunk(sb + (uint32_t)(t%3)*CHUNK_B, lane, wm, wn, acc);
    }

    int od0 = 0;
    __nv_bfloat16 *dh = nullptr, *dl = nullptr;
    switch (z) {
        case 0: dh = g_qcat_hi; dl = g_qcat_lo; od0 = 0;   break;
        case 1: dh = g_kcat_hi; dl = g_kcat_lo; od0 = 0;   break;
        case 2: break;  // v -> fp32
        case 3: dh = g_qcat_hi; dl = g_qcat_lo; od0 = 64;  break;
        case 4: dh = g_kcat_hi; dl = g_kcat_lo; od0 = 64;  break;
        case 5: dh = g_qcat_hi; dl = g_qcat_lo; od0 = 128; break;
        default: dh = g_kcat_hi; dl = g_kcat_lo; od0 = 128; break;
    }
    const float* bias = ta.bias[z];
    const int r0 = lane >> 2, tig = lane & 3;
    #pragma unroll
    for (int mt = 0; mt < 4; mt++)
        #pragma unroll
        for (int nt = 0; nt < 4; nt++) {
            const int n = n0 + wn*32 + nt*8 + tig*2;
            const float bv0 = bias[n], bv1 = bias[n+1];
            const int h = n >> 6, d = n & 63;
            #pragma unroll
            for (int rr = 0; rr < 2; rr++) {
                const int m = m0 + wm*64 + mt*16 + r0 + rr*8;
                const int b_ = m >> 9, s = m & 511;
                const float v0 = acc[mt][nt][rr*2]   + bv0;
                const float v1 = acc[mt][nt][rr*2+1] + bv1;
                if (z == 2) {
                    float2 t2 = make_float2(v0, v1);
                    *(float2*)&g_v[((size_t)((b_*NHD + h)*SS + s))*DD + d] = t2;
                } else {
                    const size_t idx = ((size_t)((b_*NHD + h)*SS + s))*CD + od0 + d;
                    __nv_bfloat16 h0 = __float2bfloat16_rn(v0);
                    __nv_bfloat16 h1 = __float2bfloat16_rn(v1);
                    __nv_bfloat16 q0 = __float2bfloat16_rn(v0 - __bfloat162float(h0));
                    __nv_bfloat16 q1 = __float2bfloat16_rn(v1 - __bfloat162float(h1));
                    *(uint32_t*)&dh[idx] =
                        ((uint32_t)__bfloat16_as_ushort(h1) << 16) | __bfloat16_as_ushort(h0);
                    *(uint32_t*)&dl[idx] =
                        ((uint32_t)__bfloat16_as_ushort(q1) << 16) | __bfloat16_as_ushort(q0);
                }
            }
        }
}

// ============================================================
// Kernel 1b: V transpose + hi/lo convert.
// ============================================================
__global__ void vt_kernel() {
    __shared__ float t[32][33];
    const int bh = blockIdx.z;
    const int s0 = blockIdx.x * 32, d0 = blockIdx.y * 32;
    const int tx = threadIdx.x, ty = threadIdx.y;
    const float* src = g_v + (size_t)bh*SS*DD;
    #pragma unroll
    for (int i = 0; i < 4; i++)
        t[ty + i*8][tx] = src[(size_t)(s0 + ty + i*8)*DD + d0 + tx];
    __syncthreads();
    #pragma unroll
    for (int i = 0; i < 4; i++) {
        const int d = d0 + ty + i*8, s = s0 + tx;
        const float v = t[tx][ty + i*8];
        const __nv_bfloat16 h = __float2bfloat16_rn(v);
        const __nv_bfloat16 l = __float2bfloat16_rn(v - __bfloat162float(h));
        g_vT_hi[(size_t)(bh*DD + d)*SS + s] = h;
        g_vT_lo[(size_t)(bh*DD + d)*SS + s] = l;
    }
}

// ============================================================
// Kernel 2: scores per (b,h), 128x128, K32, 3-stage, 1 sync.
// Snapshot after chunk 1 (content K=0..63) -> attention_map.
// ============================================================
__global__ void __launch_bounds__(256) scores_mma_kernel(
    const float* __restrict__ mask, float* __restrict__ attnmap) {
    extern __shared__ char smem[];
    const int tid = threadIdx.x, lane = tid & 31, w = tid >> 5;
    const int wm = w & 1, wn = w >> 1;
    const int bh = blockIdx.z, b_ = bh >> 4;
    const int m0 = blockIdx.y * 128, n0 = blockIdx.x * 128;

    const __nv_bfloat16* Ah = g_qcat_hi + (size_t)bh*SS*CD;
    const __nv_bfloat16* Al = g_qcat_lo + (size_t)bh*SS*CD;
    const __nv_bfloat16* Bh = g_kcat_hi + (size_t)bh*SS*CD;
    const __nv_bfloat16* Bl = g_kcat_lo + (size_t)bh*SS*CD;
    const uint32_t sb = smem_to_u32(smem);
    const int r0 = lane >> 2, tig = lane & 3;

    float acc[4][4][4];
    #pragma unroll
    for (int a = 0; a < 4; a++)
        #pragma unroll
        for (int b = 0; b < 4; b++)
            #pragma unroll
            for (int c = 0; c < 4; c++) acc[a][b][c] = 0.f;

    load_chunk(sb,           tid, Ah, Al, CD, Bh, Bl, CD, m0, n0, 0);
    load_chunk(sb + CHUNK_B, tid, Ah, Al, CD, Bh, Bl, CD, m0, n0, 32);
    const int KT = CD / 32;  // 6
    for (int t = 0; t < KT; t++) {
        cp_wait<1>();
        __syncthreads();
        if (t + 2 < KT)
            load_chunk(sb + (uint32_t)((t+2)%3)*CHUNK_B, tid,
                       Ah, Al, CD, Bh, Bl, CD, m0, n0, (t+2)*32);
        else
            CP_COMMIT();
        mma_chunk(sb + (uint32_t)(t%3)*CHUNK_B, lane, wm, wn, acc);
        if (t == 1) {  // content part (K=0..63) complete -> attention_map
            float* amb = attnmap + (size_t)bh*SS*SS;
            #pragma unroll
            for (int mt = 0; mt < 4; mt++)
                #pragma unroll
                for (int nt = 0; nt < 4; nt++) {
                    const int n = n0 + wn*32 + nt*8 + tig*2;
                    #pragma unroll
                    for (int rr = 0; rr < 2; rr++) {
                        const int m = m0 + wm*64 + mt*16 + r0 + rr*8;
                        float2 t2 = make_float2(acc[mt][nt][rr*2], acc[mt][nt][rr*2+1]);
                        *(float2*)&amb[(size_t)m*SS + n] = t2;
                    }
                }
        }
    }

    float* scb = g_scores + (size_t)bh*SS*SS;
    #pragma unroll
    for (int mt = 0; mt < 4; mt++)
        #pragma unroll
        for (int nt = 0; nt < 4; nt++) {
            const int n = n0 + wn*32 + nt*8 + tig*2;
            #pragma unroll
            for (int rr = 0; rr < 2; rr++) {
                const int m = m0 + wm*64 + mt*16 + r0 + rr*8;
                const float2 mk = *(const float2*)&mask[((size_t)b_*SS + m)*SS + n];
                float2 t2 = make_float2(acc[mt][nt][rr*2]*0.125f + mk.x,
                                        acc[mt][nt][rr*2+1]*0.125f + mk.y);
                *(float2*)&scb[(size_t)m*SS + n] = t2;
            }
        }
}

// ============================================================
// Kernel 3: row softmax on g_scores -> g_p_{hi,lo} bf16.
// ============================================================
__global__ void softmax_kernel() {
    const size_t r = blockIdx.x;
    const float* row = g_scores + r * SS;
    float4 v = ((const float4*)row)[threadIdx.x];

    float mx = fmaxf(fmaxf(v.x, v.y), fmaxf(v.z, v.w));
    #pragma unroll
    for (int o = 16; o; o >>= 1) mx = fmaxf(mx, __shfl_xor_sync(0xffffffffu, mx, o));
    __shared__ float sm[4];
    const int w = threadIdx.x >> 5;
    if ((threadIdx.x & 31) == 0) sm[w] = mx;
    __syncthreads();
    mx = fmaxf(fmaxf(sm[0], sm[1]), fmaxf(sm[2], sm[3]));

    v.x = expf(v.x - mx); v.y = expf(v.y - mx);
    v.z = expf(v.z - mx); v.w = expf(v.w - mx);
    float s = v.x + v.y + v.z + v.w;
    #pragma unroll
    for (int o = 16; o; o >>= 1) s += __shfl_xor_sync(0xffffffffu, s, o);
    __shared__ float ss[4];
    if ((threadIdx.x & 31) == 0) ss[w] = s;
    __syncthreads();
    s = ss[0] + ss[1] + ss[2] + ss[3];

    const float inv = 1.f / s;
    v.x *= inv; v.y *= inv; v.z *= inv; v.w *= inv;

    const __nv_bfloat16 h0 = __float2bfloat16_rn(v.x);
    const __nv_bfloat16 h1 = __float2bfloat16_rn(v.y);
    const __nv_bfloat16 h2 = __float2bfloat16_rn(v.z);
    const __nv_bfloat16 h3 = __float2bfloat16_rn(v.w);
    const __nv_bfloat16 l0 = __float2bfloat16_rn(v.x - __bfloat162float(h0));
    const __nv_bfloat16 l1 = __float2bfloat16_rn(v.y - __bfloat162float(h1));
    const __nv_bfloat16 l2 = __float2bfloat16_rn(v.z - __bfloat162float(h2));
    const __nv_bfloat16 l3 = __float2bfloat16_rn(v.w - __bfloat162float(h3));
    ((ushort4*)(g_p_hi + r*SS))[threadIdx.x] =
        make_ushort4(__bfloat16_as_ushort(h0), __bfloat16_as_ushort(h1),
                     __bfloat16_as_ushort(h2), __bfloat16_as_ushort(h3));
    ((ushort4*)(g_p_lo + r*SS))[threadIdx.x] =
        make_ushort4(__bfloat16_as_ushort(l0), __bfloat16_as_ushort(l1),
                     __bfloat16_as_ushort(l2), __bfloat16_as_ushort(l3));
}

// ============================================================
// Kernel 4: ctx = P @ V, 128x64 tiles, K32, 3-stage, 1 sync.
// ============================================================
__device__ __forceinline__ void ctx_load_chunk(uint32_t sbuf, int tid,
    const __nv_bfloat16* __restrict__ Ph, const __nv_bfloat16* __restrict__ Pl,
    const __nv_bfloat16* __restrict__ Vh, const __nv_bfloat16* __restrict__ Vl,
    int m0, int k0) {
    #pragma unroll
    for (int j = 0; j < 2; j++) {              // P: 512 slots (128 rows x 4 units)
        const int u = tid + 256*j;
        const int row = u >> 2, cu = u & 3;
        const uint32_t soA = (uint32_t)row*80 + (uint32_t)cu*16;
        const size_t ga = (size_t)(m0+row)*SS + k0 + cu*8;
        cp16(sbuf + soA,        Ph + ga);
        cp16(sbuf + CT_A + soA, Pl + ga);
    }
    {                                          // V: 256 slots (64 rows x 4 units)
        const int u = tid;
        const int row = u >> 2, cu = u & 3;
        const uint32_t soB = bsw((uint32_t)row, (uint32_t)cu);
        const size_t gb = (size_t)row*SS + k0 + cu*8;
        cp16(sbuf + 2*CT_A + soB,        Vh + gb);
        cp16(sbuf + 2*CT_A + CT_B + soB, Vl + gb);
    }
    CP_COMMIT();
}

__device__ __forceinline__ void ctx_mma_chunk(uint32_t buf, int lane, int wm, int wn,
                                              float acc[4][2][4]) {
    const uint32_t l7 = lane & 7, l8 = (lane >> 3) & 1, l16 = (lane >> 4) & 1;
    #pragma unroll
    for (int kk = 0; kk < 2; kk++) {
        const uint32_t colA = kk*32 + l16*16;
        const uint32_t cuB  = kk*2 + l8;
        uint32_t ah[4][4], al[4][4], bh[2][2], bl[2][2];
        #pragma unroll
        for (int mt = 0; mt < 4; mt++) {
            const uint32_t row = wm*64 + mt*16 + l7 + l8*8;
            ldsm_x4(ah[mt], buf + row*80 + colA);
            ldsm_x4(al[mt], buf + CT_A + row*80 + colA);
        }
        {
            const uint32_t row = wn*16 + l7 + l16*8;
            const uint32_t so = bsw(row, cuB);
            uint32_t t0[4], t1[4];
            ldsm_x4(t0, buf + 2*CT_A + so);
            ldsm_x4(t1, buf + 2*CT_A + CT_B + so);
            bh[0][0] = t0[0]; bh[0][1] = t0[1]; bh[1][0] = t0[2]; bh[1][1] = t0[3];
            bl[0][0] = t1[0]; bl[0][1] = t1[1]; bl[1][0] = t1[2]; bl[1][1] = t1[3];
        }
        #pragma unroll
        for (int mt = 0; mt < 4; mt++)
            #pragma unroll
            for (int nt = 0; nt < 2; nt++)
                mma_bf(acc[mt][nt], ah[mt], bh[nt]);
        #pragma unroll
        for (int mt = 0; mt < 4; mt++)
            #pragma unroll
            for (int nt = 0; nt < 2; nt++)
                mma_bf(acc[mt][nt], ah[mt], bl[nt]);
        #pragma unroll
        for (int mt = 0; mt < 4; mt++)
            #pragma unroll
            for (int nt = 0; nt < 2; nt++)
                mma_bf(acc[mt][nt], al[mt], bh[nt]);
    }
}

__global__ void __launch_bounds__(256) ctx_mma_kernel() {
    extern __shared__ char smem[];
    const int tid = threadIdx.x, lane = tid & 31, w = tid >> 5;
    const int wm = w & 1, wn = w >> 1;
    const int bh = blockIdx.y, b_ = bh >> 4, h = bh & 15;
    const int m0 = blockIdx.x * 128;

    const __nv_bfloat16* Ph = g_p_hi + (size_t)bh*SS*SS;
    const __nv_bfloat16* Pl = g_p_lo + (size_t)bh*SS*SS;
    const __nv_bfloat16* Vh = g_vT_hi + (size_t)bh*DD*SS;
    const __nv_bfloat16* Vl = g_vT_lo + (size_t)bh*DD*SS;
    const uint32_t sb = smem_to_u32(smem);

    float acc[4][2][4];
    #pragma unroll
    for (int a = 0; a < 4; a++)
        #pragma unroll
        for (int b = 0; b < 2; b++)
            #pragma unroll
            for (int c = 0; c < 4; c++) acc[a][b][c] = 0.f;

    ctx_load_chunk(sb,          tid, Ph, Pl, Vh, Vl, m0, 0);
    ctx_load_chunk(sb + CCHUNK, tid, Ph, Pl, Vh, Vl, m0, 32);
    const int KT = SS / 32;  // 16
    for (int t = 0; t < KT; t++) {
        cp_wait<1>();
        __syncthreads();
        if (t + 2 < KT)
            ctx_load_chunk(sb + (uint32_t)((t+2)%3)*CCHUNK, tid, Ph, Pl, Vh, Vl, m0, (t+2)*32);
        else
            CP_COMMIT();
        ctx_mma_chunk(sb + (uint32_t)(t%3)*CCHUNK, lane, wm, wn, acc);
    }

    const int r0 = lane >> 2, tig = lane & 3;
    #pragma unroll
    for (int mt = 0; mt < 4; mt++)
        #pragma unroll
        for (int nt = 0; nt < 2; nt++) {
            const int d = wn*16 + nt*8 + tig*2;
            #pragma unroll
            for (int rr = 0; rr < 2; rr++) {
                const int m = m0 + wm*64 + mt*16 + r0 + rr*8;
                const float v0 = acc[mt][nt][rr*2];
                const float v1 = acc[mt][nt][rr*2+1];
                const size_t idx = ((size_t)(b_*SS + m))*HH + h*DD + d;
                const __nv_bfloat16 h0 = __float2bfloat16_rn(v0);
                const __nv_bfloat16 h1 = __float2bfloat16_rn(v1);
                const __nv_bfloat16 q0 = __float2bfloat16_rn(v0 - __bfloat162float(h0));
                const __nv_bfloat16 q1 = __float2bfloat16_rn(v1 - __bfloat162float(h1));
                *(uint32_t*)&g_ctx_hi[idx] =
                    ((uint32_t)__bfloat16_as_ushort(h1) << 16) | __bfloat16_as_ushort(h0);
                *(uint32_t*)&g_ctx_lo[idx] =
                    ((uint32_t)__bfloat16_as_ushort(q1) << 16) | __bfloat16_as_ushort(q0);
            }
        }
}

// ============================================================
// Kernel 5: hidden = ctx @ Wd^T + bd, 128x128, K32, 3-stage.
// ============================================================
__global__ void __launch_bounds__(256) final_mma_kernel(
    const float* __restrict__ bias, float* __restrict__ out) {
    extern __shared__ char smem[];
    const int tid = threadIdx.x, lane = tid & 31, w = tid >> 5;
    const int wm = w & 1, wn = w >> 1;
    const int m0 = blockIdx.y * 128, n0 = blockIdx.x * 128;

    const __nv_bfloat16* Ah = g_ctx_hi;
    const __nv_bfloat16* Al = g_ctx_lo;
    const __nv_bfloat16* Bh = g_w_hi + (size_t)7*HH*HH;
    const __nv_bfloat16* Bl = g_w_lo + (size_t)7*HH*HH;
    const uint32_t sb = smem_to_u32(smem);

    float acc[4][4][4];
    #pragma unroll
    for (int a = 0; a < 4; a++)
        #pragma unroll
        for (int b = 0; b < 4; b++)
            #pragma unroll
            for (int c = 0; c < 4; c++) acc[a][b][c] = 0.f;

    load_chunk(sb,           tid, Ah, Al, HH, Bh, Bl, HH, m0, n0, 0);
    load_chunk(sb + CHUNK_B, tid, Ah, Al, HH, Bh, Bl, HH, m0, n0, 32);
    const int KT = HH / 32;  // 32
    for (int t = 0; t < KT; t++) {
        cp_wait<1>();
        __syncthreads();
        if (t + 2 < KT)
            load_chunk(sb + (uint32_t)((t+2)%3)*CHUNK_B, tid,
                       Ah, Al, HH, Bh, Bl, HH, m0, n0, (t+2)*32);
        else
            CP_COMMIT();
        mma_chunk(sb + (uint32_t)(t%3)*CHUNK_B, lane, wm, wn, acc);
    }

    const int r0 = lane >> 2, tig = lane & 3;
    #pragma unroll
    for (int mt = 0; mt < 4; mt++)
        #pragma unroll
        for (int nt = 0; nt < 4; nt++) {
            const int n = n0 + wn*32 + nt*8 + tig*2;
            const float bv0 = bias[n], bv1 = bias[n+1];
            #pragma unroll
            for (int rr = 0; rr < 2; rr++) {
                const int m = m0 + wm*64 + mt*16 + r0 + rr*8;
                float2 t2 = make_float2(acc[mt][nt][rr*2] + bv0,
                                        acc[mt][nt][rr*2+1] + bv1);
                *(float2*)&out[(size_t)m*HH + n] = t2;
            }
        }
}

// ============================================================
// Launch
// ============================================================
extern "C" void kernel_launch(void* const* d_in, const int* in_sizes, int n_in,
                              void* d_out, int out_size) {
    (void)in_sizes; (void)n_in; (void)out_size;

    const float* query = (const float*)d_in[0];
    const float* key   = (const float*)d_in[1];
    const float* value = (const float*)d_in[2];
    const float* mask  = (const float*)d_in[3];
    const float* pos   = (const float*)d_in[4];
    const float* feat  = (const float*)d_in[5];

    ConvArgs ca;
    ca.src[0] = query; ca.src[1] = key; ca.src[2] = value;
    ca.src[3] = pos;   ca.src[4] = feat;
    for (int i = 0; i < 7; i++) ca.src[5 + i] = (const float*)d_in[6 + 2*i];
    ca.src[12] = (const float*)d_in[20];  // Wd

    TCArgs ta;
    for (int i = 0; i < 7; i++) ta.bias[i] = (const float*)d_in[7 + 2*i];
    const float* bd = (const float*)d_in[21];

    float* out     = (float*)d_out;
    float* hidden  = out;                        // [B,S,H]
    float* attnmap = out + (size_t)MM * HH;      // [B,NH,S,S]

    cudaFuncSetAttribute(proj_mma_kernel,   cudaFuncAttributeMaxDynamicSharedMemorySize, SMEM3);
    cudaFuncSetAttribute(scores_mma_kernel, cudaFuncAttributeMaxDynamicSharedMemorySize, SMEM3);
    cudaFuncSetAttribute(final_mma_kernel,  cudaFuncAttributeMaxDynamicSharedMemorySize, SMEM3);
    cudaFuncSetAttribute(ctx_mma_kernel,    cudaFuncAttributeMaxDynamicSharedMemorySize, CSMEM3);

    convert_kernel<<<dim3(4096, 1, 13), 256>>>(ca);
    proj_mma_kernel<<<dim3(8, 32, 7), 256, SMEM3>>>(ta);
    vt_kernel<<<dim3(16, 2, BH), dim3(32, 8)>>>();
    scores_mma_kernel<<<dim3(4, 4, BH), 256, SMEM3>>>(mask, attnmap);
    softmax_kernel<<<BH * SS, 128>>>();
    ctx_mma_kernel<<<dim3(4, BH), 256, CSMEM3>>>();
    final_mma_kernel<<<dim3(8, 32), 256, SMEM3>>>(bd, hidden);
}

// round 13
// speedup vs baseline: 1.8290x; 1.1589x over previous
#include <cuda_runtime.h>
#include <cuda_bf16.h>
#include <math.h>
#include <cstdint>

#define BB 8
#define SS 512
#define HH 1024
#define NHD 16
#define DD 64
#define MM (BB*SS)      // 4096
#define BH (BB*NHD)     // 128
#define CD 192          // concatenated head dim (q|qp|qf)

// ---- scratch (device globals; no allocations allowed) ----
// All GEMM operands stored as tf32-rounded fp32.
static __device__ __align__(16) float g_act[(size_t)5*MM*HH];
static __device__ __align__(16) float g_w[(size_t)8*HH*HH];
static __device__ __align__(16) float g_qcat[(size_t)BH*SS*CD];
static __device__ __align__(16) float g_kcat[(size_t)BH*SS*CD];
static __device__ __align__(16) float g_v[(size_t)BH*SS*DD];       // fp32 (unrounded)
static __device__ __align__(16) float g_vT[(size_t)BH*DD*SS];      // tf32-rounded
static __device__ __align__(16) float g_scores[(size_t)BH*SS*SS];
static __device__ __align__(16) float g_p[(size_t)BH*SS*SS];       // tf32-rounded probs
static __device__ __align__(16) float g_ctx[(size_t)MM*HH];        // tf32-rounded

// ---- gemm geometry: 256 thr, tile 128x128, K-chunk 32 fp32, 3 stages ----
// Row stride 36 floats (144 B): frag LDS banks = (4r+c) mod 32, conflict-free.
#define SROW 144                      // bytes per row (36 floats)
#define T_SZ (128*SROW)               // 18432 per operand tile
#define CHUNK_B (2*T_SZ)              // 36864
#define SMEM3 (3*CHUNK_B)             // 110592 (x2 CTAs = 221184 <= 227K)

// ---- ctx geometry: tile 128x64, K-chunk 32, 3 stages ----
#define CT_PA (128*SROW)              // 18432
#define CT_VB (64*SROW)               // 9216
#define CCHUNK (CT_PA + CT_VB)        // 27648
#define CSMEM3 (3*CCHUNK)             // 82944

__device__ __forceinline__ uint32_t smem_to_u32(const void* p) {
    uint32_t a;
    asm("{ .reg .u64 t; cvta.to.shared.u64 t, %1; cvt.u32.u64 %0, t; }" : "=r"(a) : "l"(p));
    return a;
}
__device__ __forceinline__ void cp16(uint32_t s, const void* g) {
    asm volatile("cp.async.cg.shared.global [%0], [%1], 16;" :: "r"(s), "l"(g));
}
#define CP_COMMIT() asm volatile("cp.async.commit_group;" ::: "memory")
template<int N> __device__ __forceinline__ void cp_wait() {
    asm volatile("cp.async.wait_group %0;" :: "n"(N) : "memory");
}

__device__ __forceinline__ uint32_t f2tf(float x) {
    uint32_t r;
    asm("cvt.rna.tf32.f32 %0, %1;" : "=r"(r) : "f"(x));
    return r;
}

__device__ __forceinline__ void mma_tf32(float* c, const uint32_t* a, const uint32_t* b) {
    asm volatile(
        "mma.sync.aligned.m16n8k8.row.col.f32.tf32.tf32.f32 "
        "{%0,%1,%2,%3}, {%4,%5,%6,%7}, {%8,%9}, {%0,%1,%2,%3};"
        : "+f"(c[0]), "+f"(c[1]), "+f"(c[2]), "+f"(c[3])
        : "r"(a[0]), "r"(a[1]), "r"(a[2]), "r"(a[3]), "r"(b[0]), "r"(b[1]));
}

// Load one K32 chunk: A 128 rows x 32 floats + B 128 rows x 32 floats.
// 256 threads, 8 cp16 each.
__device__ __forceinline__ void load_chunk(uint32_t sbuf, int tid,
    const float* __restrict__ A, int lda,
    const float* __restrict__ B, int ldb,
    int m0, int n0, int k0) {
    #pragma unroll
    for (int j = 0; j < 4; j++) {              // A: 1024 cp16 slots
        const int u = tid + 256*j;
        const int row = u >> 3, cu = u & 7;
        cp16(sbuf + (uint32_t)(row*SROW + cu*16),
             A + (size_t)(m0+row)*lda + k0 + cu*4);
    }
    #pragma unroll
    for (int j = 0; j < 4; j++) {              // B: 1024 cp16 slots
        const int u = tid + 256*j;
        const int row = u >> 3, cu = u & 7;
        cp16(sbuf + T_SZ + (uint32_t)(row*SROW + cu*16),
             B + (size_t)(n0+row)*ldb + k0 + cu*4);
    }
    CP_COMMIT();
}

// One K32 chunk of tf32 mma (warp tile 64x32; wm 0..1, wn 0..3).
// 4 k8-steps x (4 m-frags x 4 n-frags) = 64 mma, all independent accs.
__device__ __forceinline__ void mma_chunk(const float* As, const float* Bs,
                                          int lane, int wm, int wn,
                                          float acc[4][4][4]) {
    const int r = lane >> 2, c = lane & 3;
    #pragma unroll
    for (int kf = 0; kf < 4; kf++) {
        const int k = kf * 8;
        uint32_t a[4][4], b[4][2];
        #pragma unroll
        for (int mt = 0; mt < 4; mt++) {
            const float* p = As + (size_t)(wm*64 + mt*16 + r)*36 + k + c;
            a[mt][0] = __float_as_uint(p[0]);
            a[mt][1] = __float_as_uint(p[8*36]);
            a[mt][2] = __float_as_uint(p[4]);
            a[mt][3] = __float_as_uint(p[8*36 + 4]);
        }
        #pragma unroll
        for (int nt = 0; nt < 4; nt++) {
            const float* p = Bs + (size_t)(wn*32 + nt*8 + r)*36 + k + c;
            b[nt][0] = __float_as_uint(p[0]);
            b[nt][1] = __float_as_uint(p[4]);
        }
        #pragma unroll
        for (int mt = 0; mt < 4; mt++)
            #pragma unroll
            for (int nt = 0; nt < 4; nt++)
                mma_tf32(acc[mt][nt], a[mt], b[nt]);
    }
}

// ============================================================
// Kernel 0: round fp32 -> tf32 (stored as fp32 width).
// z 0..4: activations (q,k,v,pos,feat); z 5..12: weights (Wq..Wkf,Wd)
// ============================================================
struct ConvArgs { const float* src[13]; };

__global__ void convert_kernel(ConvArgs ca) {
    const int z = blockIdx.z;
    const size_t nvec = (z < 5) ? (size_t)MM*HH/4 : (size_t)HH*HH/4;
    const size_t i = (size_t)blockIdx.x * 256 + threadIdx.x;
    if (i >= nvec) return;
    const float4 v = ((const float4*)ca.src[z])[i];
    float4 o;
    o.x = __uint_as_float(f2tf(v.x));
    o.y = __uint_as_float(f2tf(v.y));
    o.z = __uint_as_float(f2tf(v.z));
    o.w = __uint_as_float(f2tf(v.w));
    float* dst = (z < 5) ? (g_act + (size_t)z*MM*HH) : (g_w + (size_t)(z-5)*HH*HH);
    ((float4*)dst)[i] = o;
}

// ============================================================
// Kernel 1: 7 fused projections, 128x128 tiles, 256 threads,
// K32 chunks, 3-stage ring, ONE sync per chunk. tf32 single-pass.
// ============================================================
struct TCArgs { const float* bias[7]; };

__global__ void __launch_bounds__(256) proj_mma_kernel(TCArgs ta) {
    extern __shared__ char smem[];
    const int tid = threadIdx.x, lane = tid & 31, w = tid >> 5;
    const int wm = w & 1, wn = w >> 1;
    const int z = blockIdx.z;
    const int ai = (z <= 2) ? z : (z <= 4 ? 3 : 4);
    const int m0 = blockIdx.y * 128, n0 = blockIdx.x * 128;

    const float* A = g_act + (size_t)ai*MM*HH;
    const float* B = g_w + (size_t)z*HH*HH;
    const uint32_t sb = smem_to_u32(smem);

    float acc[4][4][4];
    #pragma unroll
    for (int a = 0; a < 4; a++)
        #pragma unroll
        for (int b = 0; b < 4; b++)
            #pragma unroll
            for (int c = 0; c < 4; c++) acc[a][b][c] = 0.f;

    load_chunk(sb,           tid, A, HH, B, HH, m0, n0, 0);
    load_chunk(sb + CHUNK_B, tid, A, HH, B, HH, m0, n0, 32);
    const int KT = HH / 32;  // 32
    for (int t = 0; t < KT; t++) {
        cp_wait<1>();
        __syncthreads();
        if (t + 2 < KT)
            load_chunk(sb + (uint32_t)((t+2)%3)*CHUNK_B, tid,
                       A, HH, B, HH, m0, n0, (t+2)*32);
        else
            CP_COMMIT();
        const char* buf = smem + (size_t)(t%3)*CHUNK_B;
        mma_chunk((const float*)buf, (const float*)(buf + T_SZ), lane, wm, wn, acc);
    }

    int od0 = 0;
    float* dst = nullptr;
    switch (z) {
        case 0: dst = g_qcat; od0 = 0;   break;
        case 1: dst = g_kcat; od0 = 0;   break;
        case 2: break;  // v -> fp32 plain
        case 3: dst = g_qcat; od0 = 64;  break;
        case 4: dst = g_kcat; od0 = 64;  break;
        case 5: dst = g_qcat; od0 = 128; break;
        default: dst = g_kcat; od0 = 128; break;
    }
    const float* bias = ta.bias[z];
    const int r0 = lane >> 2, tig = lane & 3;
    #pragma unroll
    for (int mt = 0; mt < 4; mt++)
        #pragma unroll
        for (int nt = 0; nt < 4; nt++) {
            const int n = n0 + wn*32 + nt*8 + tig*2;
            const float bv0 = bias[n], bv1 = bias[n+1];
            const int h = n >> 6, d = n & 63;
            #pragma unroll
            for (int rr = 0; rr < 2; rr++) {
                const int m = m0 + wm*64 + mt*16 + r0 + rr*8;
                const int b_ = m >> 9, s = m & 511;
                const float v0 = acc[mt][nt][rr*2]   + bv0;
                const float v1 = acc[mt][nt][rr*2+1] + bv1;
                if (z == 2) {
                    float2 t2 = make_float2(v0, v1);
                    *(float2*)&g_v[((size_t)((b_*NHD + h)*SS + s))*DD + d] = t2;
                } else {
                    float2 t2 = make_float2(__uint_as_float(f2tf(v0)),
                                            __uint_as_float(f2tf(v1)));
                    *(float2*)&dst[((size_t)((b_*NHD + h)*SS + s))*CD + od0 + d] = t2;
                }
            }
        }
}

// ============================================================
// Kernel 1b: V transpose + tf32 round: g_v [bh][s][d] -> g_vT [bh][d][s].
// ============================================================
__global__ void vt_kernel() {
    __shared__ float t[32][33];
    const int bh = blockIdx.z;
    const int s0 = blockIdx.x * 32, d0 = blockIdx.y * 32;
    const int tx = threadIdx.x, ty = threadIdx.y;
    const float* src = g_v + (size_t)bh*SS*DD;
    #pragma unroll
    for (int i = 0; i < 4; i++)
        t[ty + i*8][tx] = src[(size_t)(s0 + ty + i*8)*DD + d0 + tx];
    __syncthreads();
    #pragma unroll
    for (int i = 0; i < 4; i++) {
        const int d = d0 + ty + i*8, s = s0 + tx;
        g_vT[(size_t)(bh*DD + d)*SS + s] = __uint_as_float(f2tf(t[tx][ty + i*8]));
    }
}

// ============================================================
// Kernel 2: scores per (b,h), 128x128, K32 tf32, 3-stage, 1 sync.
// Snapshot after chunk 1 (content K=0..63) -> attention_map.
// ============================================================
__global__ void __launch_bounds__(256) scores_mma_kernel(
    const float* __restrict__ mask, float* __restrict__ attnmap) {
    extern __shared__ char smem[];
    const int tid = threadIdx.x, lane = tid & 31, w = tid >> 5;
    const int wm = w & 1, wn = w >> 1;
    const int bh = blockIdx.z, b_ = bh >> 4;
    const int m0 = blockIdx.y * 128, n0 = blockIdx.x * 128;

    const float* A = g_qcat + (size_t)bh*SS*CD;
    const float* B = g_kcat + (size_t)bh*SS*CD;
    const uint32_t sb = smem_to_u32(smem);
    const int r0 = lane >> 2, tig = lane & 3;

    float acc[4][4][4];
    #pragma unroll
    for (int a = 0; a < 4; a++)
        #pragma unroll
        for (int b = 0; b < 4; b++)
            #pragma unroll
            for (int c = 0; c < 4; c++) acc[a][b][c] = 0.f;

    load_chunk(sb,           tid, A, CD, B, CD, m0, n0, 0);
    load_chunk(sb + CHUNK_B, tid, A, CD, B, CD, m0, n0, 32);
    const int KT = CD / 32;  // 6
    for (int t = 0; t < KT; t++) {
        cp_wait<1>();
        __syncthreads();
        if (t + 2 < KT)
            load_chunk(sb + (uint32_t)((t+2)%3)*CHUNK_B, tid,
                       A, CD, B, CD, m0, n0, (t+2)*32);
        else
            CP_COMMIT();
        const char* buf = smem + (size_t)(t%3)*CHUNK_B;
        mma_chunk((const float*)buf, (const float*)(buf + T_SZ), lane, wm, wn, acc);
        if (t == 1) {  // content part (K=0..63) complete -> attention_map
            float* amb = attnmap + (size_t)bh*SS*SS;
            #pragma unroll
            for (int mt = 0; mt < 4; mt++)
                #pragma unroll
                for (int nt = 0; nt < 4; nt++) {
                    const int n = n0 + wn*32 + nt*8 + tig*2;
                    #pragma unroll
                    for (int rr = 0; rr < 2; rr++) {
                        const int m = m0 + wm*64 + mt*16 + r0 + rr*8;
                        float2 t2 = make_float2(acc[mt][nt][rr*2], acc[mt][nt][rr*2+1]);
                        *(float2*)&amb[(size_t)m*SS + n] = t2;
                    }
                }
        }
    }

    float* scb = g_scores + (size_t)bh*SS*SS;
    #pragma unroll
    for (int mt = 0; mt < 4; mt++)
        #pragma unroll
        for (int nt = 0; nt < 4; nt++) {
            const int n = n0 + wn*32 + nt*8 + tig*2;
            #pragma unroll
            for (int rr = 0; rr < 2; rr++) {
                const int m = m0 + wm*64 + mt*16 + r0 + rr*8;
                const float2 mk = *(const float2*)&mask[((size_t)b_*SS + m)*SS + n];
                float2 t2 = make_float2(acc[mt][nt][rr*2]*0.125f + mk.x,
                                        acc[mt][nt][rr*2+1]*0.125f + mk.y);
                *(float2*)&scb[(size_t)m*SS + n] = t2;
            }
        }
}

// ============================================================
// Kernel 3: row softmax on g_scores -> g_p (tf32-rounded fp32).
// ============================================================
__global__ void softmax_kernel() {
    const size_t r = blockIdx.x;
    const float* row = g_scores + r * SS;
    float4 v = ((const float4*)row)[threadIdx.x];

    float mx = fmaxf(fmaxf(v.x, v.y), fmaxf(v.z, v.w));
    #pragma unroll
    for (int o = 16; o; o >>= 1) mx = fmaxf(mx, __shfl_xor_sync(0xffffffffu, mx, o));
    __shared__ float sm[4];
    const int w = threadIdx.x >> 5;
    if ((threadIdx.x & 31) == 0) sm[w] = mx;
    __syncthreads();
    mx = fmaxf(fmaxf(sm[0], sm[1]), fmaxf(sm[2], sm[3]));

    v.x = expf(v.x - mx); v.y = expf(v.y - mx);
    v.z = expf(v.z - mx); v.w = expf(v.w - mx);
    float s = v.x + v.y + v.z + v.w;
    #pragma unroll
    for (int o = 16; o; o >>= 1) s += __shfl_xor_sync(0xffffffffu, s, o);
    __shared__ float ss[4];
    if ((threadIdx.x & 31) == 0) ss[w] = s;
    __syncthreads();
    s = ss[0] + ss[1] + ss[2] + ss[3];

    const float inv = 1.f / s;
    float4 o;
    o.x = __uint_as_float(f2tf(v.x * inv));
    o.y = __uint_as_float(f2tf(v.y * inv));
    o.z = __uint_as_float(f2tf(v.z * inv));
    o.w = __uint_as_float(f2tf(v.w * inv));
    ((float4*)(g_p + r*SS))[threadIdx.x] = o;
}

// ============================================================
// Kernel 4: ctx = P @ V, 128x64 tiles, K32 tf32, 3-stage, 1 sync.
// ============================================================
__device__ __forceinline__ void ctx_load_chunk(uint32_t sbuf, int tid,
    const float* __restrict__ P, const float* __restrict__ V,
    int m0, int k0) {
    #pragma unroll
    for (int j = 0; j < 4; j++) {              // P: 1024 cp16 slots
        const int u = tid + 256*j;
        const int row = u >> 3, cu = u & 7;
        cp16(sbuf + (uint32_t)(row*SROW + cu*16),
             P + (size_t)(m0+row)*SS + k0 + cu*4);
    }
    #pragma unroll
    for (int j = 0; j < 2; j++) {              // V: 512 cp16 slots (64 rows)
        const int u = tid + 256*j;
        const int row = u >> 3, cu = u & 7;
        cp16(sbuf + CT_PA + (uint32_t)(row*SROW + cu*16),
             V + (size_t)row*SS + k0 + cu*4);
    }
    CP_COMMIT();
}

__device__ __forceinline__ void ctx_mma_chunk(const float* As, const float* Bs,
                                              int lane, int wm, int wn,
                                              float acc[4][2][4]) {
    const int r = lane >> 2, c = lane & 3;
    #pragma unroll
    for (int kf = 0; kf < 4; kf++) {
        const int k = kf * 8;
        uint32_t a[4][4], b[2][2];
        #pragma unroll
        for (int mt = 0; mt < 4; mt++) {
            const float* p = As + (size_t)(wm*64 + mt*16 + r)*36 + k + c;
            a[mt][0] = __float_as_uint(p[0]);
            a[mt][1] = __float_as_uint(p[8*36]);
            a[mt][2] = __float_as_uint(p[4]);
            a[mt][3] = __float_as_uint(p[8*36 + 4]);
        }
        #pragma unroll
        for (int nt = 0; nt < 2; nt++) {
            const float* p = Bs + (size_t)(wn*16 + nt*8 + r)*36 + k + c;
            b[nt][0] = __float_as_uint(p[0]);
            b[nt][1] = __float_as_uint(p[4]);
        }
        #pragma unroll
        for (int mt = 0; mt < 4; mt++)
            #pragma unroll
            for (int nt = 0; nt < 2; nt++)
                mma_tf32(acc[mt][nt], a[mt], b[nt]);
    }
}

__global__ void __launch_bounds__(256) ctx_mma_kernel() {
    extern __shared__ char smem[];
    const int tid = threadIdx.x, lane = tid & 31, w = tid >> 5;
    const int wm = w & 1, wn = w >> 1;
    const int bh = blockIdx.y, b_ = bh >> 4, h = bh & 15;
    const int m0 = blockIdx.x * 128;

    const float* P = g_p + (size_t)bh*SS*SS;
    const float* V = g_vT + (size_t)bh*DD*SS;
    const uint32_t sb = smem_to_u32(smem);

    float acc[4][2][4];
    #pragma unroll
    for (int a = 0; a < 4; a++)
        #pragma unroll
        for (int b = 0; b < 2; b++)
            #pragma unroll
            for (int c = 0; c < 4; c++) acc[a][b][c] = 0.f;

    ctx_load_chunk(sb,          tid, P, V, m0, 0);
    ctx_load_chunk(sb + CCHUNK, tid, P, V, m0, 32);
    const int KT = SS / 32;  // 16
    for (int t = 0; t < KT; t++) {
        cp_wait<1>();
        __syncthreads();
        if (t + 2 < KT)
            ctx_load_chunk(sb + (uint32_t)((t+2)%3)*CCHUNK, tid, P, V, m0, (t+2)*32);
        else
            CP_COMMIT();
        const char* buf = smem + (size_t)(t%3)*CCHUNK;
        ctx_mma_chunk((const float*)buf, (const float*)(buf + CT_PA), lane, wm, wn, acc);
    }

    const int r0 = lane >> 2, tig = lane & 3;
    #pragma unroll
    for (int mt = 0; mt < 4; mt++)
        #pragma unroll
        for (int nt = 0; nt < 2; nt++) {
            const int d = wn*16 + nt*8 + tig*2;
            #pragma unroll
            for (int rr = 0; rr < 2; rr++) {
                const int m = m0 + wm*64 + mt*16 + r0 + rr*8;
                float2 t2 = make_float2(
                    __uint_as_float(f2tf(acc[mt][nt][rr*2])),
                    __uint_as_float(f2tf(acc[mt][nt][rr*2+1])));
                *(float2*)&g_ctx[((size_t)(b_*SS + m))*HH + h*DD + d] = t2;
            }
        }
}

// ============================================================
// Kernel 5: hidden = ctx @ Wd^T + bd, 128x128, K32 tf32, 3-stage.
// ============================================================
__global__ void __launch_bounds__(256) final_mma_kernel(
    const float* __restrict__ bias, float* __restrict__ out) {
    extern __shared__ char smem[];
    const int tid = threadIdx.x, lane = tid & 31, w = tid >> 5;
    const int wm = w & 1, wn = w >> 1;
    const int m0 = blockIdx.y * 128, n0 = blockIdx.x * 128;

    const float* A = g_ctx;
    const float* B = g_w + (size_t)7*HH*HH;
    const uint32_t sb = smem_to_u32(smem);

    float acc[4][4][4];
    #pragma unroll
    for (int a = 0; a < 4; a++)
        #pragma unroll
        for (int b = 0; b < 4; b++)
            #pragma unroll
            for (int c = 0; c < 4; c++) acc[a][b][c] = 0.f;

    load_chunk(sb,           tid, A, HH, B, HH, m0, n0, 0);
    load_chunk(sb + CHUNK_B, tid, A, HH, B, HH, m0, n0, 32);
    const int KT = HH / 32;  // 32
    for (int t = 0; t < KT; t++) {
        cp_wait<1>();
        __syncthreads();
        if (t + 2 < KT)
            load_chunk(sb + (uint32_t)((t+2)%3)*CHUNK_B, tid,
                       A, HH, B, HH, m0, n0, (t+2)*32);
        else
            CP_COMMIT();
        const char* buf = smem + (size_t)(t%3)*CHUNK_B;
        mma_chunk((const float*)buf, (const float*)(buf + T_SZ), lane, wm, wn, acc);
    }

    const int r0 = lane >> 2, tig = lane & 3;
    #pragma unroll
    for (int mt = 0; mt < 4; mt++)
        #pragma unroll
        for (int nt = 0; nt < 4; nt++) {
            const int n = n0 + wn*32 + nt*8 + tig*2;
            const float bv0 = bias[n], bv1 = bias[n+1];
            #pragma unroll
            for (int rr = 0; rr < 2; rr++) {
                const int m = m0 + wm*64 + mt*16 + r0 + rr*8;
                float2 t2 = make_float2(acc[mt][nt][rr*2] + bv0,
                                        acc[mt][nt][rr*2+1] + bv1);
                *(float2*)&out[(size_t)m*HH + n] = t2;
            }
        }
}

// ============================================================
// Launch
// ============================================================
extern "C" void kernel_launch(void* const* d_in, const int* in_sizes, int n_in,
                              void* d_out, int out_size) {
    (void)in_sizes; (void)n_in; (void)out_size;

    const float* query = (const float*)d_in[0];
    const float* key   = (const float*)d_in[1];
    const float* value = (const float*)d_in[2];
    const float* mask  = (const float*)d_in[3];
    const float* pos   = (const float*)d_in[4];
    const float* feat  = (const float*)d_in[5];

    ConvArgs ca;
    ca.src[0] = query; ca.src[1] = key; ca.src[2] = value;
    ca.src[3] = pos;   ca.src[4] = feat;
    for (int i = 0; i < 7; i++) ca.src[5 + i] = (const float*)d_in[6 + 2*i];
    ca.src[12] = (const float*)d_in[20];  // Wd

    TCArgs ta;
    for (int i = 0; i < 7; i++) ta.bias[i] = (const float*)d_in[7 + 2*i];
    const float* bd = (const float*)d_in[21];

    float* out     = (float*)d_out;
    float* hidden  = out;                        // [B,S,H]
    float* attnmap = out + (size_t)MM * HH;      // [B,NH,S,S]

    cudaFuncSetAttribute(proj_mma_kernel,   cudaFuncAttributeMaxDynamicSharedMemorySize, SMEM3);
    cudaFuncSetAttribute(scores_mma_kernel, cudaFuncAttributeMaxDynamicSharedMemorySize, SMEM3);
    cudaFuncSetAttribute(final_mma_kernel,  cudaFuncAttributeMaxDynamicSharedMemorySize, SMEM3);
    cudaFuncSetAttribute(ctx_mma_kernel,    cudaFuncAttributeMaxDynamicSharedMemorySize, CSMEM3);

    convert_kernel<<<dim3(4096, 1, 13), 256>>>(ca);
    proj_mma_kernel<<<dim3(8, 32, 7), 256, SMEM3>>>(ta);
    vt_kernel<<<dim3(16, 2, BH), dim3(32, 8)>>>();
    scores_mma_kernel<<<dim3(4, 4, BH), 256, SMEM3>>>(mask, attnmap);
    softmax_kernel<<<BH * SS, 128>>>();
    ctx_mma_kernel<<<dim3(4, BH), 256, CSMEM3>>>();
    final_mma_kernel<<<dim3(8, 32), 256, SMEM3>>>(bd, hidden);
}

// round 15
// speedup vs baseline: 1.9098x; 1.0442x over previous
#include <cuda_runtime.h>
#include <cuda_bf16.h>
#include <math.h>
#include <cstdint>

#define BB 8
#define SS 512
#define HH 1024
#define NHD 16
#define DD 64
#define MM (BB*SS)      // 4096
#define BH (BB*NHD)     // 128
#define CD 192          // concatenated head dim (q|qp|qf)

// ---- scratch (device globals; no allocations allowed) ----
// All GEMM operands stored as tf32-rounded fp32.
static __device__ __align__(16) float g_act[(size_t)5*MM*HH];
static __device__ __align__(16) float g_w[(size_t)8*HH*HH];
static __device__ __align__(16) float g_qcat[(size_t)BH*SS*CD];
static __device__ __align__(16) float g_kcat[(size_t)BH*SS*CD];
static __device__ __align__(16) float g_v[(size_t)BH*SS*DD];       // fp32 (unrounded)
static __device__ __align__(16) float g_vT[(size_t)BH*DD*SS];      // tf32-rounded
static __device__ __align__(16) float g_scores[(size_t)BH*SS*SS];
static __device__ __align__(16) float g_p[(size_t)BH*SS*SS];       // tf32-rounded probs
static __device__ __align__(16) float g_ctx[(size_t)MM*HH];        // tf32-rounded

// ---- gemm geometry: 256 thr, tile 128x128, K-chunk 32 fp32, 3 stages ----
// Row stride 36 floats (144 B): frag LDS banks = (4r+c) mod 32, conflict-free.
#define SROW 144                      // bytes per row (36 floats)
#define T_SZ (128*SROW)               // 18432 per operand tile
#define CHUNK_B (2*T_SZ)              // 36864
#define SMEM3 (3*CHUNK_B)             // 110592 (x2 CTAs = 221184 <= 227K)

// ---- ctx geometry: tile 128x64, K-chunk 32, 3 stages ----
#define CT_PA (128*SROW)              // 18432
#define CT_VB (64*SROW)               // 9216
#define CCHUNK (CT_PA + CT_VB)        // 27648
#define CSMEM3 (3*CCHUNK)             // 82944

__device__ __forceinline__ uint32_t smem_to_u32(const void* p) {
    uint32_t a;
    asm("{ .reg .u64 t; cvta.to.shared.u64 t, %1; cvt.u32.u64 %0, t; }" : "=r"(a) : "l"(p));
    return a;
}
__device__ __forceinline__ void cp16(uint32_t s, const void* g) {
    asm volatile("cp.async.cg.shared.global [%0], [%1], 16;" :: "r"(s), "l"(g));
}
#define CP_COMMIT() asm volatile("cp.async.commit_group;" ::: "memory")
template<int N> __device__ __forceinline__ void cp_wait() {
    asm volatile("cp.async.wait_group %0;" :: "n"(N) : "memory");
}

__device__ __forceinline__ uint32_t f2tf(float x) {
    uint32_t r;
    asm("cvt.rna.tf32.f32 %0, %1;" : "=r"(r) : "f"(x));
    return r;
}

__device__ __forceinline__ void mma_tf32(float* c, const uint32_t* a, const uint32_t* b) {
    asm volatile(
        "mma.sync.aligned.m16n8k8.row.col.f32.tf32.tf32.f32 "
        "{%0,%1,%2,%3}, {%4,%5,%6,%7}, {%8,%9}, {%0,%1,%2,%3};"
        : "+f"(c[0]), "+f"(c[1]), "+f"(c[2]), "+f"(c[3])
        : "r"(a[0]), "r"(a[1]), "r"(a[2]), "r"(a[3]), "r"(b[0]), "r"(b[1]));
}

// Load one K32 chunk: A 128 rows x 32 floats + B 128 rows x 32 floats.
// 256 threads, 8 cp16 each.
__device__ __forceinline__ void load_chunk(uint32_t sbuf, int tid,
    const float* __restrict__ A, int lda,
    const float* __restrict__ B, int ldb,
    int m0, int n0, int k0) {
    #pragma unroll
    for (int j = 0; j < 4; j++) {              // A: 1024 cp16 slots
        const int u = tid + 256*j;
        const int row = u >> 3, cu = u & 7;
        cp16(sbuf + (uint32_t)(row*SROW + cu*16),
             A + (size_t)(m0+row)*lda + k0 + cu*4);
    }
    #pragma unroll
    for (int j = 0; j < 4; j++) {              // B: 1024 cp16 slots
        const int u = tid + 256*j;
        const int row = u >> 3, cu = u & 7;
        cp16(sbuf + T_SZ + (uint32_t)(row*SROW + cu*16),
             B + (size_t)(n0+row)*ldb + k0 + cu*4);
    }
    CP_COMMIT();
}

// One K32 chunk of tf32 mma (warp tile 64x32; wm 0..1, wn 0..3).
// 4 k8-steps x (4 m-frags x 4 n-frags) = 64 mma, all independent accs.
__device__ __forceinline__ void mma_chunk(const float* As, const float* Bs,
                                          int lane, int wm, int wn,
                                          float acc[4][4][4]) {
    const int r = lane >> 2, c = lane & 3;
    #pragma unroll
    for (int kf = 0; kf < 4; kf++) {
        const int k = kf * 8;
        uint32_t a[4][4], b[4][2];
        #pragma unroll
        for (int mt = 0; mt < 4; mt++) {
            const float* p = As + (size_t)(wm*64 + mt*16 + r)*36 + k + c;
            a[mt][0] = __float_as_uint(p[0]);
            a[mt][1] = __float_as_uint(p[8*36]);
            a[mt][2] = __float_as_uint(p[4]);
            a[mt][3] = __float_as_uint(p[8*36 + 4]);
        }
        #pragma unroll
        for (int nt = 0; nt < 4; nt++) {
            const float* p = Bs + (size_t)(wn*32 + nt*8 + r)*36 + k + c;
            b[nt][0] = __float_as_uint(p[0]);
            b[nt][1] = __float_as_uint(p[4]);
        }
        #pragma unroll
        for (int mt = 0; mt < 4; mt++)
            #pragma unroll
            for (int nt = 0; nt < 4; nt++)
                mma_tf32(acc[mt][nt], a[mt], b[nt]);
    }
}

// ============================================================
// Kernel 0: round fp32 -> tf32 (stored as fp32 width).
// z 0..4: activations (q,k,v,pos,feat); z 5..12: weights (Wq..Wkf,Wd)
// ============================================================
struct ConvArgs { const float* src[13]; };

__global__ void convert_kernel(ConvArgs ca) {
    const int z = blockIdx.z;
    const size_t nvec = (z < 5) ? (size_t)MM*HH/4 : (size_t)HH*HH/4;
    const size_t i = (size_t)blockIdx.x * 256 + threadIdx.x;
    if (i >= nvec) return;
    const float4 v = ((const float4*)ca.src[z])[i];
    float4 o;
    o.x = __uint_as_float(f2tf(v.x));
    o.y = __uint_as_float(f2tf(v.y));
    o.z = __uint_as_float(f2tf(v.z));
    o.w = __uint_as_float(f2tf(v.w));
    float* dst = (z < 5) ? (g_act + (size_t)z*MM*HH) : (g_w + (size_t)(z-5)*HH*HH);
    ((float4*)dst)[i] = o;
}

// ============================================================
// Kernel 1: 7 fused projections, 128x128 tiles, 256 threads,
// K32 chunks, 3-stage ring, ONE sync per chunk. tf32 single-pass.
// ============================================================
struct TCArgs { const float* bias[7]; };

__global__ void __launch_bounds__(256, 2) proj_mma_kernel(TCArgs ta) {
    extern __shared__ char smem[];
    const int tid = threadIdx.x, lane = tid & 31, w = tid >> 5;
    const int wm = w & 1, wn = w >> 1;
    const int z = blockIdx.z;
    const int ai = (z <= 2) ? z : (z <= 4 ? 3 : 4);
    const int m0 = blockIdx.y * 128, n0 = blockIdx.x * 128;

    const float* A = g_act + (size_t)ai*MM*HH;
    const float* B = g_w + (size_t)z*HH*HH;
    const uint32_t sb = smem_to_u32(smem);

    float acc[4][4][4];
    #pragma unroll
    for (int a = 0; a < 4; a++)
        #pragma unroll
        for (int b = 0; b < 4; b++)
            #pragma unroll
            for (int c = 0; c < 4; c++) acc[a][b][c] = 0.f;

    load_chunk(sb,           tid, A, HH, B, HH, m0, n0, 0);
    load_chunk(sb + CHUNK_B, tid, A, HH, B, HH, m0, n0, 32);
    const int KT = HH / 32;  // 32
    for (int t = 0; t < KT; t++) {
        cp_wait<1>();
        __syncthreads();
        if (t + 2 < KT)
            load_chunk(sb + (uint32_t)((t+2)%3)*CHUNK_B, tid,
                       A, HH, B, HH, m0, n0, (t+2)*32);
        else
            CP_COMMIT();
        const char* buf = smem + (size_t)(t%3)*CHUNK_B;
        mma_chunk((const float*)buf, (const float*)(buf + T_SZ), lane, wm, wn, acc);
    }

    int od0 = 0;
    float* dst = nullptr;
    switch (z) {
        case 0: dst = g_qcat; od0 = 0;   break;
        case 1: dst = g_kcat; od0 = 0;   break;
        case 2: break;  // v -> fp32 plain
        case 3: dst = g_qcat; od0 = 64;  break;
        case 4: dst = g_kcat; od0 = 64;  break;
        case 5: dst = g_qcat; od0 = 128; break;
        default: dst = g_kcat; od0 = 128; break;
    }
    const float* bias = ta.bias[z];
    const int r0 = lane >> 2, tig = lane & 3;
    #pragma unroll
    for (int mt = 0; mt < 4; mt++)
        #pragma unroll
        for (int nt = 0; nt < 4; nt++) {
            const int n = n0 + wn*32 + nt*8 + tig*2;
            const float bv0 = bias[n], bv1 = bias[n+1];
            const int h = n >> 6, d = n & 63;
            #pragma unroll
            for (int rr = 0; rr < 2; rr++) {
                const int m = m0 + wm*64 + mt*16 + r0 + rr*8;
                const int b_ = m >> 9, s = m & 511;
                const float v0 = acc[mt][nt][rr*2]   + bv0;
                const float v1 = acc[mt][nt][rr*2+1] + bv1;
                if (z == 2) {
                    float2 t2 = make_float2(v0, v1);
                    *(float2*)&g_v[((size_t)((b_*NHD + h)*SS + s))*DD + d] = t2;
                } else {
                    float2 t2 = make_float2(__uint_as_float(f2tf(v0)),
                                            __uint_as_float(f2tf(v1)));
                    *(float2*)&dst[((size_t)((b_*NHD + h)*SS + s))*CD + od0 + d] = t2;
                }
            }
        }
}

// ============================================================
// Kernel 1b: V transpose + tf32 round: g_v [bh][s][d] -> g_vT [bh][d][s].
// ============================================================
__global__ void vt_kernel() {
    __shared__ float t[32][33];
    const int bh = blockIdx.z;
    const int s0 = blockIdx.x * 32, d0 = blockIdx.y * 32;
    const int tx = threadIdx.x, ty = threadIdx.y;
    const float* src = g_v + (size_t)bh*SS*DD;
    #pragma unroll
    for (int i = 0; i < 4; i++)
        t[ty + i*8][tx] = src[(size_t)(s0 + ty + i*8)*DD + d0 + tx];
    __syncthreads();
    #pragma unroll
    for (int i = 0; i < 4; i++) {
        const int d = d0 + ty + i*8, s = s0 + tx;
        g_vT[(size_t)(bh*DD + d)*SS + s] = __uint_as_float(f2tf(t[tx][ty + i*8]));
    }
}

// ============================================================
// Kernel 2: scores per (b,h), 128x128, K32 tf32, 3-stage, 1 sync.
// Snapshot after chunk 1 (content K=0..63) -> attention_map.
// ============================================================
__global__ void __launch_bounds__(256, 2) scores_mma_kernel(
    const float* __restrict__ mask, float* __restrict__ attnmap) {
    extern __shared__ char smem[];
    const int tid = threadIdx.x, lane = tid & 31, w = tid >> 5;
    const int wm = w & 1, wn = w >> 1;
    const int bh = blockIdx.z, b_ = bh >> 4;
    const int m0 = blockIdx.y * 128, n0 = blockIdx.x * 128;

    const float* A = g_qcat + (size_t)bh*SS*CD;
    const float* B = g_kcat + (size_t)bh*SS*CD;
    const uint32_t sb = smem_to_u32(smem);
    const int r0 = lane >> 2, tig = lane & 3;

    float acc[4][4][4];
    #pragma unroll
    for (int a = 0; a < 4; a++)
        #pragma unroll
        for (int b = 0; b < 4; b++)
            #pragma unroll
            for (int c = 0; c < 4; c++) acc[a][b][c] = 0.f;

    load_chunk(sb,           tid, A, CD, B, CD, m0, n0, 0);
    load_chunk(sb + CHUNK_B, tid, A, CD, B, CD, m0, n0, 32);
    const int KT = CD / 32;  // 6
    for (int t = 0; t < KT; t++) {
        cp_wait<1>();
        __syncthreads();
        if (t + 2 < KT)
            load_chunk(sb + (uint32_t)((t+2)%3)*CHUNK_B, tid,
                       A, CD, B, CD, m0, n0, (t+2)*32);
        else
            CP_COMMIT();
        const char* buf = smem + (size_t)(t%3)*CHUNK_B;
        mma_chunk((const float*)buf, (const float*)(buf + T_SZ), lane, wm, wn, acc);
        if (t == 1) {  // content part (K=0..63) complete -> attention_map
            float* amb = attnmap + (size_t)bh*SS*SS;
            #pragma unroll
            for (int mt = 0; mt < 4; mt++)
                #pragma unroll
                for (int nt = 0; nt < 4; nt++) {
                    const int n = n0 + wn*32 + nt*8 + tig*2;
                    #pragma unroll
                    for (int rr = 0; rr < 2; rr++) {
                        const int m = m0 + wm*64 + mt*16 + r0 + rr*8;
                        float2 t2 = make_float2(acc[mt][nt][rr*2], acc[mt][nt][rr*2+1]);
                        *(float2*)&amb[(size_t)m*SS + n] = t2;
                    }
                }
        }
    }

    float* scb = g_scores + (size_t)bh*SS*SS;
    #pragma unroll
    for (int mt = 0; mt < 4; mt++)
        #pragma unroll
        for (int nt = 0; nt < 4; nt++) {
            const int n = n0 + wn*32 + nt*8 + tig*2;
            #pragma unroll
            for (int rr = 0; rr < 2; rr++) {
                const int m = m0 + wm*64 + mt*16 + r0 + rr*8;
                const float2 mk = *(const float2*)&mask[((size_t)b_*SS + m)*SS + n];
                float2 t2 = make_float2(acc[mt][nt][rr*2]*0.125f + mk.x,
                                        acc[mt][nt][rr*2+1]*0.125f + mk.y);
                *(float2*)&scb[(size_t)m*SS + n] = t2;
            }
        }
}

// ============================================================
// Kernel 3: row softmax on g_scores -> g_p (tf32-rounded fp32).
// ============================================================
__global__ void softmax_kernel() {
    const size_t r = blockIdx.x;
    const float* row = g_scores + r * SS;
    float4 v = ((const float4*)row)[threadIdx.x];

    float mx = fmaxf(fmaxf(v.x, v.y), fmaxf(v.z, v.w));
    #pragma unroll
    for (int o = 16; o; o >>= 1) mx = fmaxf(mx, __shfl_xor_sync(0xffffffffu, mx, o));
    __shared__ float sm[4];
    const int w = threadIdx.x >> 5;
    if ((threadIdx.x & 31) == 0) sm[w] = mx;
    __syncthreads();
    mx = fmaxf(fmaxf(sm[0], sm[1]), fmaxf(sm[2], sm[3]));

    v.x = expf(v.x - mx); v.y = expf(v.y - mx);
    v.z = expf(v.z - mx); v.w = expf(v.w - mx);
    float s = v.x + v.y + v.z + v.w;
    #pragma unroll
    for (int o = 16; o; o >>= 1) s += __shfl_xor_sync(0xffffffffu, s, o);
    __shared__ float ss[4];
    if ((threadIdx.x & 31) == 0) ss[w] = s;
    __syncthreads();
    s = ss[0] + ss[1] + ss[2] + ss[3];

    const float inv = 1.f / s;
    float4 o;
    o.x = __uint_as_float(f2tf(v.x * inv));
    o.y = __uint_as_float(f2tf(v.y * inv));
    o.z = __uint_as_float(f2tf(v.z * inv));
    o.w = __uint_as_float(f2tf(v.w * inv));
    ((float4*)(g_p + r*SS))[threadIdx.x] = o;
}

// ============================================================
// Kernel 4: ctx = P @ V, 128x64 tiles, K32 tf32, 3-stage, 1 sync.
// ============================================================
__device__ __forceinline__ void ctx_load_chunk(uint32_t sbuf, int tid,
    const float* __restrict__ P, const float* __restrict__ V,
    int m0, int k0) {
    #pragma unroll
    for (int j = 0; j < 4; j++) {              // P: 1024 cp16 slots
        const int u = tid + 256*j;
        const int row = u >> 3, cu = u & 7;
        cp16(sbuf + (uint32_t)(row*SROW + cu*16),
             P + (size_t)(m0+row)*SS + k0 + cu*4);
    }
    #pragma unroll
    for (int j = 0; j < 2; j++) {              // V: 512 cp16 slots (64 rows)
        const int u = tid + 256*j;
        const int row = u >> 3, cu = u & 7;
        cp16(sbuf + CT_PA + (uint32_t)(row*SROW + cu*16),
             V + (size_t)row*SS + k0 + cu*4);
    }
    CP_COMMIT();
}

__device__ __forceinline__ void ctx_mma_chunk(const float* As, const float* Bs,
                                              int lane, int wm, int wn,
                                              float acc[4][2][4]) {
    const int r = lane >> 2, c = lane & 3;
    #pragma unroll
    for (int kf = 0; kf < 4; kf++) {
        const int k = kf * 8;
        uint32_t a[4][4], b[2][2];
        #pragma unroll
        for (int mt = 0; mt < 4; mt++) {
            const float* p = As + (size_t)(wm*64 + mt*16 + r)*36 + k + c;
            a[mt][0] = __float_as_uint(p[0]);
            a[mt][1] = __float_as_uint(p[8*36]);
            a[mt][2] = __float_as_uint(p[4]);
            a[mt][3] = __float_as_uint(p[8*36 + 4]);
        }
        #pragma unroll
        for (int nt = 0; nt < 2; nt++) {
            const float* p = Bs + (size_t)(wn*16 + nt*8 + r)*36 + k + c;
            b[nt][0] = __float_as_uint(p[0]);
            b[nt][1] = __float_as_uint(p[4]);
        }
        #pragma unroll
        for (int mt = 0; mt < 4; mt++)
            #pragma unroll
            for (int nt = 0; nt < 2; nt++)
                mma_tf32(acc[mt][nt], a[mt], b[nt]);
    }
}

__global__ void __launch_bounds__(256, 2) ctx_mma_kernel() {
    extern __shared__ char smem[];
    const int tid = threadIdx.x, lane = tid & 31, w = tid >> 5;
    const int wm = w & 1, wn = w >> 1;
    const int bh = blockIdx.y, b_ = bh >> 4, h = bh & 15;
    const int m0 = blockIdx.x * 128;

    const float* P = g_p + (size_t)bh*SS*SS;
    const float* V = g_vT + (size_t)bh*DD*SS;
    const uint32_t sb = smem_to_u32(smem);

    float acc[4][2][4];
    #pragma unroll
    for (int a = 0; a < 4; a++)
        #pragma unroll
        for (int b = 0; b < 2; b++)
            #pragma unroll
            for (int c = 0; c < 4; c++) acc[a][b][c] = 0.f;

    ctx_load_chunk(sb,          tid, P, V, m0, 0);
    ctx_load_chunk(sb + CCHUNK, tid, P, V, m0, 32);
    const int KT = SS / 32;  // 16
    for (int t = 0; t < KT; t++) {
        cp_wait<1>();
        __syncthreads();
        if (t + 2 < KT)
            ctx_load_chunk(sb + (uint32_t)((t+2)%3)*CCHUNK, tid, P, V, m0, (t+2)*32);
        else
            CP_COMMIT();
        const char* buf = smem + (size_t)(t%3)*CCHUNK;
        ctx_mma_chunk((const float*)buf, (const float*)(buf + CT_PA), lane, wm, wn, acc);
    }

    const int r0 = lane >> 2, tig = lane & 3;
    #pragma unroll
    for (int mt = 0; mt < 4; mt++)
        #pragma unroll
        for (int nt = 0; nt < 2; nt++) {
            const int d = wn*16 + nt*8 + tig*2;
            #pragma unroll
            for (int rr = 0; rr < 2; rr++) {
                const int m = m0 + wm*64 + mt*16 + r0 + rr*8;
                float2 t2 = make_float2(
                    __uint_as_float(f2tf(acc[mt][nt][rr*2])),
                    __uint_as_float(f2tf(acc[mt][nt][rr*2+1])));
                *(float2*)&g_ctx[((size_t)(b_*SS + m))*HH + h*DD + d] = t2;
            }
        }
}

// ============================================================
// Kernel 5: hidden = ctx @ Wd^T + bd, 128x128, K32 tf32, 3-stage.
// ============================================================
__global__ void __launch_bounds__(256, 2) final_mma_kernel(
    const float* __restrict__ bias, float* __restrict__ out) {
    extern __shared__ char smem[];
    const int tid = threadIdx.x, lane = tid & 31, w = tid >> 5;
    const int wm = w & 1, wn = w >> 1;
    const int m0 = blockIdx.y * 128, n0 = blockIdx.x * 128;

    const float* A = g_ctx;
    const float* B = g_w + (size_t)7*HH*HH;
    const uint32_t sb = smem_to_u32(smem);

    float acc[4][4][4];
    #pragma unroll
    for (int a = 0; a < 4; a++)
        #pragma unroll
        for (int b = 0; b < 4; b++)
            #pragma unroll
            for (int c = 0; c < 4; c++) acc[a][b][c] = 0.f;

    load_chunk(sb,           tid, A, HH, B, HH, m0, n0, 0);
    load_chunk(sb + CHUNK_B, tid, A, HH, B, HH, m0, n0, 32);
    const int KT = HH / 32;  // 32
    for (int t = 0; t < KT; t++) {
        cp_wait<1>();
        __syncthreads();
        if (t + 2 < KT)
            load_chunk(sb + (uint32_t)((t+2)%3)*CHUNK_B, tid,
                       A, HH, B, HH, m0, n0, (t+2)*32);
        else
            CP_COMMIT();
        const char* buf = smem + (size_t)(t%3)*CHUNK_B;
        mma_chunk((const float*)buf, (const float*)(buf + T_SZ), lane, wm, wn, acc);
    }

    const int r0 = lane >> 2, tig = lane & 3;
    #pragma unroll
    for (int mt = 0; mt < 4; mt++)
        #pragma unroll
        for (int nt = 0; nt < 4; nt++) {
            const int n = n0 + wn*32 + nt*8 + tig*2;
            const float bv0 = bias[n], bv1 = bias[n+1];
            #pragma unroll
            for (int rr = 0; rr < 2; rr++) {
                const int m = m0 + wm*64 + mt*16 + r0 + rr*8;
                float2 t2 = make_float2(acc[mt][nt][rr*2] + bv0,
                                        acc[mt][nt][rr*2+1] + bv1);
                *(float2*)&out[(size_t)m*HH + n] = t2;
            }
        }
}

// ============================================================
// Launch
// ============================================================
extern "C" void kernel_launch(void* const* d_in, const int* in_sizes, int n_in,
                              void* d_out, int out_size) {
    (void)in_sizes; (void)n_in; (void)out_size;

    const float* query = (const float*)d_in[0];
    const float* key   = (const float*)d_in[1];
    const float* value = (const float*)d_in[2];
    const float* mask  = (const float*)d_in[3];
    const float* pos   = (const float*)d_in[4];
    const float* feat  = (const float*)d_in[5];

    ConvArgs ca;
    ca.src[0] = query; ca.src[1] = key; ca.src[2] = value;
    ca.src[3] = pos;   ca.src[4] = feat;
    for (int i = 0; i < 7; i++) ca.src[5 + i] = (const float*)d_in[6 + 2*i];
    ca.src[12] = (const float*)d_in[20];  // Wd

    TCArgs ta;
    for (int i = 0; i < 7; i++) ta.bias[i] = (const float*)d_in[7 + 2*i];
    const float* bd = (const float*)d_in[21];

    float* out     = (float*)d_out;
    float* hidden  = out;                        // [B,S,H]
    float* attnmap = out + (size_t)MM * HH;      // [B,NH,S,S]

    cudaFuncSetAttribute(proj_mma_kernel,   cudaFuncAttributeMaxDynamicSharedMemorySize, SMEM3);
    cudaFuncSetAttribute(scores_mma_kernel, cudaFuncAttributeMaxDynamicSharedMemorySize, SMEM3);
    cudaFuncSetAttribute(final_mma_kernel,  cudaFuncAttributeMaxDynamicSharedMemorySize, SMEM3);
    cudaFuncSetAttribute(ctx_mma_kernel,    cudaFuncAttributeMaxDynamicSharedMemorySize, CSMEM3);

    convert_kernel<<<dim3(4096, 1, 13), 256>>>(ca);
    proj_mma_kernel<<<dim3(8, 32, 7), 256, SMEM3>>>(ta);
    vt_kernel<<<dim3(16, 2, BH), dim3(32, 8)>>>();
    scores_mma_kernel<<<dim3(4, 4, BH), 256, SMEM3>>>(mask, attnmap);
    softmax_kernel<<<BH * SS, 128>>>();
    ctx_mma_kernel<<<dim3(4, BH), 256, CSMEM3>>>();
    final_mma_kernel<<<dim3(8, 32), 256, SMEM3>>>(bd, hidden);
}

// round 16
// speedup vs baseline: 1.9805x; 1.0370x over previous
#include <cuda_runtime.h>
#include <cuda_bf16.h>
#include <math.h>
#include <cstdint>

#define BB 8
#define SS 512
#define HH 1024
#define NHD 16
#define DD 64
#define MM (BB*SS)      // 4096
#define BH (BB*NHD)     // 128
#define CD 192          // concatenated head dim (q|qp|qf)

// ---- scratch (device globals; no allocations allowed) ----
// All GEMM operands stored as tf32-rounded fp32.
static __device__ __align__(16) float g_act[(size_t)5*MM*HH];
static __device__ __align__(16) float g_w[(size_t)8*HH*HH];
static __device__ __align__(16) float g_qcat[(size_t)BH*SS*CD];
static __device__ __align__(16) float g_kcat[(size_t)BH*SS*CD];
static __device__ __align__(16) float g_v[(size_t)BH*SS*DD];       // fp32 (unrounded)
static __device__ __align__(16) float g_vT[(size_t)BH*DD*SS];      // tf32-rounded
static __device__ __align__(16) float g_scores[(size_t)BH*SS*SS];
static __device__ __align__(16) float g_p[(size_t)BH*SS*SS];       // tf32-rounded probs
static __device__ __align__(16) float g_ctx[(size_t)MM*HH];        // tf32-rounded

// ---- gemm geometry: 256 thr, tile 128x128, K-chunk 32 fp32, 3 stages ----
// Row stride 36 floats (144 B): ldmatrix phase unit = (9r+c) mod 8, conflict-free.
#define SROW 144                      // bytes per row (36 floats)
#define T_SZ (128*SROW)               // 18432 per operand tile
#define CHUNK_B (2*T_SZ)              // 36864
#define SMEM3 (3*CHUNK_B)             // 110592 (x2 CTAs = 221184 <= 227K)

// ---- ctx geometry: tile 128x64, K-chunk 32, 3 stages ----
#define CT_PA (128*SROW)              // 18432
#define CT_VB (64*SROW)               // 9216
#define CCHUNK (CT_PA + CT_VB)        // 27648
#define CSMEM3 (3*CCHUNK)             // 82944

__device__ __forceinline__ uint32_t smem_to_u32(const void* p) {
    uint32_t a;
    asm("{ .reg .u64 t; cvta.to.shared.u64 t, %1; cvt.u32.u64 %0, t; }" : "=r"(a) : "l"(p));
    return a;
}
__device__ __forceinline__ void cp16(uint32_t s, const void* g) {
    asm volatile("cp.async.cg.shared.global [%0], [%1], 16;" :: "r"(s), "l"(g));
}
#define CP_COMMIT() asm volatile("cp.async.commit_group;" ::: "memory")
template<int N> __device__ __forceinline__ void cp_wait() {
    asm volatile("cp.async.wait_group %0;" :: "n"(N) : "memory");
}

__device__ __forceinline__ uint32_t f2tf(float x) {
    uint32_t r;
    asm("cvt.rna.tf32.f32 %0, %1;" : "=r"(r) : "f"(x));
    return r;
}

__device__ __forceinline__ void mma_tf32(float* c, const uint32_t* a, const uint32_t* b) {
    asm volatile(
        "mma.sync.aligned.m16n8k8.row.col.f32.tf32.tf32.f32 "
        "{%0,%1,%2,%3}, {%4,%5,%6,%7}, {%8,%9}, {%0,%1,%2,%3};"
        : "+f"(c[0]), "+f"(c[1]), "+f"(c[2]), "+f"(c[3])
        : "r"(a[0]), "r"(a[1]), "r"(a[2]), "r"(a[3]), "r"(b[0]), "r"(b[1]));
}

__device__ __forceinline__ void ldsm_x4(uint32_t* r, uint32_t addr) {
    asm volatile("ldmatrix.sync.aligned.m8n8.x4.shared.b16 {%0,%1,%2,%3}, [%4];"
        : "=r"(r[0]), "=r"(r[1]), "=r"(r[2]), "=r"(r[3]) : "r"(addr));
}

// Load one K32 chunk: A 128 rows x 32 floats + B 128 rows x 32 floats.
// 256 threads, 8 cp16 each.
__device__ __forceinline__ void load_chunk(uint32_t sbuf, int tid,
    const float* __restrict__ A, int lda,
    const float* __restrict__ B, int ldb,
    int m0, int n0, int k0) {
    #pragma unroll
    for (int j = 0; j < 4; j++) {              // A: 1024 cp16 slots
        const int u = tid + 256*j;
        const int row = u >> 3, cu = u & 7;
        cp16(sbuf + (uint32_t)(row*SROW + cu*16),
             A + (size_t)(m0+row)*lda + k0 + cu*4);
    }
    #pragma unroll
    for (int j = 0; j < 4; j++) {              // B: 1024 cp16 slots
        const int u = tid + 256*j;
        const int row = u >> 3, cu = u & 7;
        cp16(sbuf + T_SZ + (uint32_t)(row*SROW + cu*16),
             B + (size_t)(n0+row)*ldb + k0 + cu*4);
    }
    CP_COMMIT();
}

// One K32 chunk of tf32 mma (warp tile 64x32; wm 0..1, wn 0..3).
// Fragments via ldmatrix.b16 on fp32 bit patterns:
//  A x4: row = R + (L&7) + l8*8, col(fp32) = k + l16*4  -> {a0,a1,a2,a3}
//  B x4 (nt pair): row = N + (L&7) + l16*8, col = k + l8*4 -> {b0e,b1e,b0o,b1o}
__device__ __forceinline__ void mma_chunk(uint32_t bufA, uint32_t bufB,
                                          int lane, int wm, int wn,
                                          float acc[4][4][4]) {
    const uint32_t l7 = lane & 7, l8 = (lane >> 3) & 1, l16 = (lane >> 4) & 1;
    #pragma unroll
    for (int kf = 0; kf < 4; kf++) {
        const uint32_t k = kf * 8;             // fp32 col base
        uint32_t a[4][4], b[4][2];
        #pragma unroll
        for (int mt = 0; mt < 4; mt++) {
            const uint32_t row = wm*64 + mt*16 + l7 + l8*8;
            ldsm_x4(a[mt], bufA + row*SROW + (k + l16*4)*4);
        }
        #pragma unroll
        for (int np = 0; np < 2; np++) {
            const uint32_t row = wn*32 + np*16 + l7 + l16*8;
            uint32_t t[4];
            ldsm_x4(t, bufB + row*SROW + (k + l8*4)*4);
            b[2*np][0] = t[0]; b[2*np][1] = t[1];
            b[2*np+1][0] = t[2]; b[2*np+1][1] = t[3];
        }
        #pragma unroll
        for (int mt = 0; mt < 4; mt++)
            #pragma unroll
            for (int nt = 0; nt < 4; nt++)
                mma_tf32(acc[mt][nt], a[mt], b[nt]);
    }
}

// ============================================================
// Kernel 0: round fp32 -> tf32 (stored as fp32 width).
// z 0..4: activations (q,k,v,pos,feat); z 5..12: weights (Wq..Wkf,Wd)
// ============================================================
struct ConvArgs { const float* src[13]; };

__global__ void convert_kernel(ConvArgs ca) {
    const int z = blockIdx.z;
    const size_t nvec = (z < 5) ? (size_t)MM*HH/4 : (size_t)HH*HH/4;
    const size_t i = (size_t)blockIdx.x * 256 + threadIdx.x;
    if (i >= nvec) return;
    const float4 v = ((const float4*)ca.src[z])[i];
    float4 o;
    o.x = __uint_as_float(f2tf(v.x));
    o.y = __uint_as_float(f2tf(v.y));
    o.z = __uint_as_float(f2tf(v.z));
    o.w = __uint_as_float(f2tf(v.w));
    float* dst = (z < 5) ? (g_act + (size_t)z*MM*HH) : (g_w + (size_t)(z-5)*HH*HH);
    ((float4*)dst)[i] = o;
}

// ============================================================
// Kernel 1: 7 fused projections, 128x128 tiles, 256 threads,
// K32 chunks, 3-stage ring, ONE sync per chunk. tf32 single-pass.
// ============================================================
struct TCArgs { const float* bias[7]; };

__global__ void __launch_bounds__(256, 2) proj_mma_kernel(TCArgs ta) {
    extern __shared__ char smem[];
    const int tid = threadIdx.x, lane = tid & 31, w = tid >> 5;
    const int wm = w & 1, wn = w >> 1;
    const int z = blockIdx.z;
    const int ai = (z <= 2) ? z : (z <= 4 ? 3 : 4);
    const int m0 = blockIdx.y * 128, n0 = blockIdx.x * 128;

    const float* A = g_act + (size_t)ai*MM*HH;
    const float* B = g_w + (size_t)z*HH*HH;
    const uint32_t sb = smem_to_u32(smem);

    float acc[4][4][4];
    #pragma unroll
    for (int a = 0; a < 4; a++)
        #pragma unroll
        for (int b = 0; b < 4; b++)
            #pragma unroll
            for (int c = 0; c < 4; c++) acc[a][b][c] = 0.f;

    load_chunk(sb,           tid, A, HH, B, HH, m0, n0, 0);
    load_chunk(sb + CHUNK_B, tid, A, HH, B, HH, m0, n0, 32);
    const int KT = HH / 32;  // 32
    for (int t = 0; t < KT; t++) {
        cp_wait<1>();
        __syncthreads();
        if (t + 2 < KT)
            load_chunk(sb + (uint32_t)((t+2)%3)*CHUNK_B, tid,
                       A, HH, B, HH, m0, n0, (t+2)*32);
        else
            CP_COMMIT();
        const uint32_t buf = sb + (uint32_t)(t%3)*CHUNK_B;
        mma_chunk(buf, buf + T_SZ, lane, wm, wn, acc);
    }

    int od0 = 0;
    float* dst = nullptr;
    switch (z) {
        case 0: dst = g_qcat; od0 = 0;   break;
        case 1: dst = g_kcat; od0 = 0;   break;
        case 2: break;  // v -> fp32 plain
        case 3: dst = g_qcat; od0 = 64;  break;
        case 4: dst = g_kcat; od0 = 64;  break;
        case 5: dst = g_qcat; od0 = 128; break;
        default: dst = g_kcat; od0 = 128; break;
    }
    const float* bias = ta.bias[z];
    const int r0 = lane >> 2, tig = lane & 3;
    #pragma unroll
    for (int mt = 0; mt < 4; mt++)
        #pragma unroll
        for (int nt = 0; nt < 4; nt++) {
            const int n = n0 + wn*32 + nt*8 + tig*2;
            const float bv0 = bias[n], bv1 = bias[n+1];
            const int h = n >> 6, d = n & 63;
            #pragma unroll
            for (int rr = 0; rr < 2; rr++) {
                const int m = m0 + wm*64 + mt*16 + r0 + rr*8;
                const int b_ = m >> 9, s = m & 511;
                const float v0 = acc[mt][nt][rr*2]   + bv0;
                const float v1 = acc[mt][nt][rr*2+1] + bv1;
                if (z == 2) {
                    float2 t2 = make_float2(v0, v1);
                    *(float2*)&g_v[((size_t)((b_*NHD + h)*SS + s))*DD + d] = t2;
                } else {
                    float2 t2 = make_float2(__uint_as_float(f2tf(v0)),
                                            __uint_as_float(f2tf(v1)));
                    *(float2*)&dst[((size_t)((b_*NHD + h)*SS + s))*CD + od0 + d] = t2;
                }
            }
        }
}

// ============================================================
// Kernel 1b: V transpose + tf32 round: g_v [bh][s][d] -> g_vT [bh][d][s].
// ============================================================
__global__ void vt_kernel() {
    __shared__ float t[32][33];
    const int bh = blockIdx.z;
    const int s0 = blockIdx.x * 32, d0 = blockIdx.y * 32;
    const int tx = threadIdx.x, ty = threadIdx.y;
    const float* src = g_v + (size_t)bh*SS*DD;
    #pragma unroll
    for (int i = 0; i < 4; i++)
        t[ty + i*8][tx] = src[(size_t)(s0 + ty + i*8)*DD + d0 + tx];
    __syncthreads();
    #pragma unroll
    for (int i = 0; i < 4; i++) {
        const int d = d0 + ty + i*8, s = s0 + tx;
        g_vT[(size_t)(bh*DD + d)*SS + s] = __uint_as_float(f2tf(t[tx][ty + i*8]));
    }
}

// ============================================================
// Kernel 2: scores per (b,h), 128x128, K32 tf32, 3-stage, 1 sync.
// Snapshot after chunk 1 (content K=0..63) -> attention_map.
// ============================================================
__global__ void __launch_bounds__(256, 2) scores_mma_kernel(
    const float* __restrict__ mask, float* __restrict__ attnmap) {
    extern __shared__ char smem[];
    const int tid = threadIdx.x, lane = tid & 31, w = tid >> 5;
    const int wm = w & 1, wn = w >> 1;
    const int bh = blockIdx.z, b_ = bh >> 4;
    const int m0 = blockIdx.y * 128, n0 = blockIdx.x * 128;

    const float* A = g_qcat + (size_t)bh*SS*CD;
    const float* B = g_kcat + (size_t)bh*SS*CD;
    const uint32_t sb = smem_to_u32(smem);
    const int r0 = lane >> 2, tig = lane & 3;

    float acc[4][4][4];
    #pragma unroll
    for (int a = 0; a < 4; a++)
        #pragma unroll
        for (int b = 0; b < 4; b++)
            #pragma unroll
            for (int c = 0; c < 4; c++) acc[a][b][c] = 0.f;

    load_chunk(sb,           tid, A, CD, B, CD, m0, n0, 0);
    load_chunk(sb + CHUNK_B, tid, A, CD, B, CD, m0, n0, 32);
    const int KT = CD / 32;  // 6
    for (int t = 0; t < KT; t++) {
        cp_wait<1>();
        __syncthreads();
        if (t + 2 < KT)
            load_chunk(sb + (uint32_t)((t+2)%3)*CHUNK_B, tid,
                       A, CD, B, CD, m0, n0, (t+2)*32);
        else
            CP_COMMIT();
        const uint32_t buf = sb + (uint32_t)(t%3)*CHUNK_B;
        mma_chunk(buf, buf + T_SZ, lane, wm, wn, acc);
        if (t == 1) {  // content part (K=0..63) complete -> attention_map
            float* amb = attnmap + (size_t)bh*SS*SS;
            #pragma unroll
            for (int mt = 0; mt < 4; mt++)
                #pragma unroll
                for (int nt = 0; nt < 4; nt++) {
                    const int n = n0 + wn*32 + nt*8 + tig*2;
                    #pragma unroll
                    for (int rr = 0; rr < 2; rr++) {
                        const int m = m0 + wm*64 + mt*16 + r0 + rr*8;
                        float2 t2 = make_float2(acc[mt][nt][rr*2], acc[mt][nt][rr*2+1]);
                        *(float2*)&amb[(size_t)m*SS + n] = t2;
                    }
                }
        }
    }

    float* scb = g_scores + (size_t)bh*SS*SS;
    #pragma unroll
    for (int mt = 0; mt < 4; mt++)
        #pragma unroll
        for (int nt = 0; nt < 4; nt++) {
            const int n = n0 + wn*32 + nt*8 + tig*2;
            #pragma unroll
            for (int rr = 0; rr < 2; rr++) {
                const int m = m0 + wm*64 + mt*16 + r0 + rr*8;
                const float2 mk = *(const float2*)&mask[((size_t)b_*SS + m)*SS + n];
                float2 t2 = make_float2(acc[mt][nt][rr*2]*0.125f + mk.x,
                                        acc[mt][nt][rr*2+1]*0.125f + mk.y);
                *(float2*)&scb[(size_t)m*SS + n] = t2;
            }
        }
}

// ============================================================
// Kernel 3: row softmax on g_scores -> g_p (tf32-rounded fp32).
// ============================================================
__global__ void softmax_kernel() {
    const size_t r = blockIdx.x;
    const float* row = g_scores + r * SS;
    float4 v = ((const float4*)row)[threadIdx.x];

    float mx = fmaxf(fmaxf(v.x, v.y), fmaxf(v.z, v.w));
    #pragma unroll
    for (int o = 16; o; o >>= 1) mx = fmaxf(mx, __shfl_xor_sync(0xffffffffu, mx, o));
    __shared__ float sm[4];
    const int w = threadIdx.x >> 5;
    if ((threadIdx.x & 31) == 0) sm[w] = mx;
    __syncthreads();
    mx = fmaxf(fmaxf(sm[0], sm[1]), fmaxf(sm[2], sm[3]));

    v.x = expf(v.x - mx); v.y = expf(v.y - mx);
    v.z = expf(v.z - mx); v.w = expf(v.w - mx);
    float s = v.x + v.y + v.z + v.w;
    #pragma unroll
    for (int o = 16; o; o >>= 1) s += __shfl_xor_sync(0xffffffffu, s, o);
    __shared__ float ss[4];
    if ((threadIdx.x & 31) == 0) ss[w] = s;
    __syncthreads();
    s = ss[0] + ss[1] + ss[2] + ss[3];

    const float inv = 1.f / s;
    float4 o;
    o.x = __uint_as_float(f2tf(v.x * inv));
    o.y = __uint_as_float(f2tf(v.y * inv));
    o.z = __uint_as_float(f2tf(v.z * inv));
    o.w = __uint_as_float(f2tf(v.w * inv));
    ((float4*)(g_p + r*SS))[threadIdx.x] = o;
}

// ============================================================
// Kernel 4: ctx = P @ V, 128x64 tiles, K32 tf32, 3-stage, 1 sync.
// ============================================================
__device__ __forceinline__ void ctx_load_chunk(uint32_t sbuf, int tid,
    const float* __restrict__ P, const float* __restrict__ V,
    int m0, int k0) {
    #pragma unroll
    for (int j = 0; j < 4; j++) {              // P: 1024 cp16 slots
        const int u = tid + 256*j;
        const int row = u >> 3, cu = u & 7;
        cp16(sbuf + (uint32_t)(row*SROW + cu*16),
             P + (size_t)(m0+row)*SS + k0 + cu*4);
    }
    #pragma unroll
    for (int j = 0; j < 2; j++) {              // V: 512 cp16 slots (64 rows)
        const int u = tid + 256*j;
        const int row = u >> 3, cu = u & 7;
        cp16(sbuf + CT_PA + (uint32_t)(row*SROW + cu*16),
             V + (size_t)row*SS + k0 + cu*4);
    }
    CP_COMMIT();
}

__device__ __forceinline__ void ctx_mma_chunk(uint32_t bufA, uint32_t bufB,
                                              int lane, int wm, int wn,
                                              float acc[4][2][4]) {
    const uint32_t l7 = lane & 7, l8 = (lane >> 3) & 1, l16 = (lane >> 4) & 1;
    #pragma unroll
    for (int kf = 0; kf < 4; kf++) {
        const uint32_t k = kf * 8;
        uint32_t a[4][4], b[2][2];
        #pragma unroll
        for (int mt = 0; mt < 4; mt++) {
            const uint32_t row = wm*64 + mt*16 + l7 + l8*8;
            ldsm_x4(a[mt], bufA + row*SROW + (k + l16*4)*4);
        }
        {
            const uint32_t row = wn*16 + l7 + l16*8;
            uint32_t t[4];
            ldsm_x4(t, bufB + row*SROW + (k + l8*4)*4);
            b[0][0] = t[0]; b[0][1] = t[1];
            b[1][0] = t[2]; b[1][1] = t[3];
        }
        #pragma unroll
        for (int mt = 0; mt < 4; mt++)
            #pragma unroll
            for (int nt = 0; nt < 2; nt++)
                mma_tf32(acc[mt][nt], a[mt], b[nt]);
    }
}

__global__ void __launch_bounds__(256, 2) ctx_mma_kernel() {
    extern __shared__ char smem[];
    const int tid = threadIdx.x, lane = tid & 31, w = tid >> 5;
    const int wm = w & 1, wn = w >> 1;
    const int bh = blockIdx.y, b_ = bh >> 4, h = bh & 15;
    const int m0 = blockIdx.x * 128;

    const float* P = g_p + (size_t)bh*SS*SS;
    const float* V = g_vT + (size_t)bh*DD*SS;
    const uint32_t sb = smem_to_u32(smem);

    float acc[4][2][4];
    #pragma unroll
    for (int a = 0; a < 4; a++)
        #pragma unroll
        for (int b = 0; b < 2; b++)
            #pragma unroll
            for (int c = 0; c < 4; c++) acc[a][b][c] = 0.f;

    ctx_load_chunk(sb,          tid, P, V, m0, 0);
    ctx_load_chunk(sb + CCHUNK, tid, P, V, m0, 32);
    const int KT = SS / 32;  // 16
    for (int t = 0; t < KT; t++) {
        cp_wait<1>();
        __syncthreads();
        if (t + 2 < KT)
            ctx_load_chunk(sb + (uint32_t)((t+2)%3)*CCHUNK, tid, P, V, m0, (t+2)*32);
        else
            CP_COMMIT();
        const uint32_t buf = sb + (uint32_t)(t%3)*CCHUNK;
        ctx_mma_chunk(buf, buf + CT_PA, lane, wm, wn, acc);
    }

    const int r0 = lane >> 2, tig = lane & 3;
    #pragma unroll
    for (int mt = 0; mt < 4; mt++)
        #pragma unroll
        for (int nt = 0; nt < 2; nt++) {
            const int d = wn*16 + nt*8 + tig*2;
            #pragma unroll
            for (int rr = 0; rr < 2; rr++) {
                const int m = m0 + wm*64 + mt*16 + r0 + rr*8;
                float2 t2 = make_float2(
                    __uint_as_float(f2tf(acc[mt][nt][rr*2])),
                    __uint_as_float(f2tf(acc[mt][nt][rr*2+1])));
                *(float2*)&g_ctx[((size_t)(b_*SS + m))*HH + h*DD + d] = t2;
            }
        }
}

// ============================================================
// Kernel 5: hidden = ctx @ Wd^T + bd, 128x128, K32 tf32, 3-stage.
// ============================================================
__global__ void __launch_bounds__(256, 2) final_mma_kernel(
    const float* __restrict__ bias, float* __restrict__ out) {
    extern __shared__ char smem[];
    const int tid = threadIdx.x, lane = tid & 31, w = tid >> 5;
    const int wm = w & 1, wn = w >> 1;
    const int m0 = blockIdx.y * 128, n0 = blockIdx.x * 128;

    const float* A = g_ctx;
    const float* B = g_w + (size_t)7*HH*HH;
    const uint32_t sb = smem_to_u32(smem);

    float acc[4][4][4];
    #pragma unroll
    for (int a = 0; a < 4; a++)
        #pragma unroll
        for (int b = 0; b < 4; b++)
            #pragma unroll
            for (int c = 0; c < 4; c++) acc[a][b][c] = 0.f;

    load_chunk(sb,           tid, A, HH, B, HH, m0, n0, 0);
    load_chunk(sb + CHUNK_B, tid, A, HH, B, HH, m0, n0, 32);
    const int KT = HH / 32;  // 32
    for (int t = 0; t < KT; t++) {
        cp_wait<1>();
        __syncthreads();
        if (t + 2 < KT)
            load_chunk(sb + (uint32_t)((t+2)%3)*CHUNK_B, tid,
                       A, HH, B, HH, m0, n0, (t+2)*32);
        else
            CP_COMMIT();
        const uint32_t buf = sb + (uint32_t)(t%3)*CHUNK_B;
        mma_chunk(buf, buf + T_SZ, lane, wm, wn, acc);
    }

    const int r0 = lane >> 2, tig = lane & 3;
    #pragma unroll
    for (int mt = 0; mt < 4; mt++)
        #pragma unroll
        for (int nt = 0; nt < 4; nt++) {
            const int n = n0 + wn*32 + nt*8 + tig*2;
            const float bv0 = bias[n], bv1 = bias[n+1];
            #pragma unroll
            for (int rr = 0; rr < 2; rr++) {
                const int m = m0 + wm*64 + mt*16 + r0 + rr*8;
                float2 t2 = make_float2(acc[mt][nt][rr*2] + bv0,
                                        acc[mt][nt][rr*2+1] + bv1);
                *(float2*)&out[(size_t)m*HH + n] = t2;
            }
        }
}

// ============================================================
// Launch
// ============================================================
extern "C" void kernel_launch(void* const* d_in, const int* in_sizes, int n_in,
                              void* d_out, int out_size) {
    (void)in_sizes; (void)n_in; (void)out_size;

    const float* query = (const float*)d_in[0];
    const float* key   = (const float*)d_in[1];
    const float* value = (const float*)d_in[2];
    const float* mask  = (const float*)d_in[3];
    const float* pos   = (const float*)d_in[4];
    const float* feat  = (const float*)d_in[5];

    ConvArgs ca;
    ca.src[0] = query; ca.src[1] = key; ca.src[2] = value;
    ca.src[3] = pos;   ca.src[4] = feat;
    for (int i = 0; i < 7; i++) ca.src[5 + i] = (const float*)d_in[6 + 2*i];
    ca.src[12] = (const float*)d_in[20];  // Wd

    TCArgs ta;
    for (int i = 0; i < 7; i++) ta.bias[i] = (const float*)d_in[7 + 2*i];
    const float* bd = (const float*)d_in[21];

    float* out     = (float*)d_out;
    float* hidden  = out;                        // [B,S,H]
    float* attnmap = out + (size_t)MM * HH;      // [B,NH,S,S]

    cudaFuncSetAttribute(proj_mma_kernel,   cudaFuncAttributeMaxDynamicSharedMemorySize, SMEM3);
    cudaFuncSetAttribute(scores_mma_kernel, cudaFuncAttributeMaxDynamicSharedMemorySize, SMEM3);
    cudaFuncSetAttribute(final_mma_kernel,  cudaFuncAttributeMaxDynamicSharedMemorySize, SMEM3);
    cudaFuncSetAttribute(ctx_mma_kernel,    cudaFuncAttributeMaxDynamicSharedMemorySize, CSMEM3);

    convert_kernel<<<dim3(4096, 1, 13), 256>>>(ca);
    proj_mma_kernel<<<dim3(8, 32, 7), 256, SMEM3>>>(ta);
    vt_kernel<<<dim3(16, 2, BH), dim3(32, 8)>>>();
    scores_mma_kernel<<<dim3(4, 4, BH), 256, SMEM3>>>(mask, attnmap);
    softmax_kernel<<<BH * SS, 128>>>();
    ctx_mma_kernel<<<dim3(4, BH), 256, CSMEM3>>>();
    final_mma_kernel<<<dim3(8, 32), 256, SMEM3>>>(bd, hidden);
}

// round 17
// speedup vs baseline: 2.0705x; 1.0455x over previous
#include <cuda_runtime.h>
#include <cuda_bf16.h>
#include <math.h>
#include <cstdint>

#define BB 8
#define SS 512
#define HH 1024
#define NHD 16
#define DD 64
#define MM (BB*SS)      // 4096
#define BH (BB*NHD)     // 128
#define CD 192          // concatenated head dim (q|qp|qf)

// ---- scratch (device globals; no allocations allowed) ----
static __device__ __align__(16) float g_act[(size_t)5*MM*HH];
static __device__ __align__(16) float g_w[(size_t)8*HH*HH];
static __device__ __align__(16) float g_qcat[(size_t)BH*SS*CD];
static __device__ __align__(16) float g_kcat[(size_t)BH*SS*CD];
static __device__ __align__(16) float g_v[(size_t)BH*SS*DD];       // fp32 (unrounded)
static __device__ __align__(16) float g_vT[(size_t)BH*DD*SS];      // tf32-rounded
static __device__ __align__(16) float g_scores[(size_t)BH*SS*SS];
static __device__ __align__(16) float g_p[(size_t)BH*SS*SS];       // tf32-rounded probs
static __device__ __align__(16) float g_ctx[(size_t)MM*HH];        // tf32-rounded

// ---- gemm geometry: 256 thr, tile 128x128, K-chunk 32 fp32, 3 stages ----
#define SROW 144                      // bytes per row (36 floats)
#define T_SZ (128*SROW)               // 18432 per operand tile
#define CHUNK_B (2*T_SZ)              // 36864
#define SMEM3 (3*CHUNK_B)             // 110592 (x2 CTAs = 221184 <= 227K)

// ---- ctx geometry: tile 128x64, K-chunk 32, 3 stages ----
#define CT_PA (128*SROW)              // 18432
#define CT_VB (64*SROW)               // 9216
#define CCHUNK (CT_PA + CT_VB)        // 27648
#define CSMEM3 (3*CCHUNK)             // 82944

// epilogue staging strides (floats)
#define EST 132                       // 128-col tiles
#define ESTC 68                       // 64-col tiles

__device__ __forceinline__ uint32_t smem_to_u32(const void* p) {
    uint32_t a;
    asm("{ .reg .u64 t; cvta.to.shared.u64 t, %1; cvt.u32.u64 %0, t; }" : "=r"(a) : "l"(p));
    return a;
}
__device__ __forceinline__ void cp16(uint32_t s, const void* g) {
    asm volatile("cp.async.cg.shared.global [%0], [%1], 16;" :: "r"(s), "l"(g));
}
#define CP_COMMIT() asm volatile("cp.async.commit_group;" ::: "memory")
template<int N> __device__ __forceinline__ void cp_wait() {
    asm volatile("cp.async.wait_group %0;" :: "n"(N) : "memory");
}

__device__ __forceinline__ uint32_t f2tf(float x) {
    uint32_t r;
    asm("cvt.rna.tf32.f32 %0, %1;" : "=r"(r) : "f"(x));
    return r;
}

__device__ __forceinline__ void mma_tf32(float* c, const uint32_t* a, const uint32_t* b) {
    asm volatile(
        "mma.sync.aligned.m16n8k8.row.col.f32.tf32.tf32.f32 "
        "{%0,%1,%2,%3}, {%4,%5,%6,%7}, {%8,%9}, {%0,%1,%2,%3};"
        : "+f"(c[0]), "+f"(c[1]), "+f"(c[2]), "+f"(c[3])
        : "r"(a[0]), "r"(a[1]), "r"(a[2]), "r"(a[3]), "r"(b[0]), "r"(b[1]));
}

__device__ __forceinline__ void ldsm_x4(uint32_t* r, uint32_t addr) {
    asm volatile("ldmatrix.sync.aligned.m8n8.x4.shared.b16 {%0,%1,%2,%3}, [%4];"
        : "=r"(r[0]), "=r"(r[1]), "=r"(r[2]), "=r"(r[3]) : "r"(addr));
}

// Load one K32 chunk: A 128 rows x 32 floats + B 128 rows x 32 floats.
__device__ __forceinline__ void load_chunk(uint32_t sbuf, int tid,
    const float* __restrict__ A, int lda,
    const float* __restrict__ B, int ldb,
    int m0, int n0, int k0) {
    #pragma unroll
    for (int j = 0; j < 4; j++) {
        const int u = tid + 256*j;
        const int row = u >> 3, cu = u & 7;
        cp16(sbuf + (uint32_t)(row*SROW + cu*16),
             A + (size_t)(m0+row)*lda + k0 + cu*4);
    }
    #pragma unroll
    for (int j = 0; j < 4; j++) {
        const int u = tid + 256*j;
        const int row = u >> 3, cu = u & 7;
        cp16(sbuf + T_SZ + (uint32_t)(row*SROW + cu*16),
             B + (size_t)(n0+row)*ldb + k0 + cu*4);
    }
    CP_COMMIT();
}

// One K32 chunk of tf32 mma (warp tile 64x32; wm 0..1, wn 0..3).
__device__ __forceinline__ void mma_chunk(uint32_t bufA, uint32_t bufB,
                                          int lane, int wm, int wn,
                                          float acc[4][4][4]) {
    const uint32_t l7 = lane & 7, l8 = (lane >> 3) & 1, l16 = (lane >> 4) & 1;
    #pragma unroll
    for (int kf = 0; kf < 4; kf++) {
        const uint32_t k = kf * 8;
        uint32_t a[4][4], b[4][2];
        #pragma unroll
        for (int mt = 0; mt < 4; mt++) {
            const uint32_t row = wm*64 + mt*16 + l7 + l8*8;
            ldsm_x4(a[mt], bufA + row*SROW + (k + l16*4)*4);
        }
        #pragma unroll
        for (int np = 0; np < 2; np++) {
            const uint32_t row = wn*32 + np*16 + l7 + l16*8;
            uint32_t t[4];
            ldsm_x4(t, bufB + row*SROW + (k + l8*4)*4);
            b[2*np][0] = t[0]; b[2*np][1] = t[1];
            b[2*np+1][0] = t[2]; b[2*np+1][1] = t[3];
        }
        #pragma unroll
        for (int mt = 0; mt < 4; mt++)
            #pragma unroll
            for (int nt = 0; nt < 4; nt++)
                mma_tf32(acc[mt][nt], a[mt], b[nt]);
    }
}

// Stage a 128-wide acc tile into smem (padded stride EST).
__device__ __forceinline__ void stage_acc128(float* S, int lane, int wm, int wn,
                                             float acc[4][4][4], float scale) {
    const int r0 = lane >> 2, tig = lane & 3;
    #pragma unroll
    for (int mt = 0; mt < 4; mt++)
        #pragma unroll
        for (int nt = 0; nt < 4; nt++) {
            const int col = wn*32 + nt*8 + tig*2;
            #pragma unroll
            for (int rr = 0; rr < 2; rr++) {
                const int row = wm*64 + mt*16 + r0 + rr*8;
                float2 t2 = make_float2(acc[mt][nt][rr*2]*scale,
                                        acc[mt][nt][rr*2+1]*scale);
                *(float2*)&S[(size_t)row*EST + col] = t2;
            }
        }
}

// ============================================================
// Kernel 0: round fp32 -> tf32 (stored as fp32 width).
// ============================================================
struct ConvArgs { const float* src[13]; };

__global__ void convert_kernel(ConvArgs ca) {
    const int z = blockIdx.z;
    const size_t nvec = (z < 5) ? (size_t)MM*HH/4 : (size_t)HH*HH/4;
    const size_t i = (size_t)blockIdx.x * 256 + threadIdx.x;
    if (i >= nvec) return;
    const float4 v = ((const float4*)ca.src[z])[i];
    float4 o;
    o.x = __uint_as_float(f2tf(v.x));
    o.y = __uint_as_float(f2tf(v.y));
    o.z = __uint_as_float(f2tf(v.z));
    o.w = __uint_as_float(f2tf(v.w));
    float* dst = (z < 5) ? (g_act + (size_t)z*MM*HH) : (g_w + (size_t)(z-5)*HH*HH);
    ((float4*)dst)[i] = o;
}

// ============================================================
// Kernel 1: 7 fused projections; staged, coalesced epilogue.
// ============================================================
struct TCArgs { const float* bias[7]; };

__global__ void __launch_bounds__(256, 2) proj_mma_kernel(TCArgs ta) {
    extern __shared__ char smem[];
    const int tid = threadIdx.x, lane = tid & 31, w = tid >> 5;
    const int wm = w & 1, wn = w >> 1;
    const int z = blockIdx.z;
    const int ai = (z <= 2) ? z : (z <= 4 ? 3 : 4);
    const int m0 = blockIdx.y * 128, n0 = blockIdx.x * 128;

    const float* A = g_act + (size_t)ai*MM*HH;
    const float* B = g_w + (size_t)z*HH*HH;
    const uint32_t sb = smem_to_u32(smem);

    float acc[4][4][4];
    #pragma unroll
    for (int a = 0; a < 4; a++)
        #pragma unroll
        for (int b = 0; b < 4; b++)
            #pragma unroll
            for (int c = 0; c < 4; c++) acc[a][b][c] = 0.f;

    load_chunk(sb,           tid, A, HH, B, HH, m0, n0, 0);
    load_chunk(sb + CHUNK_B, tid, A, HH, B, HH, m0, n0, 32);
    const int KT = HH / 32;  // 32
    for (int t = 0; t < KT; t++) {
        cp_wait<1>();
        __syncthreads();
        if (t + 2 < KT)
            load_chunk(sb + (uint32_t)((t+2)%3)*CHUNK_B, tid,
                       A, HH, B, HH, m0, n0, (t+2)*32);
        else
            CP_COMMIT();
        const uint32_t buf = sb + (uint32_t)(t%3)*CHUNK_B;
        mma_chunk(buf, buf + T_SZ, lane, wm, wn, acc);
    }

    // bias in-register
    const float* bias = ta.bias[z];
    {
        const int tig = lane & 3;
        #pragma unroll
        for (int nt = 0; nt < 4; nt++) {
            const int n = n0 + wn*32 + nt*8 + tig*2;
            const float bv0 = bias[n], bv1 = bias[n+1];
            #pragma unroll
            for (int mt = 0; mt < 4; mt++)
                #pragma unroll
                for (int rr = 0; rr < 2; rr++) {
                    acc[mt][nt][rr*2]   += bv0;
                    acc[mt][nt][rr*2+1] += bv1;
                }
        }
    }

    // stage + coalesced store
    float* S = (float*)smem;
    __syncthreads();
    stage_acc128(S, lane, wm, wn, acc, 1.0f);
    __syncthreads();

    int od0 = 0, ldo = CD;
    float* dst;
    switch (z) {
        case 0: dst = g_qcat; od0 = 0;   break;
        case 1: dst = g_kcat; od0 = 0;   break;
        case 2: dst = g_v; ldo = DD;     break;
        case 3: dst = g_qcat; od0 = 64;  break;
        case 4: dst = g_kcat; od0 = 64;  break;
        case 5: dst = g_qcat; od0 = 128; break;
        default: dst = g_kcat; od0 = 128; break;
    }
    const int h0 = (n0 >> 6);
    #pragma unroll
    for (int j = 0; j < 16; j++) {
        const int i = tid + 256*j;              // 4096 float4 slots
        const int m = i >> 5, u = i & 31;
        const int half = u >> 4, q = u & 15;    // 16 float4 per (m, half)
        float4 v = *(float4*)&S[(size_t)m*EST + half*64 + q*4];
        const int gm = m0 + m;
        const int b_ = gm >> 9, s = gm & 511;
        float* p = dst + ((size_t)((b_*NHD + h0 + half)*SS + s))*ldo + od0 + q*4;
        if (z != 2) {
            v.x = __uint_as_float(f2tf(v.x));
            v.y = __uint_as_float(f2tf(v.y));
            v.z = __uint_as_float(f2tf(v.z));
            v.w = __uint_as_float(f2tf(v.w));
        }
        *(float4*)p = v;
    }
}

// ============================================================
// Kernel 1b: V transpose + tf32 round.
// ============================================================
__global__ void vt_kernel() {
    __shared__ float t[32][33];
    const int bh = blockIdx.z;
    const int s0 = blockIdx.x * 32, d0 = blockIdx.y * 32;
    const int tx = threadIdx.x, ty = threadIdx.y;
    const float* src = g_v + (size_t)bh*SS*DD;
    #pragma unroll
    for (int i = 0; i < 4; i++)
        t[ty + i*8][tx] = src[(size_t)(s0 + ty + i*8)*DD + d0 + tx];
    __syncthreads();
    #pragma unroll
    for (int i = 0; i < 4; i++) {
        const int d = d0 + ty + i*8, s = s0 + tx;
        g_vT[(size_t)(bh*DD + d)*SS + s] = __uint_as_float(f2tf(t[tx][ty + i*8]));
    }
}

// ============================================================
// Kernel 2: scores; staged final epilogue (mask added at store).
// attention_map snapshot mid-loop (stages busy) stays unstaged.
// ============================================================
__global__ void __launch_bounds__(256, 2) scores_mma_kernel(
    const float* __restrict__ mask, float* __restrict__ attnmap) {
    extern __shared__ char smem[];
    const int tid = threadIdx.x, lane = tid & 31, w = tid >> 5;
    const int wm = w & 1, wn = w >> 1;
    const int bh = blockIdx.z, b_ = bh >> 4;
    const int m0 = blockIdx.y * 128, n0 = blockIdx.x * 128;

    const float* A = g_qcat + (size_t)bh*SS*CD;
    const float* B = g_kcat + (size_t)bh*SS*CD;
    const uint32_t sb = smem_to_u32(smem);
    const int r0 = lane >> 2, tig = lane & 3;

    float acc[4][4][4];
    #pragma unroll
    for (int a = 0; a < 4; a++)
        #pragma unroll
        for (int b = 0; b < 4; b++)
            #pragma unroll
            for (int c = 0; c < 4; c++) acc[a][b][c] = 0.f;

    load_chunk(sb,           tid, A, CD, B, CD, m0, n0, 0);
    load_chunk(sb + CHUNK_B, tid, A, CD, B, CD, m0, n0, 32);
    const int KT = CD / 32;  // 6
    for (int t = 0; t < KT; t++) {
        cp_wait<1>();
        __syncthreads();
        if (t + 2 < KT)
            load_chunk(sb + (uint32_t)((t+2)%3)*CHUNK_B, tid,
                       A, CD, B, CD, m0, n0, (t+2)*32);
        else
            CP_COMMIT();
        const uint32_t buf = sb + (uint32_t)(t%3)*CHUNK_B;
        mma_chunk(buf, buf + T_SZ, lane, wm, wn, acc);
        if (t == 1) {  // content part (K=0..63) -> attention_map
            float* amb = attnmap + (size_t)bh*SS*SS;
            #pragma unroll
            for (int mt = 0; mt < 4; mt++)
                #pragma unroll
                for (int nt = 0; nt < 4; nt++) {
                    const int n = n0 + wn*32 + nt*8 + tig*2;
                    #pragma unroll
                    for (int rr = 0; rr < 2; rr++) {
                        const int m = m0 + wm*64 + mt*16 + r0 + rr*8;
                        float2 t2 = make_float2(acc[mt][nt][rr*2], acc[mt][nt][rr*2+1]);
                        *(float2*)&amb[(size_t)m*SS + n] = t2;
                    }
                }
        }
    }

    // stage scaled acc; add mask with coalesced reads at store time
    float* S = (float*)smem;
    __syncthreads();
    stage_acc128(S, lane, wm, wn, acc, 0.125f);
    __syncthreads();

    float* scb = g_scores + (size_t)bh*SS*SS;
    #pragma unroll
    for (int j = 0; j < 16; j++) {
        const int i = tid + 256*j;              // 4096 float4
        const int m = i >> 5, q = i & 31;       // 32 float4 per row
        float4 v = *(float4*)&S[(size_t)m*EST + q*4];
        const int gm = m0 + m;
        const float4 mk = *(const float4*)&mask[((size_t)b_*SS + gm)*SS + n0 + q*4];
        v.x += mk.x; v.y += mk.y; v.z += mk.z; v.w += mk.w;
        *(float4*)&scb[(size_t)gm*SS + n0 + q*4] = v;
    }
}

// ============================================================
// Kernel 3: row softmax on g_scores -> g_p (tf32-rounded fp32).
// ============================================================
__global__ void softmax_kernel() {
    const size_t r = blockIdx.x;
    const float* row = g_scores + r * SS;
    float4 v = ((const float4*)row)[threadIdx.x];

    float mx = fmaxf(fmaxf(v.x, v.y), fmaxf(v.z, v.w));
    #pragma unroll
    for (int o = 16; o; o >>= 1) mx = fmaxf(mx, __shfl_xor_sync(0xffffffffu, mx, o));
    __shared__ float sm[4];
    const int w = threadIdx.x >> 5;
    if ((threadIdx.x & 31) == 0) sm[w] = mx;
    __syncthreads();
    mx = fmaxf(fmaxf(sm[0], sm[1]), fmaxf(sm[2], sm[3]));

    v.x = expf(v.x - mx); v.y = expf(v.y - mx);
    v.z = expf(v.z - mx); v.w = expf(v.w - mx);
    float s = v.x + v.y + v.z + v.w;
    #pragma unroll
    for (int o = 16; o; o >>= 1) s += __shfl_xor_sync(0xffffffffu, s, o);
    __shared__ float ss[4];
    if ((threadIdx.x & 31) == 0) ss[w] = s;
    __syncthreads();
    s = ss[0] + ss[1] + ss[2] + ss[3];

    const float inv = 1.f / s;
    float4 o;
    o.x = __uint_as_float(f2tf(v.x * inv));
    o.y = __uint_as_float(f2tf(v.y * inv));
    o.z = __uint_as_float(f2tf(v.z * inv));
    o.w = __uint_as_float(f2tf(v.w * inv));
    ((float4*)(g_p + r*SS))[threadIdx.x] = o;
}

// ============================================================
// Kernel 4: ctx = P @ V; staged, coalesced epilogue.
// ============================================================
__device__ __forceinline__ void ctx_load_chunk(uint32_t sbuf, int tid,
    const float* __restrict__ P, const float* __restrict__ V,
    int m0, int k0) {
    #pragma unroll
    for (int j = 0; j < 4; j++) {
        const int u = tid + 256*j;
        const int row = u >> 3, cu = u & 7;
        cp16(sbuf + (uint32_t)(row*SROW + cu*16),
             P + (size_t)(m0+row)*SS + k0 + cu*4);
    }
    #pragma unroll
    for (int j = 0; j < 2; j++) {
        const int u = tid + 256*j;
        const int row = u >> 3, cu = u & 7;
        cp16(sbuf + CT_PA + (uint32_t)(row*SROW + cu*16),
             V + (size_t)row*SS + k0 + cu*4);
    }
    CP_COMMIT();
}

__device__ __forceinline__ void ctx_mma_chunk(uint32_t bufA, uint32_t bufB,
                                              int lane, int wm, int wn,
                                              float acc[4][2][4]) {
    const uint32_t l7 = lane & 7, l8 = (lane >> 3) & 1, l16 = (lane >> 4) & 1;
    #pragma unroll
    for (int kf = 0; kf < 4; kf++) {
        const uint32_t k = kf * 8;
        uint32_t a[4][4], b[2][2];
        #pragma unroll
        for (int mt = 0; mt < 4; mt++) {
            const uint32_t row = wm*64 + mt*16 + l7 + l8*8;
            ldsm_x4(a[mt], bufA + row*SROW + (k + l16*4)*4);
        }
        {
            const uint32_t row = wn*16 + l7 + l16*8;
            uint32_t t[4];
            ldsm_x4(t, bufB + row*SROW + (k + l8*4)*4);
            b[0][0] = t[0]; b[0][1] = t[1];
            b[1][0] = t[2]; b[1][1] = t[3];
        }
        #pragma unroll
        for (int mt = 0; mt < 4; mt++)
            #pragma unroll
            for (int nt = 0; nt < 2; nt++)
                mma_tf32(acc[mt][nt], a[mt], b[nt]);
    }
}

__global__ void __launch_bounds__(256, 2) ctx_mma_kernel() {
    extern __shared__ char smem[];
    const int tid = threadIdx.x, lane = tid & 31, w = tid >> 5;
    const int wm = w & 1, wn = w >> 1;
    const int bh = blockIdx.y, b_ = bh >> 4, h = bh & 15;
    const int m0 = blockIdx.x * 128;

    const float* P = g_p + (size_t)bh*SS*SS;
    const float* V = g_vT + (size_t)bh*DD*SS;
    const uint32_t sb = smem_to_u32(smem);

    float acc[4][2][4];
    #pragma unroll
    for (int a = 0; a < 4; a++)
        #pragma unroll
        for (int b = 0; b < 2; b++)
            #pragma unroll
            for (int c = 0; c < 4; c++) acc[a][b][c] = 0.f;

    ctx_load_chunk(sb,          tid, P, V, m0, 0);
    ctx_load_chunk(sb + CCHUNK, tid, P, V, m0, 32);
    const int KT = SS / 32;  // 16
    for (int t = 0; t < KT; t++) {
        cp_wait<1>();
        __syncthreads();
        if (t + 2 < KT)
            ctx_load_chunk(sb + (uint32_t)((t+2)%3)*CCHUNK, tid, P, V, m0, (t+2)*32);
        else
            CP_COMMIT();
        const uint32_t buf = sb + (uint32_t)(t%3)*CCHUNK;
        ctx_mma_chunk(buf, buf + CT_PA, lane, wm, wn, acc);
    }

    // stage 128x64 tile
    float* S = (float*)smem;
    __syncthreads();
    {
        const int r0 = lane >> 2, tig = lane & 3;
        #pragma unroll
        for (int mt = 0; mt < 4; mt++)
            #pragma unroll
            for (int nt = 0; nt < 2; nt++) {
                const int col = wn*16 + nt*8 + tig*2;
                #pragma unroll
                for (int rr = 0; rr < 2; rr++) {
                    const int row = wm*64 + mt*16 + r0 + rr*8;
                    float2 t2 = make_float2(acc[mt][nt][rr*2], acc[mt][nt][rr*2+1]);
                    *(float2*)&S[(size_t)row*ESTC + col] = t2;
                }
            }
    }
    __syncthreads();

    #pragma unroll
    for (int j = 0; j < 8; j++) {
        const int i = tid + 256*j;              // 2048 float4
        const int m = i >> 4, q = i & 15;       // 16 float4 per row
        float4 v = *(float4*)&S[(size_t)m*ESTC + q*4];
        v.x = __uint_as_float(f2tf(v.x));
        v.y = __uint_as_float(f2tf(v.y));
        v.z = __uint_as_float(f2tf(v.z));
        v.w = __uint_as_float(f2tf(v.w));
        *(float4*)&g_ctx[((size_t)(b_*SS + m0 + m))*HH + h*DD + q*4] = v;
    }
}

// ============================================================
// Kernel 5: hidden = ctx @ Wd^T + bd; staged epilogue.
// ============================================================
__global__ void __launch_bounds__(256, 2) final_mma_kernel(
    const float* __restrict__ bias, float* __restrict__ out) {
    extern __shared__ char smem[];
    const int tid = threadIdx.x, lane = tid & 31, w = tid >> 5;
    const int wm = w & 1, wn = w >> 1;
    const int m0 = blockIdx.y * 128, n0 = blockIdx.x * 128;

    const float* A = g_ctx;
    const float* B = g_w + (size_t)7*HH*HH;
    const uint32_t sb = smem_to_u32(smem);

    float acc[4][4][4];
    #pragma unroll
    for (int a = 0; a < 4; a++)
        #pragma unroll
        for (int b = 0; b < 4; b++)
            #pragma unroll
            for (int c = 0; c < 4; c++) acc[a][b][c] = 0.f;

    load_chunk(sb,           tid, A, HH, B, HH, m0, n0, 0);
    load_chunk(sb + CHUNK_B, tid, A, HH, B, HH, m0, n0, 32);
    const int KT = HH / 32;  // 32
    for (int t = 0; t < KT; t++) {
        cp_wait<1>();
        __syncthreads();
        if (t + 2 < KT)
            load_chunk(sb + (uint32_t)((t+2)%3)*CHUNK_B, tid,
                       A, HH, B, HH, m0, n0, (t+2)*32);
        else
            CP_COMMIT();
        const uint32_t buf = sb + (uint32_t)(t%3)*CHUNK_B;
        mma_chunk(buf, buf + T_SZ, lane, wm, wn, acc);
    }

    float* S = (float*)smem;
    __syncthreads();
    stage_acc128(S, lane, wm, wn, acc, 1.0f);
    __syncthreads();

    #pragma unroll
    for (int j = 0; j < 16; j++) {
        const int i = tid + 256*j;
        const int m = i >> 5, q = i & 31;
        float4 v = *(float4*)&S[(size_t)m*EST + q*4];
        const float4 bv = *(const float4*)&bias[n0 + q*4];
        v.x += bv.x; v.y += bv.y; v.z += bv.z; v.w += bv.w;
        *(float4*)&out[(size_t)(m0 + m)*HH + n0 + q*4] = v;
    }
}

// ============================================================
// Launch
// ============================================================
extern "C" void kernel_launch(void* const* d_in, const int* in_sizes, int n_in,
                              void* d_out, int out_size) {
    (void)in_sizes; (void)n_in; (void)out_size;

    const float* query = (const float*)d_in[0];
    const float* key   = (const float*)d_in[1];
    const float* value = (const float*)d_in[2];
    const float* mask  = (const float*)d_in[3];
    const float* pos   = (const float*)d_in[4];
    const float* feat  = (const float*)d_in[5];

    ConvArgs ca;
    ca.src[0] = query; ca.src[1] = key; ca.src[2] = value;
    ca.src[3] = pos;   ca.src[4] = feat;
    for (int i = 0; i < 7; i++) ca.src[5 + i] = (const float*)d_in[6 + 2*i];
    ca.src[12] = (const float*)d_in[20];  // Wd

    TCArgs ta;
    for (int i = 0; i < 7; i++) ta.bias[i] = (const float*)d_in[7 + 2*i];
    const float* bd = (const float*)d_in[21];

    float* out     = (float*)d_out;
    float* hidden  = out;                        // [B,S,H]
    float* attnmap = out + (size_t)MM * HH;      // [B,NH,S,S]

    cudaFuncSetAttribute(proj_mma_kernel,   cudaFuncAttributeMaxDynamicSharedMemorySize, SMEM3);
    cudaFuncSetAttribute(scores_mma_kernel, cudaFuncAttributeMaxDynamicSharedMemorySize, SMEM3);
    cudaFuncSetAttribute(final_mma_kernel,  cudaFuncAttributeMaxDynamicSharedMemorySize, SMEM3);
    cudaFuncSetAttribute(ctx_mma_kernel,    cudaFuncAttributeMaxDynamicSharedMemorySize, CSMEM3);

    convert_kernel<<<dim3(4096, 1, 13), 256>>>(ca);
    proj_mma_kernel<<<dim3(8, 32, 7), 256, SMEM3>>>(ta);
    vt_kernel<<<dim3(16, 2, BH), dim3(32, 8)>>>();
    scores_mma_kernel<<<dim3(4, 4, BH), 256, SMEM3>>>(mask, attnmap);
    softmax_kernel<<<BH * SS, 128>>>();
    ctx_mma_kernel<<<dim3(4, BH), 256, CSMEM3>>>();
    final_mma_kernel<<<dim3(8, 32), 256, SMEM3>>>(bd, hidden);
}